// round 5
// baseline (speedup 1.0000x reference)
#include <cuda_runtime.h>
#include <math.h>
#include <cstdint>
#include <mma.h>

using namespace nvcuda;

#define N_VAR 50000
#define N_CLA 100000
#define NM    150000
#define DD    64
#define NC    1000
#define VC    64
#define KCL   128
#define NN    192
#define NE    8000
#define NSH   8
#define NITER 3
#define NEG   0.2f
#define INVSCALE 0.125f

typedef unsigned long long u64;

// ---------------- scalar f32x2 helpers (k_fin) --------------------------------
__device__ __forceinline__ void fma2(u64& d, u64 a, u64 b) {
    asm("fma.rn.f32x2 %0, %1, %2, %0;" : "+l"(d) : "l"(a), "l"(b));
}
__device__ __forceinline__ float lohiadd(u64 a) {
    float lo, hi;
    asm("mov.b64 {%0,%1}, %2;" : "=f"(lo), "=f"(hi) : "l"(a));
    return lo + hi;
}

typedef wmma::fragment<wmma::matrix_a, 16, 16, 8, wmma::precision::tf32, wmma::row_major> AFrag;
typedef wmma::fragment<wmma::matrix_b, 16, 16, 8, wmma::precision::tf32, wmma::col_major> BFragC;
typedef wmma::fragment<wmma::matrix_b, 16, 16, 8, wmma::precision::tf32, wmma::row_major> BFragR;
typedef wmma::fragment<wmma::accumulator, 16, 16, 8, float> CFrag;

template <typename F>
__device__ __forceinline__ void to_tf32(F& f) {
    #pragma unroll
    for (int t = 0; t < f.num_elements; t++) f.x[t] = wmma::__float_to_tf32(f.x[t]);
}

// ---------------- scratch ----------------------------------------------------
__device__ float g_x  [NM * DD];
__device__ float g_Q  [NM * DD];
__device__ float g_K  [NM * DD];
__device__ float g_V  [NM * DD];
__device__ float g_acc[NM * DD];
__device__ float g_cnt[NM];
__device__ float g_Q2 [NC * DD];
__device__ float g_K2 [NC * DD];
__device__ float g_V2 [NC * DD];
__device__ float g_pool[2 * DD];

__global__ void k_init(const float* __restrict__ xv, const float* __restrict__ xc) {
    int stride = gridDim.x * blockDim.x;
    for (int i = blockIdx.x * blockDim.x + threadIdx.x; i < NM * DD; i += stride)
        g_x[i] = (i < N_VAR * DD) ? xv[i] : xc[i - N_VAR * DD];
}
__global__ void k_poolzero() { if (threadIdx.x < 2 * DD) g_pool[threadIdx.x] = 0.f; }

// ---------------- Q/K/V projection via WMMA tf32 (+ zero g_acc/g_cnt) --------
// 128 rows per CTA, 8 warps (one 16-row tile band each), weights col_major ld=72.
#define PROJ_SMEM ((3 * 64 * 72 + 128 * 72) * 4)
__global__ void __launch_bounds__(256) k_proj(const float* __restrict__ WQ,
                                              const float* __restrict__ WK,
                                              const float* __restrict__ WV) {
    extern __shared__ float sm[];
    float* Wp = sm;               // 3 * 64*72 : (k,d) at m*4608 + d*72 + k
    float* xs = sm + 3 * 64 * 72; // 128*72 row-major
    int tid = threadIdx.x, wid = tid >> 5;

    for (int i = tid; i < 3 * 64 * 64; i += 256) {
        int m = i >> 12, d = (i >> 6) & 63, k = i & 63;
        const float* W = (m == 0) ? WQ : ((m == 1) ? WK : WV);
        Wp[m * 4608 + d * 72 + k] = W[d * 64 + k];
    }
    size_t base = (size_t)blockIdx.x * 128;
    for (int i = tid; i < 128 * 16; i += 256) {
        int row = i >> 4, q4 = i & 15;
        size_t r = base + row;
        if (r < NM)
            ((float4*)(xs + row * 72))[q4] = ((const float4*)(g_x + r * 64))[q4];
    }
    __syncthreads();

    if (base + (size_t)wid * 16 < NM) {
        AFrag a[8];
        #pragma unroll
        for (int k = 0; k < 8; k++) {
            wmma::load_matrix_sync(a[k], xs + wid * 16 * 72 + k * 8, 72);
            to_tf32(a[k]);
        }
        float* outs[3] = {g_Q, g_K, g_V};
        #pragma unroll
        for (int m = 0; m < 3; m++) {
            #pragma unroll
            for (int tc = 0; tc < 4; tc++) {
                CFrag acc;
                wmma::fill_fragment(acc, 0.f);
                #pragma unroll
                for (int k = 0; k < 8; k++) {
                    BFragC b;
                    wmma::load_matrix_sync(b, Wp + m * 4608 + tc * 16 * 72 + k * 8, 72);
                    to_tf32(b);
                    wmma::mma_sync(acc, a[k], b, acc);
                }
                wmma::store_matrix_sync(outs[m] + (base + wid * 16) * 64 + tc * 16,
                                        acc, 64, wmma::mem_row_major);
            }
        }
    }
    // zero g_acc / g_cnt for these rows
    float4 z4 = make_float4(0.f, 0.f, 0.f, 0.f);
    for (int i = tid; i < 128 * 16; i += 256) {
        int row = i >> 4, q4 = i & 15;
        size_t r = base + row;
        if (r < NM) ((float4*)(g_acc + r * 64))[q4] = z4;
    }
    for (int i = tid; i < 128; i += 256)
        if (base + i < NM) g_cnt[base + i] = 0.f;
}

// ---------------- intra-cluster attention via WMMA tf32 ----------------------
// 1 CTA per cluster, 384 threads (12 warps), 2 bands x 96 queries.
// K/V/Q tiles ld=72; S band [96 x 192] ld=200.
#define OFF_K 0
#define OFF_V 13824
#define OFF_Q 27648
#define OFF_S 34560
#define OFF_RS 53760
#define OFF_B  53856
#define OFF_N  54048
#define ATTN_SMEM ((54048 + 192) * 4)

__global__ void __launch_bounds__(384, 1) k_attn_wm(const int* __restrict__ cvar,
                                                    const int* __restrict__ ccla,
                                                    const float* __restrict__ sat,
                                                    const float* __restrict__ hw) {
    extern __shared__ float sm[];
    float* Ksh = sm + OFF_K;        // [192][72]
    float* Vsh = sm + OFF_V;        // [192][72]
    float* Qb  = sm + OFF_Q;        // [96][72]  (reused as O staging)
    float* Ssh = sm + OFF_S;        // [96][200]
    float* rowsum = sm + OFF_RS;    // [96]
    float* bsh = sm + OFF_B;        // [192]
    int*   nsh = (int*)(sm + OFF_N);// [192]

    int c = blockIdx.x, tid = threadIdx.x, wid = tid >> 5;
    if (tid < NN) {
        int g; float b;
        if (tid < VC) { g = cvar[c * VC + tid]; b = 0.f; }
        else { int cl = ccla[c * KCL + (tid - VC)]; g = N_VAR + cl; b = sat[cl]; }
        nsh[tid] = g; bsh[tid] = b;
    }
    float hwm = 0.25f * (hw[0] + hw[1] + hw[2] + hw[3]);
    __syncthreads();

    for (int idx = tid; idx < 192 * 16; idx += 384) {
        int row = idx >> 4, q4 = idx & 15;
        size_t o = (size_t)nsh[row] * 64;
        ((float4*)(Ksh + row * 72))[q4] = ((const float4*)(g_K + o))[q4];
        ((float4*)(Vsh + row * 72))[q4] = ((const float4*)(g_V + o))[q4];
    }

    int srow = tid >> 2, sc0 = tid & 3;   // softmax/scatter mapping

    for (int band = 0; band < 2; band++) {
        // gather Q band
        for (int idx = tid; idx < 96 * 16; idx += 384) {
            int row = idx >> 4, q4 = idx & 15;
            ((float4*)(Qb + row * 72))[q4] =
                ((const float4*)(g_Q + (size_t)nsh[band * 96 + row] * 64))[q4];
        }
        __syncthreads();

        // GEMM1: S[96,192] = Qb @ K^T
        {
            int tr = wid % 6, tcg = (wid / 6) * 6;
            AFrag a[8];
            #pragma unroll
            for (int k = 0; k < 8; k++) {
                wmma::load_matrix_sync(a[k], Qb + tr * 16 * 72 + k * 8, 72);
                to_tf32(a[k]);
            }
            #pragma unroll
            for (int tcx = 0; tcx < 6; tcx++) {
                int tc = tcg + tcx;
                CFrag acc;
                wmma::fill_fragment(acc, 0.f);
                #pragma unroll
                for (int k = 0; k < 8; k++) {
                    BFragC b;
                    wmma::load_matrix_sync(b, Ksh + tc * 16 * 72 + k * 8, 72);
                    to_tf32(b);
                    wmma::mma_sync(acc, a[k], b, acc);
                }
                wmma::store_matrix_sync(Ssh + tr * 16 * 200 + tc * 16, acc, 200,
                                        wmma::mem_row_major);
            }
        }
        __syncthreads();

        // softmax: 96 rows x 4-thread quads
        {
            float* srw = Ssh + srow * 200;
            float mx = -1e30f;
            #pragma unroll 8
            for (int i = 0; i < 48; i++) {
                int col = sc0 + 4 * i;
                float v = srw[col] * INVSCALE + bsh[col];
                v = (v >= 0.f) ? v : NEG * v;
                srw[col] = v;
                mx = fmaxf(mx, v);
            }
            mx = fmaxf(mx, __shfl_xor_sync(0xffffffffu, mx, 1));
            mx = fmaxf(mx, __shfl_xor_sync(0xffffffffu, mx, 2));
            float sum = 0.f;
            #pragma unroll 8
            for (int i = 0; i < 48; i++) {
                int col = sc0 + 4 * i;
                float e = __expf(srw[col] - mx);
                srw[col] = e;
                sum += e;
            }
            sum += __shfl_xor_sync(0xffffffffu, sum, 1);
            sum += __shfl_xor_sync(0xffffffffu, sum, 2);
            if (sc0 == 0) rowsum[srow] = sum;
        }
        __syncthreads();

        // GEMM2: O[96,64] = P @ V   (P = unnormalized exp weights in Ssh)
        {
            int tr2 = wid >> 1, tc0 = (wid & 1) * 2;
            CFrag o0, o1;
            wmma::fill_fragment(o0, 0.f);
            wmma::fill_fragment(o1, 0.f);
            #pragma unroll 4
            for (int k = 0; k < 24; k++) {
                AFrag a;
                wmma::load_matrix_sync(a, Ssh + tr2 * 16 * 200 + k * 8, 200);
                to_tf32(a);
                BFragR b0, b1;
                wmma::load_matrix_sync(b0, Vsh + k * 8 * 72 + tc0 * 16, 72);
                wmma::load_matrix_sync(b1, Vsh + k * 8 * 72 + (tc0 + 1) * 16, 72);
                to_tf32(b0);
                to_tf32(b1);
                wmma::mma_sync(o0, a, b0, o0);
                wmma::mma_sync(o1, a, b1, o1);
            }
            wmma::store_matrix_sync(Qb + tr2 * 16 * 72 + tc0 * 16, o0, 72,
                                    wmma::mem_row_major);
            wmma::store_matrix_sync(Qb + tr2 * 16 * 72 + (tc0 + 1) * 16, o1, 72,
                                    wmma::mem_row_major);
        }
        __syncthreads();

        // scatter-add with hwm / rowsum scale
        {
            int g = nsh[band * 96 + srow];
            float scl = hwm / rowsum[srow];
            const float* src = Qb + srow * 72 + sc0 * 16;
            float* dst = g_acc + (size_t)g * 64 + sc0 * 16;
            #pragma unroll
            for (int j = 0; j < 16; j++) atomicAdd(dst + j, src[j] * scl);
            if (sc0 == 0) atomicAdd(&g_cnt[g], 1.f);
        }
        __syncthreads();
    }
}

// ---------------- finalize: (acc/cnt) @ Wo^T + bo, residual add --------------
__global__ void __launch_bounds__(256) k_fin(const float* __restrict__ Wo,
                                             const float* __restrict__ bo) {
    extern __shared__ float sm[];
    float* Wt = sm;
    float* xs = Wt + 64 * 64;
    int tid = threadIdx.x;
    for (int i = tid; i < 64 * 64; i += 256) {
        int j = i >> 6, k = i & 63;
        Wt[(j << 6) + ((((k >> 2) ^ (j & 15)) << 2) | (k & 3))] = Wo[i];
    }
    __syncthreads();
    int warp = tid >> 5, lane = tid & 31;
    float* xw = xs + warp * 256;
    const ulonglong2* xw2 = (const ulonglong2*)xw;
    const ulonglong2* Wt2 = (const ulonglong2*)Wt;
    float b0 = bo[lane], b1 = bo[lane + 32];
    int lsw = lane & 15;
    for (int b = 0; b < 2; b++) {
        int base = blockIdx.x * 64 + warp * 8 + b * 4;
        {
            int rh = lane >> 4, qd = lane & 15;
            #pragma unroll
            for (int rr = 0; rr < 2; rr++) {
                int row = base + rr * 2 + rh;
                int rc = (row < NM) ? row : NM - 1;
                float inv = 1.f / fmaxf(g_cnt[rc], 1.f);
                float4 a = ((const float4*)(g_acc + (size_t)rc * DD))[qd];
                a.x *= inv; a.y *= inv; a.z *= inv; a.w *= inv;
                ((float4*)xw)[(rr * 2 + rh) * 16 + qd] = a;
            }
        }
        __syncwarp();
        u64 acc2[2][4];
        #pragma unroll
        for (int o = 0; o < 2; o++)
            #pragma unroll
            for (int r = 0; r < 4; r++) acc2[o][r] = 0ull;
        #pragma unroll 4
        for (int d4 = 0; d4 < 16; d4++) {
            ulonglong2 x0 = xw2[d4], x1 = xw2[16 + d4], x2 = xw2[32 + d4], x3 = xw2[48 + d4];
            int sq = (lane << 4) + (d4 ^ lsw);
            ulonglong2 wa = Wt2[sq];
            ulonglong2 wb = Wt2[sq + 512];
            fma2(acc2[0][0], wa.x, x0.x); fma2(acc2[0][0], wa.y, x0.y);
            fma2(acc2[0][1], wa.x, x1.x); fma2(acc2[0][1], wa.y, x1.y);
            fma2(acc2[0][2], wa.x, x2.x); fma2(acc2[0][2], wa.y, x2.y);
            fma2(acc2[0][3], wa.x, x3.x); fma2(acc2[0][3], wa.y, x3.y);
            fma2(acc2[1][0], wb.x, x0.x); fma2(acc2[1][0], wb.y, x0.y);
            fma2(acc2[1][1], wb.x, x1.x); fma2(acc2[1][1], wb.y, x1.y);
            fma2(acc2[1][2], wb.x, x2.x); fma2(acc2[1][2], wb.y, x2.y);
            fma2(acc2[1][3], wb.x, x3.x); fma2(acc2[1][3], wb.y, x3.y);
        }
        #pragma unroll
        for (int r = 0; r < 4; r++) {
            int row = base + r;
            if (row >= NM) continue;
            size_t o = (size_t)row * DD;
            g_x[o + lane]      += lohiadd(acc2[0][r]) + b0;
            g_x[o + lane + 32] += lohiadd(acc2[1][r]) + b1;
        }
        __syncwarp();
    }
}

// ---------------- cluster features + Q2/K2/V2 projection ---------------------
__global__ void k_cf(const int* __restrict__ cvar,
                     const float* __restrict__ WQ2, const float* __restrict__ WK2,
                     const float* __restrict__ WV2) {
    __shared__ float cf[64];
    __shared__ int ids[64];
    int c = blockIdx.x, d = threadIdx.x;
    ids[d] = cvar[c * VC + d];
    __syncthreads();
    float s = 0.f;
    #pragma unroll 8
    for (int v = 0; v < VC; v++) s += g_x[(size_t)ids[v] * DD + d];
    cf[d] = s * (1.f / 64.f);
    __syncthreads();
    float q = 0.f, k = 0.f, v = 0.f;
    #pragma unroll 8
    for (int j = 0; j < 64; j++) {
        float x = cf[j];
        q = fmaf(x, WQ2[d * 64 + j], q);
        k = fmaf(x, WK2[d * 64 + j], k);
        v = fmaf(x, WV2[d * 64 + j], v);
    }
    g_Q2[c * 64 + d] = q; g_K2[c * 64 + d] = k; g_V2[c * 64 + d] = v;
}

// ---------------- inter-cluster edge scatter (GAT2) --------------------------
__global__ void k_edge(const int* __restrict__ ei, const int* __restrict__ shv,
                       const float* __restrict__ hw) {
    int tid = threadIdx.x;
    int warp = tid >> 5, lane = tid & 31;
    int e = blockIdx.x * 8 + warp;
    if (e >= NE) return;
    int c1 = ei[e], c2 = ei[NE + e];
    float p = g_Q2[c1 * 64 + lane] * g_K2[c2 * 64 + lane]
            + g_Q2[c1 * 64 + lane + 32] * g_K2[c2 * 64 + lane + 32];
    #pragma unroll
    for (int o = 16; o > 0; o >>= 1) p += __shfl_xor_sync(0xffffffffu, p, o);
    float s = p * INVSCALE;
    float lr = (s >= 0.f) ? s : NEG * s;
    float hwm = 0.25f * (hw[0] + hw[1] + hw[2] + hw[3]);
    float a = hwm / (1.f + __expf(-lr));
    float v0 = a * g_V2[c2 * 64 + lane];
    float v1 = a * g_V2[c2 * 64 + lane + 32];
    #pragma unroll
    for (int k = 0; k < NSH; k++) {
        int sv = shv[e * NSH + k];
        atomicAdd(&g_x[(size_t)sv * DD + lane],      v0);
        atomicAdd(&g_x[(size_t)sv * DD + lane + 32], v1);
    }
}

// ---------------- pooling + MLP readout --------------------------------------
__global__ void k_pool() {
    int tid = threadIdx.x;
    int col = tid & 63;
    int rg = tid >> 6;
    float sv = 0.f, sc = 0.f;
    for (int r = blockIdx.x * 4 + rg; r < NM; r += gridDim.x * 4) {
        float x = g_x[(size_t)r * DD + col];
        if (r < N_VAR) sv += x; else sc += x;
    }
    atomicAdd(&g_pool[col], sv);
    atomicAdd(&g_pool[64 + col], sc);
}

__global__ void k_mlp(const float* __restrict__ W1, const float* __restrict__ b1,
                      const float* __restrict__ W2, const float* __restrict__ b2,
                      float* __restrict__ out) {
    __shared__ float p[128];
    __shared__ float h[64];
    int tid = threadIdx.x;
    if (tid < 128)
        p[tid] = tanhf(g_pool[tid] * (tid < 64 ? 1.f / N_VAR : 1.f / N_CLA));
    __syncthreads();
    if (tid < 64) {
        float a = b1[tid];
        #pragma unroll 8
        for (int j = 0; j < 128; j++) a = fmaf(p[j], W1[tid * 128 + j], a);
        h[tid] = (a > 0.f) ? a : 0.f;
    }
    __syncthreads();
    if (tid == 0) {
        float s = b2[0];
        for (int i = 0; i < 64; i++) s = fmaf(h[i], W2[i], s);
        out[0] = s;
    }
}

// ---------------- launch ------------------------------------------------------
extern "C" void kernel_launch(void* const* d_in, const int* in_sizes, int n_in,
                              void* d_out, int out_size) {
    (void)in_sizes; (void)n_in; (void)out_size;
    const float* xv   = (const float*)d_in[0];
    const float* xc   = (const float*)d_in[1];
    const float* sat  = (const float*)d_in[2];
    const int*   cvar = (const int*)d_in[3];
    const int*   ccla = (const int*)d_in[4];
    const int*   ei   = (const int*)d_in[5];
    const int*   shv  = (const int*)d_in[6];
    const float* WQ1  = (const float*)d_in[7];
    const float* WK1  = (const float*)d_in[8];
    const float* WV1  = (const float*)d_in[9];
    const float* hw1  = (const float*)d_in[10];
    const float* Wo   = (const float*)d_in[11];
    const float* bo   = (const float*)d_in[12];
    const float* WQ2  = (const float*)d_in[13];
    const float* WK2  = (const float*)d_in[14];
    const float* WV2  = (const float*)d_in[15];
    const float* hw2  = (const float*)d_in[16];
    const float* W1   = (const float*)d_in[17];
    const float* b1   = (const float*)d_in[18];
    const float* W2   = (const float*)d_in[19];
    const float* b2   = (const float*)d_in[20];

    const int finSmem = (64 * 64 + 8 * 4 * 64) * 4;
    cudaFuncSetAttribute(k_proj,    cudaFuncAttributeMaxDynamicSharedMemorySize, PROJ_SMEM);
    cudaFuncSetAttribute(k_attn_wm, cudaFuncAttributeMaxDynamicSharedMemorySize, ATTN_SMEM);

    k_init<<<512, 256>>>(xv, xc);
    const int projBlocks = (NM + 127) / 128;
    const int finBlocks  = (NM + 63) / 64;
    for (int it = 0; it < NITER; it++) {
        k_proj<<<projBlocks, 256, PROJ_SMEM>>>(WQ1, WK1, WV1);  // also zeroes g_acc/g_cnt
        k_attn_wm<<<NC, 384, ATTN_SMEM>>>(cvar, ccla, sat, hw1);
        k_fin<<<finBlocks, 256, finSmem>>>(Wo, bo);
        k_cf<<<NC, 64>>>(cvar, WQ2, WK2, WV2);
        k_edge<<<(NE + 7) / 8, 256>>>(ei, shv, hw2);
    }
    k_poolzero<<<1, 128>>>();
    k_pool<<<512, 256>>>();
    k_mlp<<<1, 128>>>(W1, b1, W2, b2, (float*)d_out);
}

// round 6
// speedup vs baseline: 1.2339x; 1.2339x over previous
#include <cuda_runtime.h>
#include <cuda_fp16.h>
#include <math.h>
#include <cstdint>
#include <mma.h>

using namespace nvcuda;

#define N_VAR 50000
#define N_CLA 100000
#define NM    150000
#define DD    64
#define NC    1000
#define VC    64
#define KCL   128
#define NN    192
#define NE    8000
#define NSH   8
#define NITER 3
#define NEG   0.2f
#define INVSCALE 0.125f

typedef unsigned long long u64;

// tf32 fragments (k_proj / k_fin)
typedef wmma::fragment<wmma::matrix_a, 16, 16, 8, wmma::precision::tf32, wmma::row_major> AFrag;
typedef wmma::fragment<wmma::matrix_b, 16, 16, 8, wmma::precision::tf32, wmma::col_major> BFragC;
typedef wmma::fragment<wmma::accumulator, 16, 16, 8, float> CFrag;
// fp16 fragments (k_attn)
typedef wmma::fragment<wmma::matrix_a, 16, 16, 16, __half, wmma::row_major> HA;
typedef wmma::fragment<wmma::matrix_b, 16, 16, 16, __half, wmma::col_major> HBC;
typedef wmma::fragment<wmma::matrix_b, 16, 16, 16, __half, wmma::row_major> HBR;
typedef wmma::fragment<wmma::accumulator, 16, 16, 16, float> HC;

template <typename F>
__device__ __forceinline__ void to_tf32(F& f) {
    #pragma unroll
    for (int t = 0; t < f.num_elements; t++) f.x[t] = wmma::__float_to_tf32(f.x[t]);
}

// ---------------- scratch ----------------------------------------------------
__device__ float g_x  [NM * DD];
__device__ float g_Q  [NM * DD];
__device__ float g_K  [NM * DD];
__device__ float g_V  [NM * DD];
__device__ float g_acc[NM * DD];
__device__ float g_cnt[NM];
__device__ float g_Q2 [NC * DD];
__device__ float g_K2 [NC * DD];
__device__ float g_V2 [NC * DD];
__device__ float g_pool[2 * DD];

__global__ void k_init(const float* __restrict__ xv, const float* __restrict__ xc) {
    int stride = gridDim.x * blockDim.x;
    for (int i = blockIdx.x * blockDim.x + threadIdx.x; i < NM * DD; i += stride)
        g_x[i] = (i < N_VAR * DD) ? xv[i] : xc[i - N_VAR * DD];
}
__global__ void k_poolzero() { if (threadIdx.x < 2 * DD) g_pool[threadIdx.x] = 0.f; }

// ---------------- Q/K/V projection via WMMA tf32 (+ zero g_acc/g_cnt) --------
#define PROJ_SMEM ((3 * 64 * 72 + 128 * 72) * 4)
__global__ void __launch_bounds__(256) k_proj(const float* __restrict__ WQ,
                                              const float* __restrict__ WK,
                                              const float* __restrict__ WV) {
    extern __shared__ float sm[];
    float* Wp = sm;               // 3 * 64*72 : (k,d) at m*4608 + d*72 + k
    float* xs = sm + 3 * 64 * 72; // 128*72 row-major
    int tid = threadIdx.x, wid = tid >> 5;

    for (int i = tid; i < 3 * 64 * 64; i += 256) {
        int m = i >> 12, d = (i >> 6) & 63, k = i & 63;
        const float* W = (m == 0) ? WQ : ((m == 1) ? WK : WV);
        Wp[m * 4608 + d * 72 + k] = W[d * 64 + k];
    }
    size_t base = (size_t)blockIdx.x * 128;
    for (int i = tid; i < 128 * 16; i += 256) {
        int row = i >> 4, q4 = i & 15;
        size_t r = base + row;
        if (r < NM)
            ((float4*)(xs + row * 72))[q4] = ((const float4*)(g_x + r * 64))[q4];
    }
    __syncthreads();

    if (base + (size_t)wid * 16 < NM) {
        AFrag a[8];
        #pragma unroll
        for (int k = 0; k < 8; k++) {
            wmma::load_matrix_sync(a[k], xs + wid * 16 * 72 + k * 8, 72);
            to_tf32(a[k]);
        }
        float* outs[3] = {g_Q, g_K, g_V};
        #pragma unroll
        for (int m = 0; m < 3; m++) {
            #pragma unroll
            for (int tc = 0; tc < 4; tc++) {
                CFrag acc;
                wmma::fill_fragment(acc, 0.f);
                #pragma unroll
                for (int k = 0; k < 8; k++) {
                    BFragC b;
                    wmma::load_matrix_sync(b, Wp + m * 4608 + tc * 16 * 72 + k * 8, 72);
                    to_tf32(b);
                    wmma::mma_sync(acc, a[k], b, acc);
                }
                wmma::store_matrix_sync(outs[m] + (base + wid * 16) * 64 + tc * 16,
                                        acc, 64, wmma::mem_row_major);
            }
        }
    }
    float4 z4 = make_float4(0.f, 0.f, 0.f, 0.f);
    for (int i = tid; i < 128 * 16; i += 256) {
        int row = i >> 4, q4 = i & 15;
        size_t r = base + row;
        if (r < NM) ((float4*)(g_acc + r * 64))[q4] = z4;
    }
    for (int i = tid; i < 128; i += 256)
        if (base + i < NM) g_cnt[base + i] = 0.f;
}

// ---------------- intra-cluster attention via WMMA fp16 ----------------------
// 1 CTA per cluster, 384 threads (12 warps), 2 bands x 96 queries.
// K/V/Q half tiles ld=80 (halves); S float ld=200; P half ld=200.
#define OFFB_K  0
#define OFFB_V  30720
#define OFFB_Q  61440
#define OFFB_S  76800
#define OFFB_P  153600
#define OFFB_RS 192000
#define OFFB_B  192384
#define OFFB_N  193152
#define ATTN_SMEM 193920

__global__ void __launch_bounds__(384, 1) k_attn_wm(const int* __restrict__ cvar,
                                                    const int* __restrict__ ccla,
                                                    const float* __restrict__ sat,
                                                    const float* __restrict__ hw) {
    extern __shared__ char smem[];
    __half* Kh = (__half*)(smem + OFFB_K);     // [192][80]
    __half* Vh = (__half*)(smem + OFFB_V);     // [192][80]
    __half* Qh = (__half*)(smem + OFFB_Q);     // [96][80]
    float*  Sf = (float*)(smem + OFFB_S);      // [96][200] scores; reused [96][72] O-staging
    __half* Ph = (__half*)(smem + OFFB_P);     // [96][200] exp weights
    float*  rowsum = (float*)(smem + OFFB_RS); // [96]
    float*  bsh = (float*)(smem + OFFB_B);     // [192]
    int*    nsh = (int*)(smem + OFFB_N);       // [192]

    int c = blockIdx.x, tid = threadIdx.x, wid = tid >> 5;
    if (tid < NN) {
        int g; float b;
        if (tid < VC) { g = cvar[c * VC + tid]; b = 0.f; }
        else { int cl = ccla[c * KCL + (tid - VC)]; g = N_VAR + cl; b = sat[cl]; }
        nsh[tid] = g; bsh[tid] = b;
    }
    float hwm = 0.25f * (hw[0] + hw[1] + hw[2] + hw[3]);
    __syncthreads();

    // gather K/V -> half tiles
    for (int idx = tid; idx < 192 * 16; idx += 384) {
        int row = idx >> 4, q4 = idx & 15;
        size_t o = (size_t)nsh[row] * 64;
        float4 kv = ((const float4*)(g_K + o))[q4];
        float4 vv = ((const float4*)(g_V + o))[q4];
        __half2 a, b;
        uint2 u;
        a = __floats2half2_rn(kv.x, kv.y); b = __floats2half2_rn(kv.z, kv.w);
        u.x = *(uint32_t*)&a; u.y = *(uint32_t*)&b;
        *(uint2*)(Kh + row * 80 + q4 * 4) = u;
        a = __floats2half2_rn(vv.x, vv.y); b = __floats2half2_rn(vv.z, vv.w);
        u.x = *(uint32_t*)&a; u.y = *(uint32_t*)&b;
        *(uint2*)(Vh + row * 80 + q4 * 4) = u;
    }

    int srow = tid >> 2, sc0 = tid & 3;

    for (int band = 0; band < 2; band++) {
        // gather Q band -> half
        for (int idx = tid; idx < 96 * 16; idx += 384) {
            int row = idx >> 4, q4 = idx & 15;
            float4 qv = ((const float4*)(g_Q + (size_t)nsh[band * 96 + row] * 64))[q4];
            __half2 a = __floats2half2_rn(qv.x, qv.y);
            __half2 b = __floats2half2_rn(qv.z, qv.w);
            uint2 u; u.x = *(uint32_t*)&a; u.y = *(uint32_t*)&b;
            *(uint2*)(Qh + row * 80 + q4 * 4) = u;
        }
        __syncthreads();

        // GEMM1: S[96,192] = Qh @ Kh^T (fp16, 4 k-steps)
        {
            int tr = wid % 6, tcg = (wid / 6) * 6;
            HA a[4];
            #pragma unroll
            for (int k = 0; k < 4; k++)
                wmma::load_matrix_sync(a[k], Qh + tr * 16 * 80 + k * 16, 80);
            #pragma unroll
            for (int tcx = 0; tcx < 6; tcx++) {
                int tc = tcg + tcx;
                HC acc;
                wmma::fill_fragment(acc, 0.f);
                #pragma unroll
                for (int k = 0; k < 4; k++) {
                    HBC b;
                    wmma::load_matrix_sync(b, Kh + tc * 16 * 80 + k * 16, 80);
                    wmma::mma_sync(acc, a[k], b, acc);
                }
                wmma::store_matrix_sync(Sf + tr * 16 * 200 + tc * 16, acc, 200,
                                        wmma::mem_row_major);
            }
        }
        __syncthreads();

        // softmax: 96 rows x 4-thread quads; write exp weights to Ph (half)
        {
            float* srw = Sf + srow * 200;
            __half* prw = Ph + srow * 200;
            float mx = -1e30f;
            float v[48];
            #pragma unroll 8
            for (int i = 0; i < 48; i++) {
                int col = sc0 + 4 * i;
                float s = srw[col] * INVSCALE + bsh[col];
                s = (s >= 0.f) ? s : NEG * s;
                v[i] = s;
                mx = fmaxf(mx, s);
            }
            mx = fmaxf(mx, __shfl_xor_sync(0xffffffffu, mx, 1));
            mx = fmaxf(mx, __shfl_xor_sync(0xffffffffu, mx, 2));
            float sum = 0.f;
            #pragma unroll 8
            for (int i = 0; i < 48; i++) {
                float e = __expf(v[i] - mx);
                sum += e;
                prw[sc0 + 4 * i] = __float2half_rn(e);
            }
            sum += __shfl_xor_sync(0xffffffffu, sum, 1);
            sum += __shfl_xor_sync(0xffffffffu, sum, 2);
            if (sc0 == 0) rowsum[srow] = sum;
        }
        __syncthreads();

        // GEMM2: O[96,64] = P @ V (fp16, 12 k-steps); stage O into Sf [96][72]
        {
            int tr2 = wid >> 1, tc0 = (wid & 1) * 2;
            HC o0, o1;
            wmma::fill_fragment(o0, 0.f);
            wmma::fill_fragment(o1, 0.f);
            #pragma unroll 4
            for (int k = 0; k < 12; k++) {
                HA a;
                wmma::load_matrix_sync(a, Ph + tr2 * 16 * 200 + k * 16, 200);
                HBR b0, b1;
                wmma::load_matrix_sync(b0, Vh + k * 16 * 80 + tc0 * 16, 80);
                wmma::load_matrix_sync(b1, Vh + k * 16 * 80 + (tc0 + 1) * 16, 80);
                wmma::mma_sync(o0, a, b0, o0);
                wmma::mma_sync(o1, a, b1, o1);
            }
            wmma::store_matrix_sync(Sf + tr2 * 16 * 72 + tc0 * 16, o0, 72,
                                    wmma::mem_row_major);
            wmma::store_matrix_sync(Sf + tr2 * 16 * 72 + (tc0 + 1) * 16, o1, 72,
                                    wmma::mem_row_major);
        }
        __syncthreads();

        // scatter-add with hwm / rowsum scale
        {
            int g = nsh[band * 96 + srow];
            float scl = hwm / rowsum[srow];
            const float* src = Sf + srow * 72 + sc0 * 16;
            float* dst = g_acc + (size_t)g * 64 + sc0 * 16;
            #pragma unroll
            for (int j = 0; j < 16; j++) atomicAdd(dst + j, src[j] * scl);
            if (sc0 == 0) atomicAdd(&g_cnt[g], 1.f);
        }
        __syncthreads();
    }
}

// ---------------- finalize via WMMA tf32: (acc/cnt) @ Wo^T + bo + residual ---
#define FIN_SMEM ((64 * 72 + 128 * 72 + 128 * 72) * 4)
__global__ void __launch_bounds__(256) k_fin(const float* __restrict__ Wo,
                                             const float* __restrict__ bo) {
    extern __shared__ float sm[];
    float* Wt = sm;                 // [64][72] col-major: (k,d) at d*72+k
    float* xs = Wt + 64 * 72;       // [128][72]
    float* ys = xs + 128 * 72;      // [128][72]
    int tid = threadIdx.x, wid = tid >> 5;

    for (int i = tid; i < 64 * 64; i += 256) {
        int d = i >> 6, k = i & 63;
        Wt[d * 72 + k] = Wo[i];
    }
    size_t base = (size_t)blockIdx.x * 128;
    for (int i = tid; i < 128 * 16; i += 256) {
        int row = i >> 4, q4 = i & 15;
        size_t r = base + row;
        if (r < NM) {
            float inv = 1.f / fmaxf(g_cnt[r], 1.f);
            float4 a = ((const float4*)(g_acc + r * 64))[q4];
            a.x *= inv; a.y *= inv; a.z *= inv; a.w *= inv;
            ((float4*)(xs + row * 72))[q4] = a;
        }
    }
    __syncthreads();

    if (base + (size_t)wid * 16 < NM) {
        AFrag a[8];
        #pragma unroll
        for (int k = 0; k < 8; k++) {
            wmma::load_matrix_sync(a[k], xs + wid * 16 * 72 + k * 8, 72);
            to_tf32(a[k]);
        }
        #pragma unroll
        for (int tc = 0; tc < 4; tc++) {
            CFrag acc;
            wmma::fill_fragment(acc, 0.f);
            #pragma unroll
            for (int k = 0; k < 8; k++) {
                BFragC b;
                wmma::load_matrix_sync(b, Wt + tc * 16 * 72 + k * 8, 72);
                to_tf32(b);
                wmma::mma_sync(acc, a[k], b, acc);
            }
            wmma::store_matrix_sync(ys + wid * 16 * 72 + tc * 16, acc, 72,
                                    wmma::mem_row_major);
        }
    }
    __syncthreads();

    for (int i = tid; i < 128 * 16; i += 256) {
        int row = i >> 4, q4 = i & 15;
        size_t r = base + row;
        if (r < NM) {
            float4 x = ((const float4*)(g_x + r * 64))[q4];
            float4 y = ((const float4*)(ys + row * 72))[q4];
            float4 b = ((const float4*)bo)[q4];
            x.x += y.x + b.x; x.y += y.y + b.y;
            x.z += y.z + b.z; x.w += y.w + b.w;
            ((float4*)(g_x + r * 64))[q4] = x;
        }
    }
}

// ---------------- cluster features + Q2/K2/V2 projection ---------------------
__global__ void k_cf(const int* __restrict__ cvar,
                     const float* __restrict__ WQ2, const float* __restrict__ WK2,
                     const float* __restrict__ WV2) {
    __shared__ float cf[64];
    __shared__ int ids[64];
    int c = blockIdx.x, d = threadIdx.x;
    ids[d] = cvar[c * VC + d];
    __syncthreads();
    float s = 0.f;
    #pragma unroll 8
    for (int v = 0; v < VC; v++) s += g_x[(size_t)ids[v] * DD + d];
    cf[d] = s * (1.f / 64.f);
    __syncthreads();
    float q = 0.f, k = 0.f, v = 0.f;
    #pragma unroll 8
    for (int j = 0; j < 64; j++) {
        float x = cf[j];
        q = fmaf(x, WQ2[d * 64 + j], q);
        k = fmaf(x, WK2[d * 64 + j], k);
        v = fmaf(x, WV2[d * 64 + j], v);
    }
    g_Q2[c * 64 + d] = q; g_K2[c * 64 + d] = k; g_V2[c * 64 + d] = v;
}

// ---------------- inter-cluster edge scatter (GAT2) --------------------------
__global__ void k_edge(const int* __restrict__ ei, const int* __restrict__ shv,
                       const float* __restrict__ hw) {
    int tid = threadIdx.x;
    int warp = tid >> 5, lane = tid & 31;
    int e = blockIdx.x * 8 + warp;
    if (e >= NE) return;
    int c1 = ei[e], c2 = ei[NE + e];
    float p = g_Q2[c1 * 64 + lane] * g_K2[c2 * 64 + lane]
            + g_Q2[c1 * 64 + lane + 32] * g_K2[c2 * 64 + lane + 32];
    #pragma unroll
    for (int o = 16; o > 0; o >>= 1) p += __shfl_xor_sync(0xffffffffu, p, o);
    float s = p * INVSCALE;
    float lr = (s >= 0.f) ? s : NEG * s;
    float hwm = 0.25f * (hw[0] + hw[1] + hw[2] + hw[3]);
    float a = hwm / (1.f + __expf(-lr));
    float v0 = a * g_V2[c2 * 64 + lane];
    float v1 = a * g_V2[c2 * 64 + lane + 32];
    #pragma unroll
    for (int k = 0; k < NSH; k++) {
        int sv = shv[e * NSH + k];
        atomicAdd(&g_x[(size_t)sv * DD + lane],      v0);
        atomicAdd(&g_x[(size_t)sv * DD + lane + 32], v1);
    }
}

// ---------------- pooling + MLP readout --------------------------------------
__global__ void k_pool() {
    int tid = threadIdx.x;
    int col = tid & 63;
    int rg = tid >> 6;
    float sv = 0.f, sc = 0.f;
    for (int r = blockIdx.x * 4 + rg; r < NM; r += gridDim.x * 4) {
        float x = g_x[(size_t)r * DD + col];
        if (r < N_VAR) sv += x; else sc += x;
    }
    atomicAdd(&g_pool[col], sv);
    atomicAdd(&g_pool[64 + col], sc);
}

__global__ void k_mlp(const float* __restrict__ W1, const float* __restrict__ b1,
                      const float* __restrict__ W2, const float* __restrict__ b2,
                      float* __restrict__ out) {
    __shared__ float p[128];
    __shared__ float h[64];
    int tid = threadIdx.x;
    if (tid < 128)
        p[tid] = tanhf(g_pool[tid] * (tid < 64 ? 1.f / N_VAR : 1.f / N_CLA));
    __syncthreads();
    if (tid < 64) {
        float a = b1[tid];
        #pragma unroll 8
        for (int j = 0; j < 128; j++) a = fmaf(p[j], W1[tid * 128 + j], a);
        h[tid] = (a > 0.f) ? a : 0.f;
    }
    __syncthreads();
    if (tid == 0) {
        float s = b2[0];
        for (int i = 0; i < 64; i++) s = fmaf(h[i], W2[i], s);
        out[0] = s;
    }
}

// ---------------- launch ------------------------------------------------------
extern "C" void kernel_launch(void* const* d_in, const int* in_sizes, int n_in,
                              void* d_out, int out_size) {
    (void)in_sizes; (void)n_in; (void)out_size;
    const float* xv   = (const float*)d_in[0];
    const float* xc   = (const float*)d_in[1];
    const float* sat  = (const float*)d_in[2];
    const int*   cvar = (const int*)d_in[3];
    const int*   ccla = (const int*)d_in[4];
    const int*   ei   = (const int*)d_in[5];
    const int*   shv  = (const int*)d_in[6];
    const float* WQ1  = (const float*)d_in[7];
    const float* WK1  = (const float*)d_in[8];
    const float* WV1  = (const float*)d_in[9];
    const float* hw1  = (const float*)d_in[10];
    const float* Wo   = (const float*)d_in[11];
    const float* bo   = (const float*)d_in[12];
    const float* WQ2  = (const float*)d_in[13];
    const float* WK2  = (const float*)d_in[14];
    const float* WV2  = (const float*)d_in[15];
    const float* hw2  = (const float*)d_in[16];
    const float* W1   = (const float*)d_in[17];
    const float* b1   = (const float*)d_in[18];
    const float* W2   = (const float*)d_in[19];
    const float* b2   = (const float*)d_in[20];

    cudaFuncSetAttribute(k_proj,    cudaFuncAttributeMaxDynamicSharedMemorySize, PROJ_SMEM);
    cudaFuncSetAttribute(k_attn_wm, cudaFuncAttributeMaxDynamicSharedMemorySize, ATTN_SMEM);
    cudaFuncSetAttribute(k_fin,     cudaFuncAttributeMaxDynamicSharedMemorySize, FIN_SMEM);

    k_init<<<512, 256>>>(xv, xc);
    const int projBlocks = (NM + 127) / 128;
    for (int it = 0; it < NITER; it++) {
        k_proj<<<projBlocks, 256, PROJ_SMEM>>>(WQ1, WK1, WV1);  // also zeroes g_acc/g_cnt
        k_attn_wm<<<NC, 384, ATTN_SMEM>>>(cvar, ccla, sat, hw1);
        k_fin<<<projBlocks, 256, FIN_SMEM>>>(Wo, bo);
        k_cf<<<NC, 64>>>(cvar, WQ2, WK2, WV2);
        k_edge<<<(NE + 7) / 8, 256>>>(ei, shv, hw2);
    }
    k_poolzero<<<1, 128>>>();
    k_pool<<<512, 256>>>();
    k_mlp<<<1, 128>>>(W1, b1, W2, b2, (float*)d_out);
}

// round 7
// speedup vs baseline: 1.4764x; 1.1965x over previous
#include <cuda_runtime.h>
#include <cuda_fp16.h>
#include <math.h>
#include <cstdint>
#include <mma.h>

using namespace nvcuda;

#define N_VAR 50000
#define N_CLA 100000
#define NM    150000
#define DD    64
#define NC    1000
#define VC    64
#define KCL   128
#define NN    192
#define NE    8000
#define NSH   8
#define NITER 3
#define NEG   0.2f
#define INVSCALE 0.125f

// tf32 fragments (k_proj / k_fin)
typedef wmma::fragment<wmma::matrix_a, 16, 16, 8, wmma::precision::tf32, wmma::row_major> AFrag;
typedef wmma::fragment<wmma::matrix_b, 16, 16, 8, wmma::precision::tf32, wmma::col_major> BFragC;
typedef wmma::fragment<wmma::accumulator, 16, 16, 8, float> CFrag;
// fp16 fragments (k_attn)
typedef wmma::fragment<wmma::matrix_a, 16, 16, 16, __half, wmma::row_major> HA;
typedef wmma::fragment<wmma::matrix_b, 16, 16, 16, __half, wmma::col_major> HBC;
typedef wmma::fragment<wmma::matrix_b, 16, 16, 16, __half, wmma::row_major> HBR;
typedef wmma::fragment<wmma::accumulator, 16, 16, 16, float> HC;

template <typename F>
__device__ __forceinline__ void to_tf32(F& f) {
    #pragma unroll
    for (int t = 0; t < f.num_elements; t++) f.x[t] = wmma::__float_to_tf32(f.x[t]);
}

__device__ __forceinline__ void red_add_v4(float* p, float4 v) {
    asm volatile("red.global.add.v4.f32 [%0], {%1,%2,%3,%4};"
                 :: "l"(p), "f"(v.x), "f"(v.y), "f"(v.z), "f"(v.w) : "memory");
}

// ---------------- scratch ----------------------------------------------------
__device__ float  g_x  [NM * DD];
__device__ __half g_Qh [NM * DD];
__device__ __half g_Kh [NM * DD];
__device__ __half g_Vh [NM * DD];
__device__ float  g_acc[NM * DD];
__device__ float  g_cnt[NM];
__device__ float  g_Q2 [NC * DD];
__device__ float  g_K2 [NC * DD];
__device__ float  g_V2 [NC * DD];
__device__ float  g_pool[2 * DD];

__global__ void k_init(const float* __restrict__ xv, const float* __restrict__ xc) {
    int stride = gridDim.x * blockDim.x;
    for (int i = blockIdx.x * blockDim.x + threadIdx.x; i < NM * DD; i += stride)
        g_x[i] = (i < N_VAR * DD) ? xv[i] : xc[i - N_VAR * DD];
}
__global__ void k_poolzero() { if (threadIdx.x < 2 * DD) g_pool[threadIdx.x] = 0.f; }

// ---------------- Q/K/V projection via WMMA tf32, half outputs ---------------
// 128 rows/CTA, 8 warps. Output staged through the (dead) A-band of xs, then
// converted to half (Q pre-scaled by INVSCALE). Also zeroes g_acc/g_cnt.
#define PROJ_SMEM ((3 * 64 * 72 + 128 * 72) * 4)
__global__ void __launch_bounds__(256) k_proj(const float* __restrict__ WQ,
                                              const float* __restrict__ WK,
                                              const float* __restrict__ WV) {
    extern __shared__ float sm[];
    float* Wp = sm;               // 3 * 64*72 : (k,d) at m*4608 + d*72 + k
    float* xs = sm + 3 * 64 * 72; // 128*72 row-major (input, then per-warp out)
    int tid = threadIdx.x, wid = tid >> 5, lane = tid & 31;

    for (int i = tid; i < 3 * 64 * 64; i += 256) {
        int m = i >> 12, d = (i >> 6) & 63, k = i & 63;
        const float* W = (m == 0) ? WQ : ((m == 1) ? WK : WV);
        Wp[m * 4608 + d * 72 + k] = W[d * 64 + k];
    }
    size_t base = (size_t)blockIdx.x * 128;
    for (int i = tid; i < 128 * 16; i += 256) {
        int row = i >> 4, q4 = i & 15;
        size_t r = base + row;
        if (r < NM)
            ((float4*)(xs + row * 72))[q4] = ((const float4*)(g_x + r * 64))[q4];
    }
    __syncthreads();

    if (base + (size_t)wid * 16 < NM) {
        AFrag a[8];
        #pragma unroll
        for (int k = 0; k < 8; k++) {
            wmma::load_matrix_sync(a[k], xs + wid * 16 * 72 + k * 8, 72);
            to_tf32(a[k]);
        }
        __half* outs[3] = {g_Qh, g_Kh, g_Vh};
        float* band = xs + wid * 16 * 72;
        #pragma unroll
        for (int m = 0; m < 3; m++) {
            #pragma unroll
            for (int tc = 0; tc < 4; tc++) {
                CFrag acc;
                wmma::fill_fragment(acc, 0.f);
                #pragma unroll
                for (int k = 0; k < 8; k++) {
                    BFragC b;
                    wmma::load_matrix_sync(b, Wp + m * 4608 + tc * 16 * 72 + k * 8, 72);
                    to_tf32(b);
                    wmma::mma_sync(acc, a[k], b, acc);
                }
                wmma::store_matrix_sync(band + tc * 16, acc, 72, wmma::mem_row_major);
            }
            __syncwarp();
            float scl = (m == 0) ? INVSCALE : 1.f;
            __half* dst = outs[m] + (base + wid * 16) * 64;
            for (int i = lane; i < 128; i += 32) {      // 16 rows x 8 col-chunks
                int row = i >> 3, c8 = i & 7;
                float4 f0 = *(const float4*)(band + row * 72 + c8 * 8);
                float4 f1 = *(const float4*)(band + row * 72 + c8 * 8 + 4);
                __half2 h0 = __floats2half2_rn(f0.x * scl, f0.y * scl);
                __half2 h1 = __floats2half2_rn(f0.z * scl, f0.w * scl);
                __half2 h2 = __floats2half2_rn(f1.x * scl, f1.y * scl);
                __half2 h3 = __floats2half2_rn(f1.z * scl, f1.w * scl);
                uint4 u;
                u.x = *(uint32_t*)&h0; u.y = *(uint32_t*)&h1;
                u.z = *(uint32_t*)&h2; u.w = *(uint32_t*)&h3;
                *(uint4*)(dst + row * 64 + c8 * 8) = u;
            }
            __syncwarp();
        }
    }
    float4 z4 = make_float4(0.f, 0.f, 0.f, 0.f);
    for (int i = tid; i < 128 * 16; i += 256) {
        int row = i >> 4, q4 = i & 15;
        size_t r = base + row;
        if (r < NM) ((float4*)(g_acc + r * 64))[q4] = z4;
    }
    for (int i = tid; i < 128; i += 256)
        if (base + i < NM) g_cnt[base + i] = 0.f;
}

// ---------------- intra-cluster attention via WMMA fp16 ----------------------
#define OFFB_K  0
#define OFFB_V  30720
#define OFFB_Q  61440
#define OFFB_S  76800
#define OFFB_P  153600
#define OFFB_RS 192000
#define OFFB_B  192384
#define OFFB_N  193152
#define ATTN_SMEM 193920

__global__ void __launch_bounds__(384, 1) k_attn_wm(const int* __restrict__ cvar,
                                                    const int* __restrict__ ccla,
                                                    const float* __restrict__ sat,
                                                    const float* __restrict__ hw) {
    extern __shared__ char smem[];
    __half* Kh = (__half*)(smem + OFFB_K);     // [192][80]
    __half* Vh = (__half*)(smem + OFFB_V);     // [192][80]
    __half* Qh = (__half*)(smem + OFFB_Q);     // [96][80]
    float*  Sf = (float*)(smem + OFFB_S);      // [96][200] scores; reused [96][72] O
    __half* Ph = (__half*)(smem + OFFB_P);     // [96][200] exp weights
    float*  rowsum = (float*)(smem + OFFB_RS); // [96]
    float*  bsh = (float*)(smem + OFFB_B);     // [192]
    int*    nsh = (int*)(smem + OFFB_N);       // [192]

    int c = blockIdx.x, tid = threadIdx.x, wid = tid >> 5;
    if (tid < NN) {
        int g; float b;
        if (tid < VC) { g = cvar[c * VC + tid]; b = 0.f; }
        else { int cl = ccla[c * KCL + (tid - VC)]; g = N_VAR + cl; b = sat[cl]; }
        nsh[tid] = g; bsh[tid] = b;
    }
    float hwm = 0.25f * (hw[0] + hw[1] + hw[2] + hw[3]);
    __syncthreads();

    // gather K/V (already half in global)
    for (int idx = tid; idx < 192 * 8; idx += 384) {
        int row = idx >> 3, q8 = idx & 7;
        size_t o = (size_t)nsh[row] * 64;
        *(uint4*)(Kh + row * 80 + q8 * 8) = ((const uint4*)(g_Kh + o))[q8];
        *(uint4*)(Vh + row * 80 + q8 * 8) = ((const uint4*)(g_Vh + o))[q8];
    }

    int srow = tid >> 2, sc0 = tid & 3;

    for (int band = 0; band < 2; band++) {
        for (int idx = tid; idx < 96 * 8; idx += 384) {
            int row = idx >> 3, q8 = idx & 7;
            *(uint4*)(Qh + row * 80 + q8 * 8) =
                ((const uint4*)(g_Qh + (size_t)nsh[band * 96 + row] * 64))[q8];
        }
        __syncthreads();

        // GEMM1: S[96,192] = Qh @ Kh^T (Q pre-scaled by 1/sqrt(D))
        {
            int tr = wid % 6, tcg = (wid / 6) * 6;
            HA a[4];
            #pragma unroll
            for (int k = 0; k < 4; k++)
                wmma::load_matrix_sync(a[k], Qh + tr * 16 * 80 + k * 16, 80);
            #pragma unroll
            for (int tcx = 0; tcx < 6; tcx++) {
                int tc = tcg + tcx;
                HC acc;
                wmma::fill_fragment(acc, 0.f);
                #pragma unroll
                for (int k = 0; k < 4; k++) {
                    HBC b;
                    wmma::load_matrix_sync(b, Kh + tc * 16 * 80 + k * 16, 80);
                    wmma::mma_sync(acc, a[k], b, acc);
                }
                wmma::store_matrix_sync(Sf + tr * 16 * 200 + tc * 16, acc, 200,
                                        wmma::mem_row_major);
            }
        }
        __syncthreads();

        // softmax: 96 rows x 4-thread quads; exp weights -> Ph (half)
        {
            float* srw = Sf + srow * 200;
            __half* prw = Ph + srow * 200;
            float mx = -1e30f;
            float v[48];
            #pragma unroll 8
            for (int i = 0; i < 48; i++) {
                int col = sc0 + 4 * i;
                float s = srw[col] + bsh[col];
                s = (s >= 0.f) ? s : NEG * s;
                v[i] = s;
                mx = fmaxf(mx, s);
            }
            mx = fmaxf(mx, __shfl_xor_sync(0xffffffffu, mx, 1));
            mx = fmaxf(mx, __shfl_xor_sync(0xffffffffu, mx, 2));
            float sum = 0.f;
            #pragma unroll 8
            for (int i = 0; i < 48; i++) {
                float e = __expf(v[i] - mx);
                sum += e;
                prw[sc0 + 4 * i] = __float2half_rn(e);
            }
            sum += __shfl_xor_sync(0xffffffffu, sum, 1);
            sum += __shfl_xor_sync(0xffffffffu, sum, 2);
            if (sc0 == 0) rowsum[srow] = sum;
        }
        __syncthreads();

        // GEMM2: O[96,64] = P @ V; stage O into Sf [96][72]
        {
            int tr2 = wid >> 1, tc0 = (wid & 1) * 2;
            HC o0, o1;
            wmma::fill_fragment(o0, 0.f);
            wmma::fill_fragment(o1, 0.f);
            #pragma unroll 4
            for (int k = 0; k < 12; k++) {
                HA a;
                wmma::load_matrix_sync(a, Ph + tr2 * 16 * 200 + k * 16, 200);
                HBR b0, b1;
                wmma::load_matrix_sync(b0, Vh + k * 16 * 80 + tc0 * 16, 80);
                wmma::load_matrix_sync(b1, Vh + k * 16 * 80 + (tc0 + 1) * 16, 80);
                wmma::mma_sync(o0, a, b0, o0);
                wmma::mma_sync(o1, a, b1, o1);
            }
            wmma::store_matrix_sync(Sf + tr2 * 16 * 72 + tc0 * 16, o0, 72,
                                    wmma::mem_row_major);
            wmma::store_matrix_sync(Sf + tr2 * 16 * 72 + (tc0 + 1) * 16, o1, 72,
                                    wmma::mem_row_major);
        }
        __syncthreads();

        // vectorized scatter-add with hwm / rowsum scale
        {
            int g = nsh[band * 96 + srow];
            float scl = hwm / rowsum[srow];
            const float* src = Sf + srow * 72 + sc0 * 16;
            float* dst = g_acc + (size_t)g * 64 + sc0 * 16;
            #pragma unroll
            for (int j = 0; j < 4; j++) {
                float4 v = *(const float4*)(src + j * 4);
                v.x *= scl; v.y *= scl; v.z *= scl; v.w *= scl;
                red_add_v4(dst + j * 4, v);
            }
            if (sc0 == 0) atomicAdd(&g_cnt[g], 1.f);
        }
        __syncthreads();
    }
}

// ---------------- finalize via WMMA tf32 (epilogue through A-band) -----------
#define FIN_SMEM ((64 * 72 + 128 * 72) * 4)
__global__ void __launch_bounds__(256) k_fin(const float* __restrict__ Wo,
                                             const float* __restrict__ bo) {
    extern __shared__ float sm[];
    float* Wt = sm;                 // [64][72] col-major: (k,d) at d*72+k
    float* xs = Wt + 64 * 72;       // [128][72] input, then per-warp output
    int tid = threadIdx.x, wid = tid >> 5, lane = tid & 31;

    for (int i = tid; i < 64 * 64; i += 256) {
        int d = i >> 6, k = i & 63;
        Wt[d * 72 + k] = Wo[i];
    }
    size_t base = (size_t)blockIdx.x * 128;
    for (int i = tid; i < 128 * 16; i += 256) {
        int row = i >> 4, q4 = i & 15;
        size_t r = base + row;
        if (r < NM) {
            float inv = 1.f / fmaxf(g_cnt[r], 1.f);
            float4 a = ((const float4*)(g_acc + r * 64))[q4];
            a.x *= inv; a.y *= inv; a.z *= inv; a.w *= inv;
            ((float4*)(xs + row * 72))[q4] = a;
        }
    }
    __syncthreads();

    if (base + (size_t)wid * 16 < NM) {
        float* band = xs + wid * 16 * 72;
        AFrag a[8];
        #pragma unroll
        for (int k = 0; k < 8; k++) {
            wmma::load_matrix_sync(a[k], band + k * 8, 72);
            to_tf32(a[k]);
        }
        #pragma unroll
        for (int tc = 0; tc < 4; tc++) {
            CFrag acc;
            wmma::fill_fragment(acc, 0.f);
            #pragma unroll
            for (int k = 0; k < 8; k++) {
                BFragC b;
                wmma::load_matrix_sync(b, Wt + tc * 16 * 72 + k * 8, 72);
                to_tf32(b);
                wmma::mma_sync(acc, a[k], b, acc);
            }
            wmma::store_matrix_sync(band + tc * 16, acc, 72, wmma::mem_row_major);
        }
        __syncwarp();
        for (int i = lane; i < 16 * 16; i += 32) {
            int row = i >> 4, q4 = i & 15;
            size_t r = base + wid * 16 + row;
            float4 y = *(const float4*)(band + row * 72 + q4 * 4);
            float4 x = ((const float4*)(g_x + r * 64))[q4];
            float4 b = ((const float4*)bo)[q4];
            x.x += y.x + b.x; x.y += y.y + b.y;
            x.z += y.z + b.z; x.w += y.w + b.w;
            ((float4*)(g_x + r * 64))[q4] = x;
        }
    }
}

// ---------------- cluster features + Q2/K2/V2 projection ---------------------
__global__ void k_cf(const int* __restrict__ cvar,
                     const float* __restrict__ WQ2, const float* __restrict__ WK2,
                     const float* __restrict__ WV2) {
    __shared__ float cf[64];
    __shared__ int ids[64];
    int c = blockIdx.x, d = threadIdx.x;
    ids[d] = cvar[c * VC + d];
    __syncthreads();
    float s = 0.f;
    #pragma unroll 8
    for (int v = 0; v < VC; v++) s += g_x[(size_t)ids[v] * DD + d];
    cf[d] = s * (1.f / 64.f);
    __syncthreads();
    float q = 0.f, k = 0.f, v = 0.f;
    #pragma unroll 8
    for (int j = 0; j < 64; j++) {
        float x = cf[j];
        q = fmaf(x, WQ2[d * 64 + j], q);
        k = fmaf(x, WK2[d * 64 + j], k);
        v = fmaf(x, WV2[d * 64 + j], v);
    }
    g_Q2[c * 64 + d] = q; g_K2[c * 64 + d] = k; g_V2[c * 64 + d] = v;
}

// ---------------- inter-cluster edge scatter (GAT2, vectorized atomics) ------
__global__ void k_edge(const int* __restrict__ ei, const int* __restrict__ shv,
                       const float* __restrict__ hw) {
    int tid = threadIdx.x;
    int warp = tid >> 5, lane = tid & 31;
    int e = blockIdx.x * 8 + warp;
    if (e >= NE) return;
    int c1 = ei[e], c2 = ei[NE + e];
    float p = g_Q2[c1 * 64 + lane] * g_K2[c2 * 64 + lane]
            + g_Q2[c1 * 64 + lane + 32] * g_K2[c2 * 64 + lane + 32];
    #pragma unroll
    for (int o = 16; o > 0; o >>= 1) p += __shfl_xor_sync(0xffffffffu, p, o);
    float s = p * INVSCALE;
    float lr = (s >= 0.f) ? s : NEG * s;
    float hwm = 0.25f * (hw[0] + hw[1] + hw[2] + hw[3]);
    float a = hwm / (1.f + __expf(-lr));
    float4 v4 = make_float4(0.f, 0.f, 0.f, 0.f);
    if (lane < 16) {
        v4 = ((const float4*)(g_V2 + (size_t)c2 * 64))[lane];
        v4.x *= a; v4.y *= a; v4.z *= a; v4.w *= a;
    }
    #pragma unroll
    for (int k = 0; k < NSH; k++) {
        int sv = shv[e * NSH + k];
        if (lane < 16) red_add_v4(g_x + (size_t)sv * 64 + lane * 4, v4);
    }
}

// ---------------- pooling + MLP readout --------------------------------------
__global__ void k_pool() {
    int tid = threadIdx.x;
    int col = tid & 63;
    int rg = tid >> 6;
    float sv = 0.f, sc = 0.f;
    for (int r = blockIdx.x * 4 + rg; r < NM; r += gridDim.x * 4) {
        float x = g_x[(size_t)r * DD + col];
        if (r < N_VAR) sv += x; else sc += x;
    }
    atomicAdd(&g_pool[col], sv);
    atomicAdd(&g_pool[64 + col], sc);
}

__global__ void k_mlp(const float* __restrict__ W1, const float* __restrict__ b1,
                      const float* __restrict__ W2, const float* __restrict__ b2,
                      float* __restrict__ out) {
    __shared__ float p[128];
    __shared__ float h[64];
    int tid = threadIdx.x;
    if (tid < 128)
        p[tid] = tanhf(g_pool[tid] * (tid < 64 ? 1.f / N_VAR : 1.f / N_CLA));
    __syncthreads();
    if (tid < 64) {
        float a = b1[tid];
        #pragma unroll 8
        for (int j = 0; j < 128; j++) a = fmaf(p[j], W1[tid * 128 + j], a);
        h[tid] = (a > 0.f) ? a : 0.f;
    }
    __syncthreads();
    if (tid == 0) {
        float s = b2[0];
        for (int i = 0; i < 64; i++) s = fmaf(h[i], W2[i], s);
        out[0] = s;
    }
}

// ---------------- launch ------------------------------------------------------
extern "C" void kernel_launch(void* const* d_in, const int* in_sizes, int n_in,
                              void* d_out, int out_size) {
    (void)in_sizes; (void)n_in; (void)out_size;
    const float* xv   = (const float*)d_in[0];
    const float* xc   = (const float*)d_in[1];
    const float* sat  = (const float*)d_in[2];
    const int*   cvar = (const int*)d_in[3];
    const int*   ccla = (const int*)d_in[4];
    const int*   ei   = (const int*)d_in[5];
    const int*   shv  = (const int*)d_in[6];
    const float* WQ1  = (const float*)d_in[7];
    const float* WK1  = (const float*)d_in[8];
    const float* WV1  = (const float*)d_in[9];
    const float* hw1  = (const float*)d_in[10];
    const float* Wo   = (const float*)d_in[11];
    const float* bo   = (const float*)d_in[12];
    const float* WQ2  = (const float*)d_in[13];
    const float* WK2  = (const float*)d_in[14];
    const float* WV2  = (const float*)d_in[15];
    const float* hw2  = (const float*)d_in[16];
    const float* W1   = (const float*)d_in[17];
    const float* b1   = (const float*)d_in[18];
    const float* W2   = (const float*)d_in[19];
    const float* b2   = (const float*)d_in[20];

    cudaFuncSetAttribute(k_proj,    cudaFuncAttributeMaxDynamicSharedMemorySize, PROJ_SMEM);
    cudaFuncSetAttribute(k_attn_wm, cudaFuncAttributeMaxDynamicSharedMemorySize, ATTN_SMEM);
    cudaFuncSetAttribute(k_fin,     cudaFuncAttributeMaxDynamicSharedMemorySize, FIN_SMEM);

    k_init<<<512, 256>>>(xv, xc);
    const int projBlocks = (NM + 127) / 128;
    for (int it = 0; it < NITER; it++) {
        k_proj<<<projBlocks, 256, PROJ_SMEM>>>(WQ1, WK1, WV1);  // also zeroes g_acc/g_cnt
        k_attn_wm<<<NC, 384, ATTN_SMEM>>>(cvar, ccla, sat, hw1);
        k_fin<<<projBlocks, 256, FIN_SMEM>>>(Wo, bo);
        k_cf<<<NC, 64>>>(cvar, WQ2, WK2, WV2);
        k_edge<<<(NE + 7) / 8, 256>>>(ei, shv, hw2);
    }
    k_poolzero<<<1, 128>>>();
    k_pool<<<512, 256>>>();
    k_mlp<<<1, 128>>>(W1, b1, W2, b2, (float*)d_out);
}

// round 8
// speedup vs baseline: 1.6078x; 1.0890x over previous
#include <cuda_runtime.h>
#include <cuda_fp16.h>
#include <math.h>
#include <cstdint>
#include <mma.h>

using namespace nvcuda;

#define N_VAR 50000
#define N_CLA 100000
#define NM    150000
#define DD    64
#define NC    1000
#define VC    64
#define KCL   128
#define NN    192
#define NE    8000
#define NSH   8
#define NITER 3
#define NEG   0.2f
#define INVSCALE 0.125f

// tf32 fragments (k_proj / k_fin)
typedef wmma::fragment<wmma::matrix_a, 16, 16, 8, wmma::precision::tf32, wmma::row_major> AFrag;
typedef wmma::fragment<wmma::matrix_b, 16, 16, 8, wmma::precision::tf32, wmma::col_major> BFragC;
typedef wmma::fragment<wmma::accumulator, 16, 16, 8, float> CFrag;
// fp16 fragments (k_attn)
typedef wmma::fragment<wmma::matrix_a, 16, 16, 16, __half, wmma::row_major> HA;
typedef wmma::fragment<wmma::matrix_b, 16, 16, 16, __half, wmma::col_major> HBC;
typedef wmma::fragment<wmma::matrix_b, 16, 16, 16, __half, wmma::row_major> HBR;
typedef wmma::fragment<wmma::accumulator, 16, 16, 16, float> HC;

template <typename F>
__device__ __forceinline__ void to_tf32(F& f) {
    #pragma unroll
    for (int t = 0; t < f.num_elements; t++) f.x[t] = wmma::__float_to_tf32(f.x[t]);
}

__device__ __forceinline__ void red_add_v4(float* p, float4 v) {
    asm volatile("red.global.add.v4.f32 [%0], {%1,%2,%3,%4};"
                 :: "l"(p), "f"(v.x), "f"(v.y), "f"(v.z), "f"(v.w) : "memory");
}

// ---------------- scratch ----------------------------------------------------
__device__ float  g_x  [NM * DD];
__device__ __half g_Qh [NM * DD];
__device__ __half g_Kh [NM * DD];
__device__ __half g_Vh [NM * DD];
__device__ float  g_acc[NM * DD];
__device__ float  g_cnt[NM];
__device__ float  g_Q2 [NC * DD];
__device__ float  g_K2 [NC * DD];
__device__ float  g_V2 [NC * DD];
__device__ float  g_pool[2 * DD];

__global__ void k_init(const float* __restrict__ xv, const float* __restrict__ xc) {
    int stride = gridDim.x * blockDim.x;
    for (int i = blockIdx.x * blockDim.x + threadIdx.x; i < NM * DD; i += stride)
        g_x[i] = (i < N_VAR * DD) ? xv[i] : xc[i - N_VAR * DD];
}
__global__ void k_poolzero() { if (threadIdx.x < 2 * DD) g_pool[threadIdx.x] = 0.f; }

// ---------------- Q/K/V projection via WMMA tf32, half outputs ---------------
#define PROJ_SMEM ((3 * 64 * 72 + 128 * 72) * 4)
__global__ void __launch_bounds__(256) k_proj(const float* __restrict__ WQ,
                                              const float* __restrict__ WK,
                                              const float* __restrict__ WV) {
    extern __shared__ float sm[];
    float* Wp = sm;               // 3 * 64*72 : (k,d) at m*4608 + d*72 + k
    float* xs = sm + 3 * 64 * 72; // 128*72 row-major (input, then per-warp out)
    int tid = threadIdx.x, wid = tid >> 5, lane = tid & 31;

    for (int i = tid; i < 3 * 64 * 64; i += 256) {
        int m = i >> 12, d = (i >> 6) & 63, k = i & 63;
        const float* W = (m == 0) ? WQ : ((m == 1) ? WK : WV);
        Wp[m * 4608 + d * 72 + k] = W[d * 64 + k];
    }
    size_t base = (size_t)blockIdx.x * 128;
    for (int i = tid; i < 128 * 16; i += 256) {
        int row = i >> 4, q4 = i & 15;
        size_t r = base + row;
        if (r < NM)
            ((float4*)(xs + row * 72))[q4] = ((const float4*)(g_x + r * 64))[q4];
    }
    __syncthreads();

    if (base + (size_t)wid * 16 < NM) {
        AFrag a[8];
        #pragma unroll
        for (int k = 0; k < 8; k++) {
            wmma::load_matrix_sync(a[k], xs + wid * 16 * 72 + k * 8, 72);
            to_tf32(a[k]);
        }
        __half* outs[3] = {g_Qh, g_Kh, g_Vh};
        float* band = xs + wid * 16 * 72;
        #pragma unroll
        for (int m = 0; m < 3; m++) {
            #pragma unroll
            for (int tc = 0; tc < 4; tc++) {
                CFrag acc;
                wmma::fill_fragment(acc, 0.f);
                #pragma unroll
                for (int k = 0; k < 8; k++) {
                    BFragC b;
                    wmma::load_matrix_sync(b, Wp + m * 4608 + tc * 16 * 72 + k * 8, 72);
                    to_tf32(b);
                    wmma::mma_sync(acc, a[k], b, acc);
                }
                wmma::store_matrix_sync(band + tc * 16, acc, 72, wmma::mem_row_major);
            }
            __syncwarp();
            float scl = (m == 0) ? INVSCALE : 1.f;
            __half* dst = outs[m] + (base + wid * 16) * 64;
            for (int i = lane; i < 128; i += 32) {      // 16 rows x 8 col-chunks
                int row = i >> 3, c8 = i & 7;
                float4 f0 = *(const float4*)(band + row * 72 + c8 * 8);
                float4 f1 = *(const float4*)(band + row * 72 + c8 * 8 + 4);
                __half2 h0 = __floats2half2_rn(f0.x * scl, f0.y * scl);
                __half2 h1 = __floats2half2_rn(f0.z * scl, f0.w * scl);
                __half2 h2 = __floats2half2_rn(f1.x * scl, f1.y * scl);
                __half2 h3 = __floats2half2_rn(f1.z * scl, f1.w * scl);
                uint4 u;
                u.x = *(uint32_t*)&h0; u.y = *(uint32_t*)&h1;
                u.z = *(uint32_t*)&h2; u.w = *(uint32_t*)&h3;
                *(uint4*)(dst + row * 64 + c8 * 8) = u;
            }
            __syncwarp();
        }
    }
    float4 z4 = make_float4(0.f, 0.f, 0.f, 0.f);
    for (int i = tid; i < 128 * 16; i += 256) {
        int row = i >> 4, q4 = i & 15;
        size_t r = base + row;
        if (r < NM) ((float4*)(g_acc + r * 64))[q4] = z4;
    }
    for (int i = tid; i < 128; i += 256)
        if (base + i < NM) g_cnt[base + i] = 0.f;
}

// ---------------- intra-cluster attention via WMMA fp16 ----------------------
// 6 bands x 32 queries; smem ~97.6KB -> 2 CTAs/SM. K/V/Q ld=72 halves.
#define OFFB_K  0
#define OFFB_V  27648
#define OFFB_Q  55296
#define OFFB_S  59904
#define OFFB_P  85504
#define OFFB_RS 98304
#define OFFB_B  98432
#define OFFB_N  99200
#define ATTN_SMEM 99968

__global__ void __launch_bounds__(384, 2) k_attn_wm(const int* __restrict__ cvar,
                                                    const int* __restrict__ ccla,
                                                    const float* __restrict__ sat,
                                                    const float* __restrict__ hw) {
    extern __shared__ char smem[];
    __half* Kh = (__half*)(smem + OFFB_K);     // [192][72]
    __half* Vh = (__half*)(smem + OFFB_V);     // [192][72]
    __half* Qh = (__half*)(smem + OFFB_Q);     // [32][72]
    float*  Sf = (float*)(smem + OFFB_S);      // [32][200] scores; reused [32][72] O
    __half* Ph = (__half*)(smem + OFFB_P);     // [32][200] exp weights
    float*  rowsum = (float*)(smem + OFFB_RS); // [32]
    float*  bsh = (float*)(smem + OFFB_B);     // [192]
    int*    nsh = (int*)(smem + OFFB_N);       // [192]

    int c = blockIdx.x, tid = threadIdx.x, wid = tid >> 5;
    if (tid < NN) {
        int g; float b;
        if (tid < VC) { g = cvar[c * VC + tid]; b = 0.f; }
        else { int cl = ccla[c * KCL + (tid - VC)]; g = N_VAR + cl; b = sat[cl]; }
        nsh[tid] = g; bsh[tid] = b;
    }
    float hwm = 0.25f * (hw[0] + hw[1] + hw[2] + hw[3]);
    __syncthreads();

    // gather K/V (half in global, 8 uint4 per row; cols 64..71 unread pad)
    for (int idx = tid; idx < 192 * 8; idx += 384) {
        int row = idx >> 3, q8 = idx & 7;
        size_t o = (size_t)nsh[row] * 64;
        *(uint4*)(Kh + row * 72 + q8 * 8) = ((const uint4*)(g_Kh + o))[q8];
        *(uint4*)(Vh + row * 72 + q8 * 8) = ((const uint4*)(g_Vh + o))[q8];
    }

    for (int band = 0; band < 6; band++) {
        // gather 32-query band
        for (int idx = tid; idx < 32 * 8; idx += 384) {
            int row = idx >> 3, q8 = idx & 7;
            *(uint4*)(Qh + row * 72 + q8 * 8) =
                ((const uint4*)(g_Qh + (size_t)nsh[band * 32 + row] * 64))[q8];
        }
        __syncthreads();

        // GEMM1: S[32,192] = Qh @ Kh^T  (2 row-tiles x 12 col-tiles; 2 per warp)
        {
            int tr = wid & 1, tc = wid >> 1;
            HA a[4];
            #pragma unroll
            for (int k = 0; k < 4; k++)
                wmma::load_matrix_sync(a[k], Qh + tr * 16 * 72 + k * 16, 72);
            #pragma unroll
            for (int half2x = 0; half2x < 2; half2x++) {
                int tcc = tc + half2x * 6;
                HC acc;
                wmma::fill_fragment(acc, 0.f);
                #pragma unroll
                for (int k = 0; k < 4; k++) {
                    HBC b;
                    wmma::load_matrix_sync(b, Kh + tcc * 16 * 72 + k * 16, 72);
                    wmma::mma_sync(acc, a[k], b, acc);
                }
                wmma::store_matrix_sync(Sf + tr * 16 * 200 + tcc * 16, acc, 200,
                                        wmma::mem_row_major);
            }
        }
        __syncthreads();

        // softmax: 32 rows x 8-thread groups (tid<256); exp weights -> Ph
        if (tid < 256) {
            int srow = tid >> 3, c0 = tid & 7;
            float* srw = Sf + srow * 200;
            __half* prw = Ph + srow * 200;
            float mx = -1e30f;
            float v[24];
            #pragma unroll 8
            for (int i = 0; i < 24; i++) {
                int col = c0 + 8 * i;
                float s = srw[col] + bsh[col];
                s = (s >= 0.f) ? s : NEG * s;
                v[i] = s;
                mx = fmaxf(mx, s);
            }
            mx = fmaxf(mx, __shfl_xor_sync(0xffffffffu, mx, 1));
            mx = fmaxf(mx, __shfl_xor_sync(0xffffffffu, mx, 2));
            mx = fmaxf(mx, __shfl_xor_sync(0xffffffffu, mx, 4));
            float sum = 0.f;
            #pragma unroll 8
            for (int i = 0; i < 24; i++) {
                float e = __expf(v[i] - mx);
                sum += e;
                prw[c0 + 8 * i] = __float2half_rn(e);
            }
            sum += __shfl_xor_sync(0xffffffffu, sum, 1);
            sum += __shfl_xor_sync(0xffffffffu, sum, 2);
            sum += __shfl_xor_sync(0xffffffffu, sum, 4);
            if (c0 == 0) rowsum[srow] = sum;
        }
        __syncthreads();

        // GEMM2: O[32,64] = P @ V (8 warps); stage O into Sf [32][72]
        if (wid < 8) {
            int tr2 = wid >> 2, tc = wid & 3;
            HC o0;
            wmma::fill_fragment(o0, 0.f);
            #pragma unroll 4
            for (int k = 0; k < 12; k++) {
                HA a;
                wmma::load_matrix_sync(a, Ph + tr2 * 16 * 200 + k * 16, 200);
                HBR b0;
                wmma::load_matrix_sync(b0, Vh + k * 16 * 72 + tc * 16, 72);
                wmma::mma_sync(o0, a, b0, o0);
            }
            wmma::store_matrix_sync(Sf + tr2 * 16 * 72 + tc * 16, o0, 72,
                                    wmma::mem_row_major);
        }
        __syncthreads();

        // vectorized scatter-add (tid<128): 32 rows x 4 quads
        if (tid < 128) {
            int srow = tid >> 2, sc0 = tid & 3;
            int g = nsh[band * 32 + srow];
            float scl = hwm / rowsum[srow];
            const float* src = Sf + srow * 72 + sc0 * 16;
            float* dst = g_acc + (size_t)g * 64 + sc0 * 16;
            #pragma unroll
            for (int j = 0; j < 4; j++) {
                float4 v = *(const float4*)(src + j * 4);
                v.x *= scl; v.y *= scl; v.z *= scl; v.w *= scl;
                red_add_v4(dst + j * 4, v);
            }
            if (sc0 == 0) atomicAdd(&g_cnt[g], 1.f);
        }
        __syncthreads();
    }
}

// ---------------- finalize via WMMA tf32 (epilogue through A-band) -----------
#define FIN_SMEM ((64 * 72 + 128 * 72) * 4)
__global__ void __launch_bounds__(256) k_fin(const float* __restrict__ Wo,
                                             const float* __restrict__ bo) {
    extern __shared__ float sm[];
    float* Wt = sm;                 // [64][72] col-major: (k,d) at d*72+k
    float* xs = Wt + 64 * 72;       // [128][72] input, then per-warp output
    int tid = threadIdx.x, wid = tid >> 5, lane = tid & 31;

    for (int i = tid; i < 64 * 64; i += 256) {
        int d = i >> 6, k = i & 63;
        Wt[d * 72 + k] = Wo[i];
    }
    size_t base = (size_t)blockIdx.x * 128;
    for (int i = tid; i < 128 * 16; i += 256) {
        int row = i >> 4, q4 = i & 15;
        size_t r = base + row;
        if (r < NM) {
            float inv = 1.f / fmaxf(g_cnt[r], 1.f);
            float4 a = ((const float4*)(g_acc + r * 64))[q4];
            a.x *= inv; a.y *= inv; a.z *= inv; a.w *= inv;
            ((float4*)(xs + row * 72))[q4] = a;
        }
    }
    __syncthreads();

    if (base + (size_t)wid * 16 < NM) {
        float* band = xs + wid * 16 * 72;
        AFrag a[8];
        #pragma unroll
        for (int k = 0; k < 8; k++) {
            wmma::load_matrix_sync(a[k], band + k * 8, 72);
            to_tf32(a[k]);
        }
        #pragma unroll
        for (int tc = 0; tc < 4; tc++) {
            CFrag acc;
            wmma::fill_fragment(acc, 0.f);
            #pragma unroll
            for (int k = 0; k < 8; k++) {
                BFragC b;
                wmma::load_matrix_sync(b, Wt + tc * 16 * 72 + k * 8, 72);
                to_tf32(b);
                wmma::mma_sync(acc, a[k], b, acc);
            }
            wmma::store_matrix_sync(band + tc * 16, acc, 72, wmma::mem_row_major);
        }
        __syncwarp();
        for (int i = lane; i < 16 * 16; i += 32) {
            int row = i >> 4, q4 = i & 15;
            size_t r = base + wid * 16 + row;
            float4 y = *(const float4*)(band + row * 72 + q4 * 4);
            float4 x = ((const float4*)(g_x + r * 64))[q4];
            float4 b = ((const float4*)bo)[q4];
            x.x += y.x + b.x; x.y += y.y + b.y;
            x.z += y.z + b.z; x.w += y.w + b.w;
            ((float4*)(g_x + r * 64))[q4] = x;
        }
    }
}

// ---------------- cluster features + Q2/K2/V2 projection ---------------------
__global__ void k_cf(const int* __restrict__ cvar,
                     const float* __restrict__ WQ2, const float* __restrict__ WK2,
                     const float* __restrict__ WV2) {
    __shared__ float cf[64];
    __shared__ int ids[64];
    int c = blockIdx.x, d = threadIdx.x;
    ids[d] = cvar[c * VC + d];
    __syncthreads();
    float s = 0.f;
    #pragma unroll 8
    for (int v = 0; v < VC; v++) s += g_x[(size_t)ids[v] * DD + d];
    cf[d] = s * (1.f / 64.f);
    __syncthreads();
    float q = 0.f, k = 0.f, v = 0.f;
    #pragma unroll 8
    for (int j = 0; j < 64; j++) {
        float x = cf[j];
        q = fmaf(x, WQ2[d * 64 + j], q);
        k = fmaf(x, WK2[d * 64 + j], k);
        v = fmaf(x, WV2[d * 64 + j], v);
    }
    g_Q2[c * 64 + d] = q; g_K2[c * 64 + d] = k; g_V2[c * 64 + d] = v;
}

// ---------------- inter-cluster edge scatter (GAT2, vectorized atomics) ------
__global__ void k_edge(const int* __restrict__ ei, const int* __restrict__ shv,
                       const float* __restrict__ hw) {
    int tid = threadIdx.x;
    int warp = tid >> 5, lane = tid & 31;
    int e = blockIdx.x * 8 + warp;
    if (e >= NE) return;
    int c1 = ei[e], c2 = ei[NE + e];
    float p = g_Q2[c1 * 64 + lane] * g_K2[c2 * 64 + lane]
            + g_Q2[c1 * 64 + lane + 32] * g_K2[c2 * 64 + lane + 32];
    #pragma unroll
    for (int o = 16; o > 0; o >>= 1) p += __shfl_xor_sync(0xffffffffu, p, o);
    float s = p * INVSCALE;
    float lr = (s >= 0.f) ? s : NEG * s;
    float hwm = 0.25f * (hw[0] + hw[1] + hw[2] + hw[3]);
    float a = hwm / (1.f + __expf(-lr));
    float4 v4 = make_float4(0.f, 0.f, 0.f, 0.f);
    if (lane < 16) {
        v4 = ((const float4*)(g_V2 + (size_t)c2 * 64))[lane];
        v4.x *= a; v4.y *= a; v4.z *= a; v4.w *= a;
    }
    #pragma unroll
    for (int k = 0; k < NSH; k++) {
        int sv = shv[e * NSH + k];
        if (lane < 16) red_add_v4(g_x + (size_t)sv * 64 + lane * 4, v4);
    }
}

// ---------------- pooling + MLP readout --------------------------------------
__global__ void k_pool() {
    int tid = threadIdx.x;
    int col = tid & 63;
    int rg = tid >> 6;
    float sv = 0.f, sc = 0.f;
    for (int r = blockIdx.x * 4 + rg; r < NM; r += gridDim.x * 4) {
        float x = g_x[(size_t)r * DD + col];
        if (r < N_VAR) sv += x; else sc += x;
    }
    atomicAdd(&g_pool[col], sv);
    atomicAdd(&g_pool[64 + col], sc);
}

__global__ void k_mlp(const float* __restrict__ W1, const float* __restrict__ b1,
                      const float* __restrict__ W2, const float* __restrict__ b2,
                      float* __restrict__ out) {
    __shared__ float p[128];
    __shared__ float h[64];
    int tid = threadIdx.x;
    if (tid < 128)
        p[tid] = tanhf(g_pool[tid] * (tid < 64 ? 1.f / N_VAR : 1.f / N_CLA));
    __syncthreads();
    if (tid < 64) {
        float a = b1[tid];
        #pragma unroll 8
        for (int j = 0; j < 128; j++) a = fmaf(p[j], W1[tid * 128 + j], a);
        h[tid] = (a > 0.f) ? a : 0.f;
    }
    __syncthreads();
    if (tid == 0) {
        float s = b2[0];
        for (int i = 0; i < 64; i++) s = fmaf(h[i], W2[i], s);
        out[0] = s;
    }
}

// ---------------- launch ------------------------------------------------------
extern "C" void kernel_launch(void* const* d_in, const int* in_sizes, int n_in,
                              void* d_out, int out_size) {
    (void)in_sizes; (void)n_in; (void)out_size;
    const float* xv   = (const float*)d_in[0];
    const float* xc   = (const float*)d_in[1];
    const float* sat  = (const float*)d_in[2];
    const int*   cvar = (const int*)d_in[3];
    const int*   ccla = (const int*)d_in[4];
    const int*   ei   = (const int*)d_in[5];
    const int*   shv  = (const int*)d_in[6];
    const float* WQ1  = (const float*)d_in[7];
    const float* WK1  = (const float*)d_in[8];
    const float* WV1  = (const float*)d_in[9];
    const float* hw1  = (const float*)d_in[10];
    const float* Wo   = (const float*)d_in[11];
    const float* bo   = (const float*)d_in[12];
    const float* WQ2  = (const float*)d_in[13];
    const float* WK2  = (const float*)d_in[14];
    const float* WV2  = (const float*)d_in[15];
    const float* hw2  = (const float*)d_in[16];
    const float* W1   = (const float*)d_in[17];
    const float* b1   = (const float*)d_in[18];
    const float* W2   = (const float*)d_in[19];
    const float* b2   = (const float*)d_in[20];

    cudaFuncSetAttribute(k_proj,    cudaFuncAttributeMaxDynamicSharedMemorySize, PROJ_SMEM);
    cudaFuncSetAttribute(k_attn_wm, cudaFuncAttributeMaxDynamicSharedMemorySize, ATTN_SMEM);
    cudaFuncSetAttribute(k_fin,     cudaFuncAttributeMaxDynamicSharedMemorySize, FIN_SMEM);

    k_init<<<512, 256>>>(xv, xc);
    const int projBlocks = (NM + 127) / 128;
    for (int it = 0; it < NITER; it++) {
        k_proj<<<projBlocks, 256, PROJ_SMEM>>>(WQ1, WK1, WV1);  // also zeroes g_acc/g_cnt
        k_attn_wm<<<NC, 384, ATTN_SMEM>>>(cvar, ccla, sat, hw1);
        k_fin<<<projBlocks, 256, FIN_SMEM>>>(Wo, bo);
        k_cf<<<NC, 64>>>(cvar, WQ2, WK2, WV2);
        k_edge<<<(NE + 7) / 8, 256>>>(ei, shv, hw2);
    }
    k_poolzero<<<1, 128>>>();
    k_pool<<<512, 256>>>();
    k_mlp<<<1, 128>>>(W1, b1, W2, b2, (float*)d_out);
}

// round 9
// speedup vs baseline: 1.6934x; 1.0532x over previous
#include <cuda_runtime.h>
#include <cuda_fp16.h>
#include <math.h>
#include <cstdint>
#include <mma.h>

using namespace nvcuda;

#define N_VAR 50000
#define N_CLA 100000
#define NM    150000
#define DD    64
#define NC    1000
#define VC    64
#define KCL   128
#define NN    192
#define NE    8000
#define NSH   8
#define NITER 3
#define NEG   0.2f
#define INVSCALE 0.125f

// tf32 fragments (k_proj / k_fin)
typedef wmma::fragment<wmma::matrix_a, 16, 16, 8, wmma::precision::tf32, wmma::row_major> AFrag;
typedef wmma::fragment<wmma::matrix_b, 16, 16, 8, wmma::precision::tf32, wmma::col_major> BFragC;
typedef wmma::fragment<wmma::accumulator, 16, 16, 8, float> CFrag;
// fp16 fragments (k_attn)
typedef wmma::fragment<wmma::matrix_a, 16, 16, 16, __half, wmma::row_major> HA;
typedef wmma::fragment<wmma::matrix_b, 16, 16, 16, __half, wmma::col_major> HBC;
typedef wmma::fragment<wmma::matrix_b, 16, 16, 16, __half, wmma::row_major> HBR;
typedef wmma::fragment<wmma::accumulator, 16, 16, 16, float> HC;

template <typename F>
__device__ __forceinline__ void to_tf32(F& f) {
    #pragma unroll
    for (int t = 0; t < f.num_elements; t++) f.x[t] = wmma::__float_to_tf32(f.x[t]);
}

__device__ __forceinline__ void red_add_v4(float* p, float4 v) {
    asm volatile("red.global.add.v4.f32 [%0], {%1,%2,%3,%4};"
                 :: "l"(p), "f"(v.x), "f"(v.y), "f"(v.z), "f"(v.w) : "memory");
}
__device__ __forceinline__ void red_add_v4h2(__half* p, uint32_t a, uint32_t b,
                                             uint32_t c, uint32_t d) {
    asm volatile("red.global.add.noftz.v4.f16x2 [%0], {%1,%2,%3,%4};"
                 :: "l"(p), "r"(a), "r"(b), "r"(c), "r"(d) : "memory");
}

// ---------------- scratch ----------------------------------------------------
__device__ float  g_x   [NM * DD];
__device__ __half g_Qh  [NM * DD];
__device__ __half g_Kh  [NM * DD];
__device__ __half g_Vh  [NM * DD];
__device__ __half g_acch[NM * DD];
__device__ float  g_cnt [NM];        // reciprocal counts after k_rcnt
__device__ float  g_Q2  [NC * DD];
__device__ float  g_K2  [NC * DD];
__device__ float  g_V2  [NC * DD];
__device__ float  g_pool[2 * DD];

__global__ void k_init(const float* __restrict__ xv, const float* __restrict__ xc) {
    int stride = gridDim.x * blockDim.x;
    int t = blockIdx.x * blockDim.x + threadIdx.x;
    for (int i = t; i < NM * DD; i += stride)
        g_x[i] = (i < N_VAR * DD) ? xv[i] : xc[i - N_VAR * DD];
    for (int i = t; i < NM; i += stride) g_cnt[i] = 0.f;
    if (t < 2 * DD) g_pool[t] = 0.f;
}

// count node occurrences across cluster lists (iteration-invariant)
__global__ void k_cnt(const int* __restrict__ cvar, const int* __restrict__ ccla) {
    int i = blockIdx.x * blockDim.x + threadIdx.x;
    if (i < NC * VC) atomicAdd(&g_cnt[cvar[i]], 1.f);
    else if (i < NC * (VC + KCL)) atomicAdd(&g_cnt[N_VAR + ccla[i - NC * VC]], 1.f);
}
__global__ void k_rcnt() {
    int i = blockIdx.x * blockDim.x + threadIdx.x;
    if (i < NM) g_cnt[i] = 1.f / fmaxf(g_cnt[i], 1.f);
}

// ---------------- Q/K/V projection via WMMA tf32, half outputs ---------------
#define PROJ_SMEM ((3 * 64 * 72 + 128 * 72) * 4)
__global__ void __launch_bounds__(256) k_proj(const float* __restrict__ WQ,
                                              const float* __restrict__ WK,
                                              const float* __restrict__ WV) {
    extern __shared__ float sm[];
    float* Wp = sm;               // 3 * 64*72 : (k,d) at m*4608 + d*72 + k
    float* xs = sm + 3 * 64 * 72; // 128*72 row-major (input, then per-warp out)
    int tid = threadIdx.x, wid = tid >> 5, lane = tid & 31;

    for (int i = tid; i < 3 * 64 * 64; i += 256) {
        int m = i >> 12, d = (i >> 6) & 63, k = i & 63;
        const float* W = (m == 0) ? WQ : ((m == 1) ? WK : WV);
        Wp[m * 4608 + d * 72 + k] = W[d * 64 + k];
    }
    size_t base = (size_t)blockIdx.x * 128;
    for (int i = tid; i < 128 * 16; i += 256) {
        int row = i >> 4, q4 = i & 15;
        size_t r = base + row;
        if (r < NM)
            ((float4*)(xs + row * 72))[q4] = ((const float4*)(g_x + r * 64))[q4];
    }
    __syncthreads();

    if (base + (size_t)wid * 16 < NM) {
        AFrag a[8];
        #pragma unroll
        for (int k = 0; k < 8; k++) {
            wmma::load_matrix_sync(a[k], xs + wid * 16 * 72 + k * 8, 72);
            to_tf32(a[k]);
        }
        __half* outs[3] = {g_Qh, g_Kh, g_Vh};
        float* band = xs + wid * 16 * 72;
        #pragma unroll
        for (int m = 0; m < 3; m++) {
            #pragma unroll
            for (int tc = 0; tc < 4; tc++) {
                CFrag acc;
                wmma::fill_fragment(acc, 0.f);
                #pragma unroll
                for (int k = 0; k < 8; k++) {
                    BFragC b;
                    wmma::load_matrix_sync(b, Wp + m * 4608 + tc * 16 * 72 + k * 8, 72);
                    to_tf32(b);
                    wmma::mma_sync(acc, a[k], b, acc);
                }
                wmma::store_matrix_sync(band + tc * 16, acc, 72, wmma::mem_row_major);
            }
            __syncwarp();
            float scl = (m == 0) ? INVSCALE : 1.f;
            __half* dst = outs[m] + (base + wid * 16) * 64;
            for (int i = lane; i < 128; i += 32) {      // 16 rows x 8 col-chunks
                int row = i >> 3, c8 = i & 7;
                float4 f0 = *(const float4*)(band + row * 72 + c8 * 8);
                float4 f1 = *(const float4*)(band + row * 72 + c8 * 8 + 4);
                __half2 h0 = __floats2half2_rn(f0.x * scl, f0.y * scl);
                __half2 h1 = __floats2half2_rn(f0.z * scl, f0.w * scl);
                __half2 h2 = __floats2half2_rn(f1.x * scl, f1.y * scl);
                __half2 h3 = __floats2half2_rn(f1.z * scl, f1.w * scl);
                uint4 u;
                u.x = *(uint32_t*)&h0; u.y = *(uint32_t*)&h1;
                u.z = *(uint32_t*)&h2; u.w = *(uint32_t*)&h3;
                *(uint4*)(dst + row * 64 + c8 * 8) = u;
            }
            __syncwarp();
        }
    }
    // zero g_acch (128 rows x 64 halves = 1024 uint4)
    uint4 z4 = make_uint4(0u, 0u, 0u, 0u);
    for (int i = tid; i < 128 * 8; i += 256) {
        int row = i >> 3, q8 = i & 7;
        size_t r = base + row;
        if (r < NM) *(uint4*)(g_acch + r * 64 + q8 * 8) = z4;
    }
}

// ---------------- intra-cluster attention via WMMA fp16 ----------------------
// 6 bands x 32 queries; smem ~97.6KB -> 2 CTAs/SM. K/V/Q ld=72 halves.
#define OFFB_K  0
#define OFFB_V  27648
#define OFFB_Q  55296
#define OFFB_S  59904
#define OFFB_P  85504
#define OFFB_RS 98304
#define OFFB_B  98432
#define OFFB_N  99200
#define ATTN_SMEM 99968

__global__ void __launch_bounds__(384, 2) k_attn_wm(const int* __restrict__ cvar,
                                                    const int* __restrict__ ccla,
                                                    const float* __restrict__ sat,
                                                    const float* __restrict__ hw) {
    extern __shared__ char smem[];
    __half* Kh = (__half*)(smem + OFFB_K);     // [192][72]
    __half* Vh = (__half*)(smem + OFFB_V);     // [192][72]
    __half* Qh = (__half*)(smem + OFFB_Q);     // [32][72]
    float*  Sf = (float*)(smem + OFFB_S);      // [32][200] scores; reused [32][72] O
    __half* Ph = (__half*)(smem + OFFB_P);     // [32][200] exp weights
    float*  rowsum = (float*)(smem + OFFB_RS); // [32]
    float*  bsh = (float*)(smem + OFFB_B);     // [192]
    int*    nsh = (int*)(smem + OFFB_N);       // [192]

    int c = blockIdx.x, tid = threadIdx.x, wid = tid >> 5;
    if (tid < NN) {
        int g; float b;
        if (tid < VC) { g = cvar[c * VC + tid]; b = 0.f; }
        else { int cl = ccla[c * KCL + (tid - VC)]; g = N_VAR + cl; b = sat[cl]; }
        nsh[tid] = g; bsh[tid] = b;
    }
    float hwm = 0.25f * (hw[0] + hw[1] + hw[2] + hw[3]);
    __syncthreads();

    // gather K/V (half in global; cols 64..71 unread pad)
    for (int idx = tid; idx < 192 * 8; idx += 384) {
        int row = idx >> 3, q8 = idx & 7;
        size_t o = (size_t)nsh[row] * 64;
        *(uint4*)(Kh + row * 72 + q8 * 8) = ((const uint4*)(g_Kh + o))[q8];
        *(uint4*)(Vh + row * 72 + q8 * 8) = ((const uint4*)(g_Vh + o))[q8];
    }

    for (int band = 0; band < 6; band++) {
        // gather 32-query band
        for (int idx = tid; idx < 32 * 8; idx += 384) {
            int row = idx >> 3, q8 = idx & 7;
            *(uint4*)(Qh + row * 72 + q8 * 8) =
                ((const uint4*)(g_Qh + (size_t)nsh[band * 32 + row] * 64))[q8];
        }
        __syncthreads();

        // GEMM1: S[32,192] = Qh @ Kh^T  (2 row-tiles x 12 col-tiles; 2 per warp)
        {
            int tr = wid & 1, tc = wid >> 1;
            HA a[4];
            #pragma unroll
            for (int k = 0; k < 4; k++)
                wmma::load_matrix_sync(a[k], Qh + tr * 16 * 72 + k * 16, 72);
            #pragma unroll
            for (int half2x = 0; half2x < 2; half2x++) {
                int tcc = tc + half2x * 6;
                HC acc;
                wmma::fill_fragment(acc, 0.f);
                #pragma unroll
                for (int k = 0; k < 4; k++) {
                    HBC b;
                    wmma::load_matrix_sync(b, Kh + tcc * 16 * 72 + k * 16, 72);
                    wmma::mma_sync(acc, a[k], b, acc);
                }
                wmma::store_matrix_sync(Sf + tr * 16 * 200 + tcc * 16, acc, 200,
                                        wmma::mem_row_major);
            }
        }
        __syncthreads();

        // softmax: 32 rows x 8-thread groups (tid<256); exp weights -> Ph
        if (tid < 256) {
            int srow = tid >> 3, c0 = tid & 7;
            float* srw = Sf + srow * 200;
            __half* prw = Ph + srow * 200;
            float mx = -1e30f;
            float v[24];
            #pragma unroll 8
            for (int i = 0; i < 24; i++) {
                int col = c0 + 8 * i;
                float s = srw[col] + bsh[col];
                s = (s >= 0.f) ? s : NEG * s;
                v[i] = s;
                mx = fmaxf(mx, s);
            }
            mx = fmaxf(mx, __shfl_xor_sync(0xffffffffu, mx, 1));
            mx = fmaxf(mx, __shfl_xor_sync(0xffffffffu, mx, 2));
            mx = fmaxf(mx, __shfl_xor_sync(0xffffffffu, mx, 4));
            float sum = 0.f;
            #pragma unroll 8
            for (int i = 0; i < 24; i++) {
                float e = __expf(v[i] - mx);
                sum += e;
                prw[c0 + 8 * i] = __float2half_rn(e);
            }
            sum += __shfl_xor_sync(0xffffffffu, sum, 1);
            sum += __shfl_xor_sync(0xffffffffu, sum, 2);
            sum += __shfl_xor_sync(0xffffffffu, sum, 4);
            if (c0 == 0) rowsum[srow] = sum;
        }
        __syncthreads();

        // GEMM2: O[32,64] = P @ V (8 warps); stage O into Sf [32][72]
        if (wid < 8) {
            int tr2 = wid >> 2, tc = wid & 3;
            HC o0;
            wmma::fill_fragment(o0, 0.f);
            #pragma unroll 4
            for (int k = 0; k < 12; k++) {
                HA a;
                wmma::load_matrix_sync(a, Ph + tr2 * 16 * 200 + k * 16, 200);
                HBR b0;
                wmma::load_matrix_sync(b0, Vh + k * 16 * 72 + tc * 16, 72);
                wmma::mma_sync(o0, a, b0, o0);
            }
            wmma::store_matrix_sync(Sf + tr2 * 16 * 72 + tc * 16, o0, 72,
                                    wmma::mem_row_major);
        }
        __syncthreads();

        // fp16 vectorized scatter-add (tid<128): 32 rows x 4 quads of 16
        if (tid < 128) {
            int srow = tid >> 2, sc0 = tid & 3;
            int g = nsh[band * 32 + srow];
            float scl = hwm / rowsum[srow];
            const float* src = Sf + srow * 72 + sc0 * 16;
            __half* dst = g_acch + (size_t)g * 64 + sc0 * 16;
            uint32_t h[8];
            #pragma unroll
            for (int j = 0; j < 8; j++) {
                __half2 p = __floats2half2_rn(src[2*j] * scl, src[2*j+1] * scl);
                h[j] = *(uint32_t*)&p;
            }
            red_add_v4h2(dst,     h[0], h[1], h[2], h[3]);
            red_add_v4h2(dst + 8, h[4], h[5], h[6], h[7]);
        }
        __syncthreads();
    }
}

// ---------------- finalize via WMMA tf32 (epilogue through A-band) -----------
#define FIN_SMEM ((64 * 72 + 128 * 72) * 4)
__global__ void __launch_bounds__(256) k_fin(const float* __restrict__ Wo,
                                             const float* __restrict__ bo) {
    extern __shared__ float sm[];
    float* Wt = sm;                 // [64][72] col-major: (k,d) at d*72+k
    float* xs = Wt + 64 * 72;       // [128][72] input, then per-warp output
    int tid = threadIdx.x, wid = tid >> 5, lane = tid & 31;

    for (int i = tid; i < 64 * 64; i += 256) {
        int d = i >> 6, k = i & 63;
        Wt[d * 72 + k] = Wo[i];
    }
    size_t base = (size_t)blockIdx.x * 128;
    for (int i = tid; i < 128 * 8; i += 256) {
        int row = i >> 3, q8 = i & 7;
        size_t r = base + row;
        if (r < NM) {
            float rc = g_cnt[r];      // reciprocal count
            uint4 u = *(const uint4*)(g_acch + r * 64 + q8 * 8);
            __half2 h0 = *(__half2*)&u.x, h1 = *(__half2*)&u.y;
            __half2 h2 = *(__half2*)&u.z, h3 = *(__half2*)&u.w;
            float2 f0 = __half22float2(h0), f1 = __half22float2(h1);
            float2 f2 = __half22float2(h2), f3 = __half22float2(h3);
            float* d = xs + row * 72 + q8 * 8;
            d[0] = f0.x * rc; d[1] = f0.y * rc; d[2] = f1.x * rc; d[3] = f1.y * rc;
            d[4] = f2.x * rc; d[5] = f2.y * rc; d[6] = f3.x * rc; d[7] = f3.y * rc;
        }
    }
    __syncthreads();

    if (base + (size_t)wid * 16 < NM) {
        float* band = xs + wid * 16 * 72;
        AFrag a[8];
        #pragma unroll
        for (int k = 0; k < 8; k++) {
            wmma::load_matrix_sync(a[k], band + k * 8, 72);
            to_tf32(a[k]);
        }
        #pragma unroll
        for (int tc = 0; tc < 4; tc++) {
            CFrag acc;
            wmma::fill_fragment(acc, 0.f);
            #pragma unroll
            for (int k = 0; k < 8; k++) {
                BFragC b;
                wmma::load_matrix_sync(b, Wt + tc * 16 * 72 + k * 8, 72);
                to_tf32(b);
                wmma::mma_sync(acc, a[k], b, acc);
            }
            wmma::store_matrix_sync(band + tc * 16, acc, 72, wmma::mem_row_major);
        }
        __syncwarp();
        for (int i = lane; i < 16 * 16; i += 32) {
            int row = i >> 4, q4 = i & 15;
            size_t r = base + wid * 16 + row;
            float4 y = *(const float4*)(band + row * 72 + q4 * 4);
            float4 x = ((const float4*)(g_x + r * 64))[q4];
            float4 b = ((const float4*)bo)[q4];
            x.x += y.x + b.x; x.y += y.y + b.y;
            x.z += y.z + b.z; x.w += y.w + b.w;
            ((float4*)(g_x + r * 64))[q4] = x;
        }
    }
}

// ---------------- cluster features + Q2/K2/V2 projection ---------------------
__global__ void k_cf(const int* __restrict__ cvar,
                     const float* __restrict__ WQ2, const float* __restrict__ WK2,
                     const float* __restrict__ WV2) {
    __shared__ float cf[64];
    __shared__ int ids[64];
    int c = blockIdx.x, d = threadIdx.x;
    ids[d] = cvar[c * VC + d];
    __syncthreads();
    float s = 0.f;
    #pragma unroll 8
    for (int v = 0; v < VC; v++) s += g_x[(size_t)ids[v] * DD + d];
    cf[d] = s * (1.f / 64.f);
    __syncthreads();
    float q = 0.f, k = 0.f, v = 0.f;
    #pragma unroll 8
    for (int j = 0; j < 64; j++) {
        float x = cf[j];
        q = fmaf(x, WQ2[d * 64 + j], q);
        k = fmaf(x, WK2[d * 64 + j], k);
        v = fmaf(x, WV2[d * 64 + j], v);
    }
    g_Q2[c * 64 + d] = q; g_K2[c * 64 + d] = k; g_V2[c * 64 + d] = v;
}

// ---------------- inter-cluster edge scatter (GAT2, vectorized atomics) ------
__global__ void k_edge(const int* __restrict__ ei, const int* __restrict__ shv,
                       const float* __restrict__ hw) {
    int tid = threadIdx.x;
    int warp = tid >> 5, lane = tid & 31;
    int e = blockIdx.x * 8 + warp;
    if (e >= NE) return;
    int c1 = ei[e], c2 = ei[NE + e];
    float p = g_Q2[c1 * 64 + lane] * g_K2[c2 * 64 + lane]
            + g_Q2[c1 * 64 + lane + 32] * g_K2[c2 * 64 + lane + 32];
    #pragma unroll
    for (int o = 16; o > 0; o >>= 1) p += __shfl_xor_sync(0xffffffffu, p, o);
    float s = p * INVSCALE;
    float lr = (s >= 0.f) ? s : NEG * s;
    float hwm = 0.25f * (hw[0] + hw[1] + hw[2] + hw[3]);
    float a = hwm / (1.f + __expf(-lr));
    float4 v4 = make_float4(0.f, 0.f, 0.f, 0.f);
    if (lane < 16) {
        v4 = ((const float4*)(g_V2 + (size_t)c2 * 64))[lane];
        v4.x *= a; v4.y *= a; v4.z *= a; v4.w *= a;
    }
    #pragma unroll
    for (int k = 0; k < NSH; k++) {
        int sv = shv[e * NSH + k];
        if (lane < 16) red_add_v4(g_x + (size_t)sv * 64 + lane * 4, v4);
    }
}

// ---------------- pooling + MLP readout --------------------------------------
__global__ void k_pool() {
    int tid = threadIdx.x;
    int col = tid & 63;
    int rg = tid >> 6;
    float sv = 0.f, sc = 0.f;
    for (int r = blockIdx.x * 4 + rg; r < NM; r += gridDim.x * 4) {
        float x = g_x[(size_t)r * DD + col];
        if (r < N_VAR) sv += x; else sc += x;
    }
    atomicAdd(&g_pool[col], sv);
    atomicAdd(&g_pool[64 + col], sc);
}

__global__ void k_mlp(const float* __restrict__ W1, const float* __restrict__ b1,
                      const float* __restrict__ W2, const float* __restrict__ b2,
                      float* __restrict__ out) {
    __shared__ float p[128];
    __shared__ float h[64];
    int tid = threadIdx.x;
    if (tid < 128)
        p[tid] = tanhf(g_pool[tid] * (tid < 64 ? 1.f / N_VAR : 1.f / N_CLA));
    __syncthreads();
    if (tid < 64) {
        float a = b1[tid];
        #pragma unroll 8
        for (int j = 0; j < 128; j++) a = fmaf(p[j], W1[tid * 128 + j], a);
        h[tid] = (a > 0.f) ? a : 0.f;
    }
    __syncthreads();
    if (tid == 0) {
        float s = b2[0];
        for (int i = 0; i < 64; i++) s = fmaf(h[i], W2[i], s);
        out[0] = s;
    }
}

// ---------------- launch ------------------------------------------------------
extern "C" void kernel_launch(void* const* d_in, const int* in_sizes, int n_in,
                              void* d_out, int out_size) {
    (void)in_sizes; (void)n_in; (void)out_size;
    const float* xv   = (const float*)d_in[0];
    const float* xc   = (const float*)d_in[1];
    const float* sat  = (const float*)d_in[2];
    const int*   cvar = (const int*)d_in[3];
    const int*   ccla = (const int*)d_in[4];
    const int*   ei   = (const int*)d_in[5];
    const int*   shv  = (const int*)d_in[6];
    const float* WQ1  = (const float*)d_in[7];
    const float* WK1  = (const float*)d_in[8];
    const float* WV1  = (const float*)d_in[9];
    const float* hw1  = (const float*)d_in[10];
    const float* Wo   = (const float*)d_in[11];
    const float* bo   = (const float*)d_in[12];
    const float* WQ2  = (const float*)d_in[13];
    const float* WK2  = (const float*)d_in[14];
    const float* WV2  = (const float*)d_in[15];
    const float* hw2  = (const float*)d_in[16];
    const float* W1   = (const float*)d_in[17];
    const float* b1   = (const float*)d_in[18];
    const float* W2   = (const float*)d_in[19];
    const float* b2   = (const float*)d_in[20];

    cudaFuncSetAttribute(k_proj,    cudaFuncAttributeMaxDynamicSharedMemorySize, PROJ_SMEM);
    cudaFuncSetAttribute(k_attn_wm, cudaFuncAttributeMaxDynamicSharedMemorySize, ATTN_SMEM);
    cudaFuncSetAttribute(k_fin,     cudaFuncAttributeMaxDynamicSharedMemorySize, FIN_SMEM);

    k_init<<<512, 256>>>(xv, xc);
    k_cnt<<<(NC * (VC + KCL) + 255) / 256, 256>>>(cvar, ccla);
    k_rcnt<<<(NM + 255) / 256, 256>>>();
    const int projBlocks = (NM + 127) / 128;
    for (int it = 0; it < NITER; it++) {
        k_proj<<<projBlocks, 256, PROJ_SMEM>>>(WQ1, WK1, WV1);  // also zeroes g_acch
        k_attn_wm<<<NC, 384, ATTN_SMEM>>>(cvar, ccla, sat, hw1);
        k_fin<<<projBlocks, 256, FIN_SMEM>>>(Wo, bo);
        k_cf<<<NC, 64>>>(cvar, WQ2, WK2, WV2);
        k_edge<<<(NE + 7) / 8, 256>>>(ei, shv, hw2);
    }
    k_pool<<<512, 256>>>();
    k_mlp<<<1, 128>>>(W1, b1, W2, b2, (float*)d_out);
}

// round 10
// speedup vs baseline: 2.1726x; 1.2830x over previous
#include <cuda_runtime.h>
#include <cuda_fp16.h>
#include <math.h>
#include <cstdint>
#include <mma.h>

using namespace nvcuda;

#define N_VAR 50000
#define N_CLA 100000
#define NM    150000
#define DD    64
#define NC    1000
#define VC    64
#define KCL   128
#define NN    192
#define NE    8000
#define NSH   8
#define NITER 3
#define NEG   0.2f
#define INVSCALE 0.125f

// fp16 fragments (all GEMMs)
typedef wmma::fragment<wmma::matrix_a, 16, 16, 16, __half, wmma::row_major> HA;
typedef wmma::fragment<wmma::matrix_b, 16, 16, 16, __half, wmma::col_major> HBC;
typedef wmma::fragment<wmma::matrix_b, 16, 16, 16, __half, wmma::row_major> HBR;
typedef wmma::fragment<wmma::accumulator, 16, 16, 16, float> HC;

__device__ __forceinline__ void red_add_v4(float* p, float4 v) {
    asm volatile("red.global.add.v4.f32 [%0], {%1,%2,%3,%4};"
                 :: "l"(p), "f"(v.x), "f"(v.y), "f"(v.z), "f"(v.w) : "memory");
}
__device__ __forceinline__ void red_add_v4h2(__half* p, uint32_t a, uint32_t b,
                                             uint32_t c, uint32_t d) {
    asm volatile("red.global.add.noftz.v4.f16x2 [%0], {%1,%2,%3,%4};"
                 :: "l"(p), "r"(a), "r"(b), "r"(c), "r"(d) : "memory");
}

// ---------------- scratch ----------------------------------------------------
__device__ float  g_x   [NM * DD];
__device__ __half g_Qh  [NM * DD];
__device__ __half g_Kh  [NM * DD];
__device__ __half g_Vh  [NM * DD];
__device__ __half g_acch[NM * DD];
__device__ float  g_cnt [NM];        // reciprocal counts after k_rcnt
__device__ float  g_Q2  [NC * DD];
__device__ float  g_K2  [NC * DD];
__device__ float  g_V2  [NC * DD];
__device__ float  g_pool[2 * DD];
__device__ __half g_Wh  [3 * DD * DD];   // WQ1/WK1/WV1 as half
__device__ __half g_Woh [DD * DD];       // Wo as half

__global__ void k_init(const float* __restrict__ xv, const float* __restrict__ xc) {
    int stride = gridDim.x * blockDim.x;
    int t = blockIdx.x * blockDim.x + threadIdx.x;
    for (int i = t; i < NM * DD; i += stride)
        g_x[i] = (i < N_VAR * DD) ? xv[i] : xc[i - N_VAR * DD];
    for (int i = t; i < NM; i += stride) g_cnt[i] = 0.f;
    if (t < 2 * DD) g_pool[t] = 0.f;
}

// pre-convert weights to half (once)
__global__ void k_prepw(const float* __restrict__ WQ, const float* __restrict__ WK,
                        const float* __restrict__ WV, const float* __restrict__ Wo) {
    int i = blockIdx.x * blockDim.x + threadIdx.x;
    if (i < 4096)       g_Wh[i]        = __float2half_rn(WQ[i]);
    else if (i < 8192)  g_Wh[i]        = __float2half_rn(WK[i - 4096]);
    else if (i < 12288) g_Wh[i]        = __float2half_rn(WV[i - 8192]);
    else if (i < 16384) g_Woh[i-12288] = __float2half_rn(Wo[i - 12288]);
}

// count node occurrences across cluster lists (iteration-invariant)
__global__ void k_cnt(const int* __restrict__ cvar, const int* __restrict__ ccla) {
    int i = blockIdx.x * blockDim.x + threadIdx.x;
    if (i < NC * VC) atomicAdd(&g_cnt[cvar[i]], 1.f);
    else if (i < NC * (VC + KCL)) atomicAdd(&g_cnt[N_VAR + ccla[i - NC * VC]], 1.f);
}
__global__ void k_rcnt() {
    int i = blockIdx.x * blockDim.x + threadIdx.x;
    if (i < NM) g_cnt[i] = 1.f / fmaxf(g_cnt[i], 1.f);
}

// ---------------- Q/K/V projection via WMMA fp16, half outputs ---------------
// 128 rows/CTA, 8 warps. W half [3][64][72], x half [128][72], fp32 staging.
#define PROJ_SMEM (27648 + 18432 + 36864)
__global__ void __launch_bounds__(256) k_proj() {
    extern __shared__ char smem[];
    __half* Wh  = (__half*)smem;                       // [3][64][72]
    __half* xs  = (__half*)(smem + 27648);             // [128][72]
    float*  stg = (float*)(smem + 27648 + 18432);      // 8 x [16][72]
    int tid = threadIdx.x, wid = tid >> 5, lane = tid & 31;

    // weights: half copies, 4 halves (8B) per iter
    for (int i = tid; i < 3 * 64 * 16; i += 256) {
        int m = i >> 10, rem = i & 1023, d = rem >> 4, q4 = rem & 15;
        *(uint2*)(Wh + m * 4608 + d * 72 + q4 * 4) =
            *(const uint2*)(g_Wh + m * 4096 + d * 64 + q4 * 4);
    }
    size_t base = (size_t)blockIdx.x * 128;
    for (int i = tid; i < 128 * 16; i += 256) {
        int row = i >> 4, q4 = i & 15;
        size_t r = base + row;
        if (r < NM) {
            float4 v = ((const float4*)(g_x + r * 64))[q4];
            __half2 h0 = __floats2half2_rn(v.x, v.y);
            __half2 h1 = __floats2half2_rn(v.z, v.w);
            uint2 u; u.x = *(uint32_t*)&h0; u.y = *(uint32_t*)&h1;
            *(uint2*)(xs + row * 72 + q4 * 4) = u;
        }
    }
    __syncthreads();

    if (base + (size_t)wid * 16 < NM) {
        HA a[4];
        #pragma unroll
        for (int k = 0; k < 4; k++)
            wmma::load_matrix_sync(a[k], xs + wid * 16 * 72 + k * 16, 72);
        __half* outs[3] = {g_Qh, g_Kh, g_Vh};
        float* band = stg + wid * 16 * 72;
        #pragma unroll
        for (int m = 0; m < 3; m++) {
            #pragma unroll
            for (int tc = 0; tc < 4; tc++) {
                HC acc;
                wmma::fill_fragment(acc, 0.f);
                #pragma unroll
                for (int k = 0; k < 4; k++) {
                    HBC b;
                    wmma::load_matrix_sync(b, Wh + m * 4608 + tc * 16 * 72 + k * 16, 72);
                    wmma::mma_sync(acc, a[k], b, acc);
                }
                wmma::store_matrix_sync(band + tc * 16, acc, 72, wmma::mem_row_major);
            }
            __syncwarp();
            float scl = (m == 0) ? INVSCALE : 1.f;
            __half* dst = outs[m] + (base + wid * 16) * 64;
            for (int i = lane; i < 128; i += 32) {      // 16 rows x 8 col-chunks
                int row = i >> 3, c8 = i & 7;
                float4 f0 = *(const float4*)(band + row * 72 + c8 * 8);
                float4 f1 = *(const float4*)(band + row * 72 + c8 * 8 + 4);
                __half2 h0 = __floats2half2_rn(f0.x * scl, f0.y * scl);
                __half2 h1 = __floats2half2_rn(f0.z * scl, f0.w * scl);
                __half2 h2 = __floats2half2_rn(f1.x * scl, f1.y * scl);
                __half2 h3 = __floats2half2_rn(f1.z * scl, f1.w * scl);
                uint4 u;
                u.x = *(uint32_t*)&h0; u.y = *(uint32_t*)&h1;
                u.z = *(uint32_t*)&h2; u.w = *(uint32_t*)&h3;
                *(uint4*)(dst + row * 64 + c8 * 8) = u;
            }
            __syncwarp();
        }
    }
    // zero g_acch
    uint4 z4 = make_uint4(0u, 0u, 0u, 0u);
    for (int i = tid; i < 128 * 8; i += 256) {
        int row = i >> 3, q8 = i & 7;
        size_t r = base + row;
        if (r < NM) *(uint4*)(g_acch + r * 64 + q8 * 8) = z4;
    }
}

// ---------------- intra-cluster attention via WMMA fp16 ----------------------
// 6 bands x 32 queries; smem ~97.6KB -> 2 CTAs/SM. K/V/Q ld=72 halves.
#define OFFB_K  0
#define OFFB_V  27648
#define OFFB_Q  55296
#define OFFB_S  59904
#define OFFB_P  85504
#define OFFB_RS 98304
#define OFFB_B  98432
#define OFFB_N  99200
#define ATTN_SMEM 99968

__global__ void __launch_bounds__(384, 2) k_attn_wm(const int* __restrict__ cvar,
                                                    const int* __restrict__ ccla,
                                                    const float* __restrict__ sat,
                                                    const float* __restrict__ hw) {
    extern __shared__ char smem[];
    __half* Kh = (__half*)(smem + OFFB_K);     // [192][72]
    __half* Vh = (__half*)(smem + OFFB_V);     // [192][72]
    __half* Qh = (__half*)(smem + OFFB_Q);     // [32][72]
    float*  Sf = (float*)(smem + OFFB_S);      // [32][200] scores; reused [32][72] O
    __half* Ph = (__half*)(smem + OFFB_P);     // [32][200] exp weights
    float*  rowsum = (float*)(smem + OFFB_RS); // [32]
    float*  bsh = (float*)(smem + OFFB_B);     // [192]
    int*    nsh = (int*)(smem + OFFB_N);       // [192]

    int c = blockIdx.x, tid = threadIdx.x, wid = tid >> 5;
    if (tid < NN) {
        int g; float b;
        if (tid < VC) { g = cvar[c * VC + tid]; b = 0.f; }
        else { int cl = ccla[c * KCL + (tid - VC)]; g = N_VAR + cl; b = sat[cl]; }
        nsh[tid] = g; bsh[tid] = b;
    }
    float hwm = 0.25f * (hw[0] + hw[1] + hw[2] + hw[3]);
    __syncthreads();

    for (int idx = tid; idx < 192 * 8; idx += 384) {
        int row = idx >> 3, q8 = idx & 7;
        size_t o = (size_t)nsh[row] * 64;
        *(uint4*)(Kh + row * 72 + q8 * 8) = ((const uint4*)(g_Kh + o))[q8];
        *(uint4*)(Vh + row * 72 + q8 * 8) = ((const uint4*)(g_Vh + o))[q8];
    }

    for (int band = 0; band < 6; band++) {
        for (int idx = tid; idx < 32 * 8; idx += 384) {
            int row = idx >> 3, q8 = idx & 7;
            *(uint4*)(Qh + row * 72 + q8 * 8) =
                ((const uint4*)(g_Qh + (size_t)nsh[band * 32 + row] * 64))[q8];
        }
        __syncthreads();

        // GEMM1: S[32,192] = Qh @ Kh^T
        {
            int tr = wid & 1, tc = wid >> 1;
            HA a[4];
            #pragma unroll
            for (int k = 0; k < 4; k++)
                wmma::load_matrix_sync(a[k], Qh + tr * 16 * 72 + k * 16, 72);
            #pragma unroll
            for (int half2x = 0; half2x < 2; half2x++) {
                int tcc = tc + half2x * 6;
                HC acc;
                wmma::fill_fragment(acc, 0.f);
                #pragma unroll
                for (int k = 0; k < 4; k++) {
                    HBC b;
                    wmma::load_matrix_sync(b, Kh + tcc * 16 * 72 + k * 16, 72);
                    wmma::mma_sync(acc, a[k], b, acc);
                }
                wmma::store_matrix_sync(Sf + tr * 16 * 200 + tcc * 16, acc, 200,
                                        wmma::mem_row_major);
            }
        }
        __syncthreads();

        // softmax: 32 rows x 8-thread groups (tid<256); exp weights -> Ph
        if (tid < 256) {
            int srow = tid >> 3, c0 = tid & 7;
            float* srw = Sf + srow * 200;
            __half* prw = Ph + srow * 200;
            float mx = -1e30f;
            float v[24];
            #pragma unroll 8
            for (int i = 0; i < 24; i++) {
                int col = c0 + 8 * i;
                float s = srw[col] + bsh[col];
                s = (s >= 0.f) ? s : NEG * s;
                v[i] = s;
                mx = fmaxf(mx, s);
            }
            mx = fmaxf(mx, __shfl_xor_sync(0xffffffffu, mx, 1));
            mx = fmaxf(mx, __shfl_xor_sync(0xffffffffu, mx, 2));
            mx = fmaxf(mx, __shfl_xor_sync(0xffffffffu, mx, 4));
            float sum = 0.f;
            #pragma unroll 8
            for (int i = 0; i < 24; i++) {
                float e = __expf(v[i] - mx);
                sum += e;
                prw[c0 + 8 * i] = __float2half_rn(e);
            }
            sum += __shfl_xor_sync(0xffffffffu, sum, 1);
            sum += __shfl_xor_sync(0xffffffffu, sum, 2);
            sum += __shfl_xor_sync(0xffffffffu, sum, 4);
            if (c0 == 0) rowsum[srow] = sum;
        }
        __syncthreads();

        // GEMM2: O[32,64] = P @ V (8 warps); stage O into Sf [32][72]
        if (wid < 8) {
            int tr2 = wid >> 2, tc = wid & 3;
            HC o0;
            wmma::fill_fragment(o0, 0.f);
            #pragma unroll 4
            for (int k = 0; k < 12; k++) {
                HA a;
                wmma::load_matrix_sync(a, Ph + tr2 * 16 * 200 + k * 16, 200);
                HBR b0;
                wmma::load_matrix_sync(b0, Vh + k * 16 * 72 + tc * 16, 72);
                wmma::mma_sync(o0, a, b0, o0);
            }
            wmma::store_matrix_sync(Sf + tr2 * 16 * 72 + tc * 16, o0, 72,
                                    wmma::mem_row_major);
        }
        __syncthreads();

        // fp16 vectorized scatter-add (tid<128)
        if (tid < 128) {
            int srow = tid >> 2, sc0 = tid & 3;
            int g = nsh[band * 32 + srow];
            float scl = hwm / rowsum[srow];
            const float* src = Sf + srow * 72 + sc0 * 16;
            __half* dst = g_acch + (size_t)g * 64 + sc0 * 16;
            uint32_t h[8];
            #pragma unroll
            for (int j = 0; j < 8; j++) {
                __half2 p = __floats2half2_rn(src[2*j] * scl, src[2*j+1] * scl);
                h[j] = *(uint32_t*)&p;
            }
            red_add_v4h2(dst,     h[0], h[1], h[2], h[3]);
            red_add_v4h2(dst + 8, h[4], h[5], h[6], h[7]);
        }
        __syncthreads();
    }
}

// ---------------- finalize via WMMA fp16: (acc @ Wo^T)*rc + bo + residual ----
#define FIN_SMEM (9216 + 18432 + 36864)
__global__ void __launch_bounds__(256) k_fin(const float* __restrict__ bo) {
    extern __shared__ char smem[];
    __half* Wh  = (__half*)smem;                   // [64][72] (d,k) at d*72+k
    __half* xs  = (__half*)(smem + 9216);          // [128][72] raw acc halves
    float*  stg = (float*)(smem + 9216 + 18432);   // 8 x [16][72]
    int tid = threadIdx.x, wid = tid >> 5, lane = tid & 31;

    for (int i = tid; i < 64 * 16; i += 256) {
        int d = i >> 4, q4 = i & 15;
        *(uint2*)(Wh + d * 72 + q4 * 4) = *(const uint2*)(g_Woh + d * 64 + q4 * 4);
    }
    size_t base = (size_t)blockIdx.x * 128;
    for (int i = tid; i < 128 * 8; i += 256) {
        int row = i >> 3, q8 = i & 7;
        size_t r = base + row;
        if (r < NM)
            *(uint4*)(xs + row * 72 + q8 * 8) = *(const uint4*)(g_acch + r * 64 + q8 * 8);
    }
    __syncthreads();

    if (base + (size_t)wid * 16 < NM) {
        HA a[4];
        #pragma unroll
        for (int k = 0; k < 4; k++)
            wmma::load_matrix_sync(a[k], xs + wid * 16 * 72 + k * 16, 72);
        float* band = stg + wid * 16 * 72;
        #pragma unroll
        for (int tc = 0; tc < 4; tc++) {
            HC acc;
            wmma::fill_fragment(acc, 0.f);
            #pragma unroll
            for (int k = 0; k < 4; k++) {
                HBC b;
                wmma::load_matrix_sync(b, Wh + tc * 16 * 72 + k * 16, 72);
                wmma::mma_sync(acc, a[k], b, acc);
            }
            wmma::store_matrix_sync(band + tc * 16, acc, 72, wmma::mem_row_major);
        }
        __syncwarp();
        for (int i = lane; i < 16 * 16; i += 32) {
            int row = i >> 4, q4 = i & 15;
            size_t r = base + wid * 16 + row;
            float rc = g_cnt[r];
            float4 y = *(const float4*)(band + row * 72 + q4 * 4);
            float4 x = ((const float4*)(g_x + r * 64))[q4];
            float4 b = ((const float4*)bo)[q4];
            x.x += y.x * rc + b.x; x.y += y.y * rc + b.y;
            x.z += y.z * rc + b.z; x.w += y.w * rc + b.w;
            ((float4*)(g_x + r * 64))[q4] = x;
        }
    }
}

// ---------------- cluster features + Q2/K2/V2 projection ---------------------
__global__ void k_cf(const int* __restrict__ cvar,
                     const float* __restrict__ WQ2, const float* __restrict__ WK2,
                     const float* __restrict__ WV2) {
    __shared__ float cf[64];
    __shared__ int ids[64];
    int c = blockIdx.x, d = threadIdx.x;
    ids[d] = cvar[c * VC + d];
    __syncthreads();
    float s = 0.f;
    #pragma unroll 8
    for (int v = 0; v < VC; v++) s += g_x[(size_t)ids[v] * DD + d];
    cf[d] = s * (1.f / 64.f);
    __syncthreads();
    float q = 0.f, k = 0.f, v = 0.f;
    #pragma unroll 8
    for (int j = 0; j < 64; j++) {
        float x = cf[j];
        q = fmaf(x, WQ2[d * 64 + j], q);
        k = fmaf(x, WK2[d * 64 + j], k);
        v = fmaf(x, WV2[d * 64 + j], v);
    }
    g_Q2[c * 64 + d] = q; g_K2[c * 64 + d] = k; g_V2[c * 64 + d] = v;
}

// ---------------- inter-cluster edge scatter (GAT2, vectorized atomics) ------
__global__ void k_edge(const int* __restrict__ ei, const int* __restrict__ shv,
                       const float* __restrict__ hw) {
    int tid = threadIdx.x;
    int warp = tid >> 5, lane = tid & 31;
    int e = blockIdx.x * 8 + warp;
    if (e >= NE) return;
    int c1 = ei[e], c2 = ei[NE + e];
    float p = g_Q2[c1 * 64 + lane] * g_K2[c2 * 64 + lane]
            + g_Q2[c1 * 64 + lane + 32] * g_K2[c2 * 64 + lane + 32];
    #pragma unroll
    for (int o = 16; o > 0; o >>= 1) p += __shfl_xor_sync(0xffffffffu, p, o);
    float s = p * INVSCALE;
    float lr = (s >= 0.f) ? s : NEG * s;
    float hwm = 0.25f * (hw[0] + hw[1] + hw[2] + hw[3]);
    float a = hwm / (1.f + __expf(-lr));
    float4 v4 = make_float4(0.f, 0.f, 0.f, 0.f);
    if (lane < 16) {
        v4 = ((const float4*)(g_V2 + (size_t)c2 * 64))[lane];
        v4.x *= a; v4.y *= a; v4.z *= a; v4.w *= a;
    }
    #pragma unroll
    for (int k = 0; k < NSH; k++) {
        int sv = shv[e * NSH + k];
        if (lane < 16) red_add_v4(g_x + (size_t)sv * 64 + lane * 4, v4);
    }
}

// ---------------- pooling + MLP readout --------------------------------------
__global__ void k_pool() {
    int tid = threadIdx.x;
    int col = tid & 63;
    int rg = tid >> 6;
    float sv = 0.f, sc = 0.f;
    for (int r = blockIdx.x * 4 + rg; r < NM; r += gridDim.x * 4) {
        float x = g_x[(size_t)r * DD + col];
        if (r < N_VAR) sv += x; else sc += x;
    }
    atomicAdd(&g_pool[col], sv);
    atomicAdd(&g_pool[64 + col], sc);
}

__global__ void k_mlp(const float* __restrict__ W1, const float* __restrict__ b1,
                      const float* __restrict__ W2, const float* __restrict__ b2,
                      float* __restrict__ out) {
    __shared__ float p[128];
    __shared__ float h[64];
    int tid = threadIdx.x;
    if (tid < 128)
        p[tid] = tanhf(g_pool[tid] * (tid < 64 ? 1.f / N_VAR : 1.f / N_CLA));
    __syncthreads();
    if (tid < 64) {
        float a = b1[tid];
        #pragma unroll 8
        for (int j = 0; j < 128; j++) a = fmaf(p[j], W1[tid * 128 + j], a);
        h[tid] = (a > 0.f) ? a : 0.f;
    }
    __syncthreads();
    if (tid == 0) {
        float s = b2[0];
        for (int i = 0; i < 64; i++) s = fmaf(h[i], W2[i], s);
        out[0] = s;
    }
}

// ---------------- launch ------------------------------------------------------
extern "C" void kernel_launch(void* const* d_in, const int* in_sizes, int n_in,
                              void* d_out, int out_size) {
    (void)in_sizes; (void)n_in; (void)out_size;
    const float* xv   = (const float*)d_in[0];
    const float* xc   = (const float*)d_in[1];
    const float* sat  = (const float*)d_in[2];
    const int*   cvar = (const int*)d_in[3];
    const int*   ccla = (const int*)d_in[4];
    const int*   ei   = (const int*)d_in[5];
    const int*   shv  = (const int*)d_in[6];
    const float* WQ1  = (const float*)d_in[7];
    const float* WK1  = (const float*)d_in[8];
    const float* WV1  = (const float*)d_in[9];
    const float* hw1  = (const float*)d_in[10];
    const float* Wo   = (const float*)d_in[11];
    const float* bo   = (const float*)d_in[12];
    const float* WQ2  = (const float*)d_in[13];
    const float* WK2  = (const float*)d_in[14];
    const float* WV2  = (const float*)d_in[15];
    const float* hw2  = (const float*)d_in[16];
    const float* W1   = (const float*)d_in[17];
    const float* b1   = (const float*)d_in[18];
    const float* W2   = (const float*)d_in[19];
    const float* b2   = (const float*)d_in[20];

    cudaFuncSetAttribute(k_proj,    cudaFuncAttributeMaxDynamicSharedMemorySize, PROJ_SMEM);
    cudaFuncSetAttribute(k_attn_wm, cudaFuncAttributeMaxDynamicSharedMemorySize, ATTN_SMEM);
    cudaFuncSetAttribute(k_fin,     cudaFuncAttributeMaxDynamicSharedMemorySize, FIN_SMEM);

    k_init<<<512, 256>>>(xv, xc);
    k_prepw<<<64, 256>>>(WQ1, WK1, WV1, Wo);
    k_cnt<<<(NC * (VC + KCL) + 255) / 256, 256>>>(cvar, ccla);
    k_rcnt<<<(NM + 255) / 256, 256>>>();
    const int projBlocks = (NM + 127) / 128;
    for (int it = 0; it < NITER; it++) {
        k_proj<<<projBlocks, 256, PROJ_SMEM>>>();               // also zeroes g_acch
        k_attn_wm<<<NC, 384, ATTN_SMEM>>>(cvar, ccla, sat, hw1);
        k_fin<<<projBlocks, 256, FIN_SMEM>>>(bo);
        k_cf<<<NC, 64>>>(cvar, WQ2, WK2, WV2);
        k_edge<<<(NE + 7) / 8, 256>>>(ei, shv, hw2);
    }
    k_pool<<<512, 256>>>();
    k_mlp<<<1, 128>>>(W1, b1, W2, b2, (float*)d_out);
}

// round 11
// speedup vs baseline: 2.2850x; 1.0517x over previous
#include <cuda_runtime.h>
#include <cuda_fp16.h>
#include <math.h>
#include <cstdint>
#include <mma.h>

using namespace nvcuda;

#define N_VAR 50000
#define N_CLA 100000
#define NM    150000
#define DD    64
#define NC    1000
#define VC    64
#define KCL   128
#define NN    192
#define NE    8000
#define NSH   8
#define NITER 3
#define NEG   0.2f
#define INVSCALE 0.125f

// fp16 fragments (all GEMMs)
typedef wmma::fragment<wmma::matrix_a, 16, 16, 16, __half, wmma::row_major> HA;
typedef wmma::fragment<wmma::matrix_b, 16, 16, 16, __half, wmma::col_major> HBC;
typedef wmma::fragment<wmma::matrix_b, 16, 16, 16, __half, wmma::row_major> HBR;
typedef wmma::fragment<wmma::accumulator, 16, 16, 16, float> HC;
typedef wmma::fragment<wmma::accumulator, 16, 16, 16, __half> HCH;

__device__ __forceinline__ void red_add_v4(float* p, float4 v) {
    asm volatile("red.global.add.v4.f32 [%0], {%1,%2,%3,%4};"
                 :: "l"(p), "f"(v.x), "f"(v.y), "f"(v.z), "f"(v.w) : "memory");
}
__device__ __forceinline__ void red_add_v4h2(__half* p, uint32_t a, uint32_t b,
                                             uint32_t c, uint32_t d) {
    asm volatile("red.global.add.noftz.v4.f16x2 [%0], {%1,%2,%3,%4};"
                 :: "l"(p), "r"(a), "r"(b), "r"(c), "r"(d) : "memory");
}

// ---------------- scratch ----------------------------------------------------
__device__ float  g_x   [NM * DD];
__device__ __half g_Qh  [NM * DD];
__device__ __half g_Kh  [NM * DD];
__device__ __half g_Vh  [NM * DD];
__device__ __half g_acch[NM * DD];
__device__ float  g_cnt [NM];        // reciprocal counts after k_rcnt
__device__ float  g_Q2  [NC * DD];
__device__ float  g_K2  [NC * DD];
__device__ float  g_V2  [NC * DD];
__device__ float  g_pool[2 * DD];
__device__ __half g_Wh  [3 * DD * DD];   // WQ1/WK1/WV1 as half
__device__ __half g_Woh [DD * DD];       // Wo as half

__global__ void k_init(const float* __restrict__ xv, const float* __restrict__ xc) {
    int stride = gridDim.x * blockDim.x;
    int t = blockIdx.x * blockDim.x + threadIdx.x;
    for (int i = t; i < NM * DD; i += stride)
        g_x[i] = (i < N_VAR * DD) ? xv[i] : xc[i - N_VAR * DD];
    for (int i = t; i < NM; i += stride) g_cnt[i] = 0.f;
    if (t < 2 * DD) g_pool[t] = 0.f;
}

// pre-convert weights to half (once)
__global__ void k_prepw(const float* __restrict__ WQ, const float* __restrict__ WK,
                        const float* __restrict__ WV, const float* __restrict__ Wo) {
    int i = blockIdx.x * blockDim.x + threadIdx.x;
    if (i < 4096)       g_Wh[i]        = __float2half_rn(WQ[i]);
    else if (i < 8192)  g_Wh[i]        = __float2half_rn(WK[i - 4096]);
    else if (i < 12288) g_Wh[i]        = __float2half_rn(WV[i - 8192]);
    else if (i < 16384) g_Woh[i-12288] = __float2half_rn(Wo[i - 12288]);
}

// count node occurrences across cluster lists (iteration-invariant)
__global__ void k_cnt(const int* __restrict__ cvar, const int* __restrict__ ccla) {
    int i = blockIdx.x * blockDim.x + threadIdx.x;
    if (i < NC * VC) atomicAdd(&g_cnt[cvar[i]], 1.f);
    else if (i < NC * (VC + KCL)) atomicAdd(&g_cnt[N_VAR + ccla[i - NC * VC]], 1.f);
}
__global__ void k_rcnt() {
    int i = blockIdx.x * blockDim.x + threadIdx.x;
    if (i < NM) g_cnt[i] = 1.f / fmaxf(g_cnt[i], 1.f);
}

// ---------------- Q/K/V projection via WMMA fp16, direct half stores ---------
// 128 rows/CTA, 8 warps. C-fragments converted to half in regs, stored
// straight to global (no staging). 46KB smem -> 3 CTAs/SM.
#define PROJ_SMEM (27648 + 18432)
__global__ void __launch_bounds__(256, 3) k_proj() {
    extern __shared__ char smem[];
    __half* Wh = (__half*)smem;                       // [3][64][72]
    __half* xs = (__half*)(smem + 27648);             // [128][72]
    int tid = threadIdx.x, wid = tid >> 5;

    for (int i = tid; i < 3 * 64 * 16; i += 256) {
        int m = i >> 10, rem = i & 1023, d = rem >> 4, q4 = rem & 15;
        *(uint2*)(Wh + m * 4608 + d * 72 + q4 * 4) =
            *(const uint2*)(g_Wh + m * 4096 + d * 64 + q4 * 4);
    }
    size_t base = (size_t)blockIdx.x * 128;
    for (int i = tid; i < 128 * 16; i += 256) {
        int row = i >> 4, q4 = i & 15;
        size_t r = base + row;
        if (r < NM) {
            float4 v = ((const float4*)(g_x + r * 64))[q4];
            __half2 h0 = __floats2half2_rn(v.x, v.y);
            __half2 h1 = __floats2half2_rn(v.z, v.w);
            uint2 u; u.x = *(uint32_t*)&h0; u.y = *(uint32_t*)&h1;
            *(uint2*)(xs + row * 72 + q4 * 4) = u;
        }
    }
    __syncthreads();

    if (base + (size_t)wid * 16 < NM) {
        HA a[4];
        #pragma unroll
        for (int k = 0; k < 4; k++)
            wmma::load_matrix_sync(a[k], xs + wid * 16 * 72 + k * 16, 72);
        __half* outs[3] = {g_Qh, g_Kh, g_Vh};
        #pragma unroll
        for (int m = 0; m < 3; m++) {
            #pragma unroll
            for (int tc = 0; tc < 4; tc++) {
                HC acc;
                wmma::fill_fragment(acc, 0.f);
                #pragma unroll
                for (int k = 0; k < 4; k++) {
                    HBC b;
                    wmma::load_matrix_sync(b, Wh + m * 4608 + tc * 16 * 72 + k * 16, 72);
                    wmma::mma_sync(acc, a[k], b, acc);
                }
                HCH h;
                if (m == 0) {
                    #pragma unroll
                    for (int t = 0; t < acc.num_elements; t++)
                        h.x[t] = __float2half_rn(acc.x[t] * INVSCALE);
                } else {
                    #pragma unroll
                    for (int t = 0; t < acc.num_elements; t++)
                        h.x[t] = __float2half_rn(acc.x[t]);
                }
                wmma::store_matrix_sync(outs[m] + (base + wid * 16) * 64 + tc * 16,
                                        h, 64, wmma::mem_row_major);
            }
        }
    }
    // zero g_acch
    uint4 z4 = make_uint4(0u, 0u, 0u, 0u);
    for (int i = tid; i < 128 * 8; i += 256) {
        int row = i >> 3, q8 = i & 7;
        size_t r = base + row;
        if (r < NM) *(uint4*)(g_acch + r * 64 + q8 * 8) = z4;
    }
}

// ---------------- intra-cluster attention via WMMA fp16 ----------------------
// 6 bands x 32 queries; half scores in-place; 74.4KB -> 3 CTAs/SM.
#define OFFB_K  0
#define OFFB_V  27648
#define OFFB_Q  55296
#define OFFB_S  59904
#define OFFB_RS 72704
#define OFFB_B  72832
#define OFFB_N  73600
#define ATTN_SMEM 74368

__global__ void __launch_bounds__(384, 3) k_attn_wm(const int* __restrict__ cvar,
                                                    const int* __restrict__ ccla,
                                                    const float* __restrict__ sat,
                                                    const float* __restrict__ hw) {
    extern __shared__ char smem[];
    __half* Kh = (__half*)(smem + OFFB_K);     // [192][72]
    __half* Vh = (__half*)(smem + OFFB_V);     // [192][72]
    __half* Qh = (__half*)(smem + OFFB_Q);     // [32][72]
    __half* Sh = (__half*)(smem + OFFB_S);     // [32][200] scores -> exp (in place)
    float*  Of = (float*)(smem + OFFB_S);      // [32][72] O staging (after GEMM2)
    float*  rowsum = (float*)(smem + OFFB_RS); // [32]
    float*  bsh = (float*)(smem + OFFB_B);     // [192]
    int*    nsh = (int*)(smem + OFFB_N);       // [192]

    int c = blockIdx.x, tid = threadIdx.x, wid = tid >> 5;
    if (tid < NN) {
        int g; float b;
        if (tid < VC) { g = cvar[c * VC + tid]; b = 0.f; }
        else { int cl = ccla[c * KCL + (tid - VC)]; g = N_VAR + cl; b = sat[cl]; }
        nsh[tid] = g; bsh[tid] = b;
    }
    float hwm = 0.25f * (hw[0] + hw[1] + hw[2] + hw[3]);
    __syncthreads();

    for (int idx = tid; idx < 192 * 8; idx += 384) {
        int row = idx >> 3, q8 = idx & 7;
        size_t o = (size_t)nsh[row] * 64;
        *(uint4*)(Kh + row * 72 + q8 * 8) = ((const uint4*)(g_Kh + o))[q8];
        *(uint4*)(Vh + row * 72 + q8 * 8) = ((const uint4*)(g_Vh + o))[q8];
    }

    for (int band = 0; band < 6; band++) {
        for (int idx = tid; idx < 32 * 8; idx += 384) {
            int row = idx >> 3, q8 = idx & 7;
            *(uint4*)(Qh + row * 72 + q8 * 8) =
                ((const uint4*)(g_Qh + (size_t)nsh[band * 32 + row] * 64))[q8];
        }
        __syncthreads();

        // GEMM1: S[32,192] = Qh @ Kh^T, stored as half
        {
            int tr = wid & 1, tc = wid >> 1;
            HA a[4];
            #pragma unroll
            for (int k = 0; k < 4; k++)
                wmma::load_matrix_sync(a[k], Qh + tr * 16 * 72 + k * 16, 72);
            #pragma unroll
            for (int half2x = 0; half2x < 2; half2x++) {
                int tcc = tc + half2x * 6;
                HC acc;
                wmma::fill_fragment(acc, 0.f);
                #pragma unroll
                for (int k = 0; k < 4; k++) {
                    HBC b;
                    wmma::load_matrix_sync(b, Kh + tcc * 16 * 72 + k * 16, 72);
                    wmma::mma_sync(acc, a[k], b, acc);
                }
                HCH h;
                #pragma unroll
                for (int t = 0; t < acc.num_elements; t++)
                    h.x[t] = __float2half_rn(acc.x[t]);
                wmma::store_matrix_sync(Sh + tr * 16 * 200 + tcc * 16, h, 200,
                                        wmma::mem_row_major);
            }
        }
        __syncthreads();

        // softmax: 32 rows x 8-thread groups (tid<256); two passes, exp in place
        if (tid < 256) {
            int srow = tid >> 3, c0 = tid & 7;
            __half* srw = Sh + srow * 200;
            float mx = -1e30f;
            #pragma unroll 8
            for (int i = 0; i < 24; i++) {
                int col = c0 + 8 * i;
                float s = __half2float(srw[col]) + bsh[col];
                s = (s >= 0.f) ? s : NEG * s;
                mx = fmaxf(mx, s);
            }
            mx = fmaxf(mx, __shfl_xor_sync(0xffffffffu, mx, 1));
            mx = fmaxf(mx, __shfl_xor_sync(0xffffffffu, mx, 2));
            mx = fmaxf(mx, __shfl_xor_sync(0xffffffffu, mx, 4));
            float sum = 0.f;
            #pragma unroll 8
            for (int i = 0; i < 24; i++) {
                int col = c0 + 8 * i;
                float s = __half2float(srw[col]) + bsh[col];
                s = (s >= 0.f) ? s : NEG * s;
                float e = __expf(s - mx);
                sum += e;
                srw[col] = __float2half_rn(e);
            }
            sum += __shfl_xor_sync(0xffffffffu, sum, 1);
            sum += __shfl_xor_sync(0xffffffffu, sum, 2);
            sum += __shfl_xor_sync(0xffffffffu, sum, 4);
            if (c0 == 0) rowsum[srow] = sum;
        }
        __syncthreads();

        // GEMM2: O[32,64] = P @ V; C-frag held in regs across sync, then staged
        HC o0;
        wmma::fill_fragment(o0, 0.f);
        int tr2 = wid >> 2, tc2 = wid & 3;
        if (wid < 8) {
            #pragma unroll 4
            for (int k = 0; k < 12; k++) {
                HA a;
                wmma::load_matrix_sync(a, Sh + tr2 * 16 * 200 + k * 16, 200);
                HBR b0;
                wmma::load_matrix_sync(b0, Vh + k * 16 * 72 + tc2 * 16, 72);
                wmma::mma_sync(o0, a, b0, o0);
            }
        }
        __syncthreads();   // all reads of Sh done
        if (wid < 8)
            wmma::store_matrix_sync(Of + tr2 * 16 * 72 + tc2 * 16, o0, 72,
                                    wmma::mem_row_major);
        __syncthreads();

        // fp16 vectorized scatter-add (tid<128)
        if (tid < 128) {
            int srow = tid >> 2, sc0 = tid & 3;
            int g = nsh[band * 32 + srow];
            float scl = hwm / rowsum[srow];
            const float* src = Of + srow * 72 + sc0 * 16;
            __half* dst = g_acch + (size_t)g * 64 + sc0 * 16;
            uint32_t h[8];
            #pragma unroll
            for (int j = 0; j < 8; j++) {
                __half2 p = __floats2half2_rn(src[2*j] * scl, src[2*j+1] * scl);
                h[j] = *(uint32_t*)&p;
            }
            red_add_v4h2(dst,     h[0], h[1], h[2], h[3]);
            red_add_v4h2(dst + 8, h[4], h[5], h[6], h[7]);
        }
        __syncthreads();
    }
}

// ---------------- finalize via WMMA fp16: (acc @ Wo^T)*rc + bo + residual ----
#define FIN_SMEM (9216 + 18432 + 36864)
__global__ void __launch_bounds__(256) k_fin(const float* __restrict__ bo) {
    extern __shared__ char smem[];
    __half* Wh  = (__half*)smem;                   // [64][72] (d,k) at d*72+k
    __half* xs  = (__half*)(smem + 9216);          // [128][72] raw acc halves
    float*  stg = (float*)(smem + 9216 + 18432);   // 8 x [16][72]
    int tid = threadIdx.x, wid = tid >> 5, lane = tid & 31;

    for (int i = tid; i < 64 * 16; i += 256) {
        int d = i >> 4, q4 = i & 15;
        *(uint2*)(Wh + d * 72 + q4 * 4) = *(const uint2*)(g_Woh + d * 64 + q4 * 4);
    }
    size_t base = (size_t)blockIdx.x * 128;
    for (int i = tid; i < 128 * 8; i += 256) {
        int row = i >> 3, q8 = i & 7;
        size_t r = base + row;
        if (r < NM)
            *(uint4*)(xs + row * 72 + q8 * 8) = *(const uint4*)(g_acch + r * 64 + q8 * 8);
    }
    __syncthreads();

    if (base + (size_t)wid * 16 < NM) {
        HA a[4];
        #pragma unroll
        for (int k = 0; k < 4; k++)
            wmma::load_matrix_sync(a[k], xs + wid * 16 * 72 + k * 16, 72);
        float* band = stg + wid * 16 * 72;
        #pragma unroll
        for (int tc = 0; tc < 4; tc++) {
            HC acc;
            wmma::fill_fragment(acc, 0.f);
            #pragma unroll
            for (int k = 0; k < 4; k++) {
                HBC b;
                wmma::load_matrix_sync(b, Wh + tc * 16 * 72 + k * 16, 72);
                wmma::mma_sync(acc, a[k], b, acc);
            }
            wmma::store_matrix_sync(band + tc * 16, acc, 72, wmma::mem_row_major);
        }
        __syncwarp();
        for (int i = lane; i < 16 * 16; i += 32) {
            int row = i >> 4, q4 = i & 15;
            size_t r = base + wid * 16 + row;
            float rc = g_cnt[r];
            float4 y = *(const float4*)(band + row * 72 + q4 * 4);
            float4 x = ((const float4*)(g_x + r * 64))[q4];
            float4 b = ((const float4*)bo)[q4];
            x.x += y.x * rc + b.x; x.y += y.y * rc + b.y;
            x.z += y.z * rc + b.z; x.w += y.w * rc + b.w;
            ((float4*)(g_x + r * 64))[q4] = x;
        }
    }
}

// ---------------- cluster features + Q2/K2/V2 projection ---------------------
__global__ void k_cf(const int* __restrict__ cvar,
                     const float* __restrict__ WQ2, const float* __restrict__ WK2,
                     const float* __restrict__ WV2) {
    __shared__ float cf[64];
    __shared__ int ids[64];
    int c = blockIdx.x, d = threadIdx.x;
    ids[d] = cvar[c * VC + d];
    __syncthreads();
    float s = 0.f;
    #pragma unroll 8
    for (int v = 0; v < VC; v++) s += g_x[(size_t)ids[v] * DD + d];
    cf[d] = s * (1.f / 64.f);
    __syncthreads();
    float q = 0.f, k = 0.f, v = 0.f;
    #pragma unroll 8
    for (int j = 0; j < 64; j++) {
        float x = cf[j];
        q = fmaf(x, WQ2[d * 64 + j], q);
        k = fmaf(x, WK2[d * 64 + j], k);
        v = fmaf(x, WV2[d * 64 + j], v);
    }
    g_Q2[c * 64 + d] = q; g_K2[c * 64 + d] = k; g_V2[c * 64 + d] = v;
}

// ---------------- inter-cluster edge scatter (GAT2, vectorized atomics) ------
__global__ void k_edge(const int* __restrict__ ei, const int* __restrict__ shv,
                       const float* __restrict__ hw) {
    int tid = threadIdx.x;
    int warp = tid >> 5, lane = tid & 31;
    int e = blockIdx.x * 8 + warp;
    if (e >= NE) return;
    int c1 = ei[e], c2 = ei[NE + e];
    float p = g_Q2[c1 * 64 + lane] * g_K2[c2 * 64 + lane]
            + g_Q2[c1 * 64 + lane + 32] * g_K2[c2 * 64 + lane + 32];
    #pragma unroll
    for (int o = 16; o > 0; o >>= 1) p += __shfl_xor_sync(0xffffffffu, p, o);
    float s = p * INVSCALE;
    float lr = (s >= 0.f) ? s : NEG * s;
    float hwm = 0.25f * (hw[0] + hw[1] + hw[2] + hw[3]);
    float a = hwm / (1.f + __expf(-lr));
    float4 v4 = make_float4(0.f, 0.f, 0.f, 0.f);
    if (lane < 16) {
        v4 = ((const float4*)(g_V2 + (size_t)c2 * 64))[lane];
        v4.x *= a; v4.y *= a; v4.z *= a; v4.w *= a;
    }
    #pragma unroll
    for (int k = 0; k < NSH; k++) {
        int sv = shv[e * NSH + k];
        if (lane < 16) red_add_v4(g_x + (size_t)sv * 64 + lane * 4, v4);
    }
}

// ---------------- pooling + MLP readout --------------------------------------
__global__ void k_pool() {
    int tid = threadIdx.x;
    int col = tid & 63;
    int rg = tid >> 6;
    float sv = 0.f, sc = 0.f;
    for (int r = blockIdx.x * 4 + rg; r < NM; r += gridDim.x * 4) {
        float x = g_x[(size_t)r * DD + col];
        if (r < N_VAR) sv += x; else sc += x;
    }
    atomicAdd(&g_pool[col], sv);
    atomicAdd(&g_pool[64 + col], sc);
}

__global__ void k_mlp(const float* __restrict__ W1, const float* __restrict__ b1,
                      const float* __restrict__ W2, const float* __restrict__ b2,
                      float* __restrict__ out) {
    __shared__ float p[128];
    __shared__ float h[64];
    int tid = threadIdx.x;
    if (tid < 128)
        p[tid] = tanhf(g_pool[tid] * (tid < 64 ? 1.f / N_VAR : 1.f / N_CLA));
    __syncthreads();
    if (tid < 64) {
        float a = b1[tid];
        #pragma unroll 8
        for (int j = 0; j < 128; j++) a = fmaf(p[j], W1[tid * 128 + j], a);
        h[tid] = (a > 0.f) ? a : 0.f;
    }
    __syncthreads();
    if (tid == 0) {
        float s = b2[0];
        for (int i = 0; i < 64; i++) s = fmaf(h[i], W2[i], s);
        out[0] = s;
    }
}

// ---------------- launch ------------------------------------------------------
extern "C" void kernel_launch(void* const* d_in, const int* in_sizes, int n_in,
                              void* d_out, int out_size) {
    (void)in_sizes; (void)n_in; (void)out_size;
    const float* xv   = (const float*)d_in[0];
    const float* xc   = (const float*)d_in[1];
    const float* sat  = (const float*)d_in[2];
    const int*   cvar = (const int*)d_in[3];
    const int*   ccla = (const int*)d_in[4];
    const int*   ei   = (const int*)d_in[5];
    const int*   shv  = (const int*)d_in[6];
    const float* WQ1  = (const float*)d_in[7];
    const float* WK1  = (const float*)d_in[8];
    const float* WV1  = (const float*)d_in[9];
    const float* hw1  = (const float*)d_in[10];
    const float* Wo   = (const float*)d_in[11];
    const float* bo   = (const float*)d_in[12];
    const float* WQ2  = (const float*)d_in[13];
    const float* WK2  = (const float*)d_in[14];
    const float* WV2  = (const float*)d_in[15];
    const float* hw2  = (const float*)d_in[16];
    const float* W1   = (const float*)d_in[17];
    const float* b1   = (const float*)d_in[18];
    const float* W2   = (const float*)d_in[19];
    const float* b2   = (const float*)d_in[20];

    cudaFuncSetAttribute(k_proj,    cudaFuncAttributeMaxDynamicSharedMemorySize, PROJ_SMEM);
    cudaFuncSetAttribute(k_attn_wm, cudaFuncAttributeMaxDynamicSharedMemorySize, ATTN_SMEM);
    cudaFuncSetAttribute(k_fin,     cudaFuncAttributeMaxDynamicSharedMemorySize, FIN_SMEM);

    k_init<<<512, 256>>>(xv, xc);
    k_prepw<<<64, 256>>>(WQ1, WK1, WV1, Wo);
    k_cnt<<<(NC * (VC + KCL) + 255) / 256, 256>>>(cvar, ccla);
    k_rcnt<<<(NM + 255) / 256, 256>>>();
    const int projBlocks = (NM + 127) / 128;
    for (int it = 0; it < NITER; it++) {
        k_proj<<<projBlocks, 256, PROJ_SMEM>>>();               // also zeroes g_acch
        k_attn_wm<<<NC, 384, ATTN_SMEM>>>(cvar, ccla, sat, hw1);
        k_fin<<<projBlocks, 256, FIN_SMEM>>>(bo);
        k_cf<<<NC, 64>>>(cvar, WQ2, WK2, WV2);
        k_edge<<<(NE + 7) / 8, 256>>>(ei, shv, hw2);
    }
    k_pool<<<512, 256>>>();
    k_mlp<<<1, 128>>>(W1, b1, W2, b2, (float*)d_out);
}

// round 12
// speedup vs baseline: 2.3621x; 1.0337x over previous
#include <cuda_runtime.h>
#include <cuda_fp16.h>
#include <math.h>
#include <cstdint>
#include <mma.h>

using namespace nvcuda;

#define N_VAR 50000
#define N_CLA 100000
#define NM    150000
#define DD    64
#define NC    1000
#define VC    64
#define KCL   128
#define NN    192
#define NE    8000
#define NSH   8
#define NITER 3
#define NEG   0.2f
#define INVSCALE 0.125f

// fp16 fragments (all GEMMs)
typedef wmma::fragment<wmma::matrix_a, 16, 16, 16, __half, wmma::row_major> HA;
typedef wmma::fragment<wmma::matrix_b, 16, 16, 16, __half, wmma::col_major> HBC;
typedef wmma::fragment<wmma::matrix_b, 16, 16, 16, __half, wmma::row_major> HBR;
typedef wmma::fragment<wmma::accumulator, 16, 16, 16, float> HC;
typedef wmma::fragment<wmma::accumulator, 16, 16, 16, __half> HCH;

__device__ __forceinline__ void red_add_v4(float* p, float4 v) {
    asm volatile("red.global.add.v4.f32 [%0], {%1,%2,%3,%4};"
                 :: "l"(p), "f"(v.x), "f"(v.y), "f"(v.z), "f"(v.w) : "memory");
}
__device__ __forceinline__ void red_add_v4h2(__half* p, uint32_t a, uint32_t b,
                                             uint32_t c, uint32_t d) {
    asm volatile("red.global.add.noftz.v4.f16x2 [%0], {%1,%2,%3,%4};"
                 :: "l"(p), "r"(a), "r"(b), "r"(c), "r"(d) : "memory");
}

// ---------------- scratch ----------------------------------------------------
__device__ float  g_x   [NM * DD];
__device__ __half g_Qh  [NM * DD];
__device__ __half g_Kh  [NM * DD];
__device__ __half g_Vh  [NM * DD];
__device__ __half g_acch[NM * DD];
__device__ float  g_cnt [NM];        // reciprocal counts after k_rcnt
__device__ float  g_Q2  [NC * DD];
__device__ float  g_K2  [NC * DD];
__device__ float  g_V2  [NC * DD];
__device__ float  g_pool[2 * DD];
__device__ __half g_Wh  [3 * DD * DD];   // WQ1/WK1/WV1 as half
__device__ __half g_Woh [DD * DD];       // Wo as half

__global__ void k_init(const float* __restrict__ xv, const float* __restrict__ xc) {
    int stride = gridDim.x * blockDim.x;
    int t = blockIdx.x * blockDim.x + threadIdx.x;
    for (int i = t; i < NM * DD; i += stride)
        g_x[i] = (i < N_VAR * DD) ? xv[i] : xc[i - N_VAR * DD];
    for (int i = t; i < NM; i += stride) g_cnt[i] = 0.f;
    if (t < 2 * DD) g_pool[t] = 0.f;
}

// weights->half AND node occurrence counts (both iteration-invariant)
__global__ void k_prep(const float* __restrict__ WQ, const float* __restrict__ WK,
                       const float* __restrict__ WV, const float* __restrict__ Wo,
                       const int* __restrict__ cvar, const int* __restrict__ ccla) {
    int i = blockIdx.x * blockDim.x + threadIdx.x;
    if (i < 4096)       g_Wh[i]        = __float2half_rn(WQ[i]);
    else if (i < 8192)  g_Wh[i]        = __float2half_rn(WK[i - 4096]);
    else if (i < 12288) g_Wh[i]        = __float2half_rn(WV[i - 8192]);
    else if (i < 16384) g_Woh[i-12288] = __float2half_rn(Wo[i - 12288]);
    if (i < NC * VC) atomicAdd(&g_cnt[cvar[i]], 1.f);
    else if (i < NC * (VC + KCL)) atomicAdd(&g_cnt[N_VAR + ccla[i - NC * VC]], 1.f);
}
__global__ void k_rcnt() {
    int i = blockIdx.x * blockDim.x + threadIdx.x;
    if (i < NM) g_cnt[i] = 1.f / fmaxf(g_cnt[i], 1.f);
}

// ---------------- Q/K/V projection via WMMA fp16, direct half stores ---------
// 256 rows/CTA, 8 warps x 2 bands. 64.5KB smem -> 3 CTAs/SM.
#define PROJ_SMEM (27648 + 36864)
__global__ void __launch_bounds__(256, 3) k_proj() {
    extern __shared__ char smem[];
    __half* Wh = (__half*)smem;                       // [3][64][72]
    __half* xs = (__half*)(smem + 27648);             // [256][72]
    int tid = threadIdx.x, wid = tid >> 5;

    for (int i = tid; i < 3 * 64 * 16; i += 256) {
        int m = i >> 10, rem = i & 1023, d = rem >> 4, q4 = rem & 15;
        *(uint2*)(Wh + m * 4608 + d * 72 + q4 * 4) =
            *(const uint2*)(g_Wh + m * 4096 + d * 64 + q4 * 4);
    }
    size_t base = (size_t)blockIdx.x * 256;
    for (int i = tid; i < 256 * 16; i += 256) {
        int row = i >> 4, q4 = i & 15;
        size_t r = base + row;
        if (r < NM) {
            float4 v = ((const float4*)(g_x + r * 64))[q4];
            __half2 h0 = __floats2half2_rn(v.x, v.y);
            __half2 h1 = __floats2half2_rn(v.z, v.w);
            uint2 u; u.x = *(uint32_t*)&h0; u.y = *(uint32_t*)&h1;
            *(uint2*)(xs + row * 72 + q4 * 4) = u;
        }
    }
    __syncthreads();

    __half* outs[3] = {g_Qh, g_Kh, g_Vh};
    #pragma unroll
    for (int band = 0; band < 2; band++) {
        int rowbase = band * 128 + wid * 16;
        if (base + rowbase >= NM) continue;
        HA a[4];
        #pragma unroll
        for (int k = 0; k < 4; k++)
            wmma::load_matrix_sync(a[k], xs + rowbase * 72 + k * 16, 72);
        #pragma unroll
        for (int m = 0; m < 3; m++) {
            #pragma unroll
            for (int tc = 0; tc < 4; tc++) {
                HC acc;
                wmma::fill_fragment(acc, 0.f);
                #pragma unroll
                for (int k = 0; k < 4; k++) {
                    HBC b;
                    wmma::load_matrix_sync(b, Wh + m * 4608 + tc * 16 * 72 + k * 16, 72);
                    wmma::mma_sync(acc, a[k], b, acc);
                }
                HCH h;
                if (m == 0) {
                    #pragma unroll
                    for (int t = 0; t < acc.num_elements; t++)
                        h.x[t] = __float2half_rn(acc.x[t] * INVSCALE);
                } else {
                    #pragma unroll
                    for (int t = 0; t < acc.num_elements; t++)
                        h.x[t] = __float2half_rn(acc.x[t]);
                }
                wmma::store_matrix_sync(outs[m] + (base + rowbase) * 64 + tc * 16,
                                        h, 64, wmma::mem_row_major);
            }
        }
    }
    // zero g_acch (256 rows)
    uint4 z4 = make_uint4(0u, 0u, 0u, 0u);
    for (int i = tid; i < 256 * 8; i += 256) {
        int row = i >> 3, q8 = i & 7;
        size_t r = base + row;
        if (r < NM) *(uint4*)(g_acch + r * 64 + q8 * 8) = z4;
    }
}

// ---------------- intra-cluster attention via WMMA fp16 ----------------------
// 6 bands x 32 queries; Q prefetch overlapped with softmax; fused tile scatter.
#define OFFB_K  0
#define OFFB_V  27648
#define OFFB_Q  55296
#define OFFB_S  59904
#define OFFB_RS 72704
#define OFFB_B  72832
#define OFFB_N  73600
#define ATTN_SMEM 74368

__global__ void __launch_bounds__(384, 3) k_attn_wm(const int* __restrict__ cvar,
                                                    const int* __restrict__ ccla,
                                                    const float* __restrict__ sat,
                                                    const float* __restrict__ hw) {
    extern __shared__ char smem[];
    __half* Kh = (__half*)(smem + OFFB_K);     // [192][72]
    __half* Vh = (__half*)(smem + OFFB_V);     // [192][72]
    __half* Qh = (__half*)(smem + OFFB_Q);     // [32][72]
    __half* Sh = (__half*)(smem + OFFB_S);     // [32][200] scores -> exp (in place)
    float*  Of = (float*)(smem + OFFB_S);      // [32][72] O staging (aliases Sh)
    float*  rowsum = (float*)(smem + OFFB_RS); // [32]
    float*  bsh = (float*)(smem + OFFB_B);     // [192]
    int*    nsh = (int*)(smem + OFFB_N);       // [192]

    int c = blockIdx.x, tid = threadIdx.x, wid = tid >> 5, lane = tid & 31;
    if (tid < NN) {
        int g; float b;
        if (tid < VC) { g = cvar[c * VC + tid]; b = 0.f; }
        else { int cl = ccla[c * KCL + (tid - VC)]; g = N_VAR + cl; b = sat[cl]; }
        nsh[tid] = g; bsh[tid] = b;
    }
    float hwm = 0.25f * (hw[0] + hw[1] + hw[2] + hw[3]);
    __syncthreads();

    for (int idx = tid; idx < 192 * 8; idx += 384) {
        int row = idx >> 3, q8 = idx & 7;
        size_t o = (size_t)nsh[row] * 64;
        *(uint4*)(Kh + row * 72 + q8 * 8) = ((const uint4*)(g_Kh + o))[q8];
        *(uint4*)(Vh + row * 72 + q8 * 8) = ((const uint4*)(g_Vh + o))[q8];
    }
    // gather band-0 Q
    for (int idx = tid; idx < 32 * 8; idx += 384) {
        int row = idx >> 3, q8 = idx & 7;
        *(uint4*)(Qh + row * 72 + q8 * 8) =
            ((const uint4*)(g_Qh + (size_t)nsh[row] * 64))[q8];
    }
    __syncthreads();

    for (int band = 0; band < 6; band++) {
        // GEMM1: S[32,192] = Qh @ Kh^T, stored as half
        {
            int tr = wid & 1, tc = wid >> 1;
            HA a[4];
            #pragma unroll
            for (int k = 0; k < 4; k++)
                wmma::load_matrix_sync(a[k], Qh + tr * 16 * 72 + k * 16, 72);
            #pragma unroll
            for (int half2x = 0; half2x < 2; half2x++) {
                int tcc = tc + half2x * 6;
                HC acc;
                wmma::fill_fragment(acc, 0.f);
                #pragma unroll
                for (int k = 0; k < 4; k++) {
                    HBC b;
                    wmma::load_matrix_sync(b, Kh + tcc * 16 * 72 + k * 16, 72);
                    wmma::mma_sync(acc, a[k], b, acc);
                }
                HCH h;
                #pragma unroll
                for (int t = 0; t < acc.num_elements; t++)
                    h.x[t] = __float2half_rn(acc.x[t]);
                wmma::store_matrix_sync(Sh + tr * 16 * 200 + tcc * 16, h, 200,
                                        wmma::mem_row_major);
            }
        }
        __syncthreads();

        // softmax (warps 0-7) || prefetch next band's Q (warps 8-11)
        if (tid < 256) {
            int srow = tid >> 3, c0 = tid & 7;
            __half* srw = Sh + srow * 200;
            float mx = -1e30f;
            #pragma unroll 8
            for (int i = 0; i < 24; i++) {
                int col = c0 + 8 * i;
                float s = __half2float(srw[col]) + bsh[col];
                s = (s >= 0.f) ? s : NEG * s;
                srw[col] = __float2half_rn(s);
                mx = fmaxf(mx, s);
            }
            mx = fmaxf(mx, __shfl_xor_sync(0xffffffffu, mx, 1));
            mx = fmaxf(mx, __shfl_xor_sync(0xffffffffu, mx, 2));
            mx = fmaxf(mx, __shfl_xor_sync(0xffffffffu, mx, 4));
            float sum = 0.f;
            #pragma unroll 8
            for (int i = 0; i < 24; i++) {
                int col = c0 + 8 * i;
                float e = __expf(__half2float(srw[col]) - mx);
                sum += e;
                srw[col] = __float2half_rn(e);
            }
            sum += __shfl_xor_sync(0xffffffffu, sum, 1);
            sum += __shfl_xor_sync(0xffffffffu, sum, 2);
            sum += __shfl_xor_sync(0xffffffffu, sum, 4);
            if (c0 == 0) rowsum[srow] = sum;
        } else if (band < 5) {
            for (int idx = tid - 256; idx < 32 * 8; idx += 128) {
                int row = idx >> 3, q8 = idx & 7;
                *(uint4*)(Qh + row * 72 + q8 * 8) =
                    ((const uint4*)(g_Qh + (size_t)nsh[(band + 1) * 32 + row] * 64))[q8];
            }
        }
        __syncthreads();

        // GEMM2: O[32,64] = P @ V; C-frag in regs across sync
        HC o0;
        wmma::fill_fragment(o0, 0.f);
        int tr2 = wid >> 2, tc2 = wid & 3;
        if (wid < 8) {
            #pragma unroll 4
            for (int k = 0; k < 12; k++) {
                HA a;
                wmma::load_matrix_sync(a, Sh + tr2 * 16 * 200 + k * 16, 200);
                HBR b0;
                wmma::load_matrix_sync(b0, Vh + k * 16 * 72 + tc2 * 16, 72);
                wmma::mma_sync(o0, a, b0, o0);
            }
        }
        __syncthreads();   // all reads of Sh done
        if (wid < 8) {
            wmma::store_matrix_sync(Of + tr2 * 16 * 72 + tc2 * 16, o0, 72,
                                    wmma::mem_row_major);
            __syncwarp();
            // fused scatter of this warp's own 16x16 tile: lane -> (row, 8-col chunk)
            int row = lane >> 1, c8 = (lane & 1) * 8;
            int grow = tr2 * 16 + row;
            int g = nsh[band * 32 + grow];
            float scl = hwm / rowsum[grow];
            const float* src = Of + grow * 72 + tc2 * 16 + c8;
            __half* dst = g_acch + (size_t)g * 64 + tc2 * 16 + c8;
            float4 f0 = *(const float4*)(src);
            float4 f1 = *(const float4*)(src + 4);
            __half2 h0 = __floats2half2_rn(f0.x * scl, f0.y * scl);
            __half2 h1 = __floats2half2_rn(f0.z * scl, f0.w * scl);
            __half2 h2 = __floats2half2_rn(f1.x * scl, f1.y * scl);
            __half2 h3 = __floats2half2_rn(f1.z * scl, f1.w * scl);
            red_add_v4h2(dst, *(uint32_t*)&h0, *(uint32_t*)&h1,
                              *(uint32_t*)&h2, *(uint32_t*)&h3);
        }
        __syncthreads();   // Of reads done before next band's GEMM1 writes Sh
    }
}

// ---------------- finalize via WMMA fp16: (acc @ Wo^T)*rc + bo + residual ----
#define FIN_SMEM (9216 + 18432 + 36864)
__global__ void __launch_bounds__(256) k_fin(const float* __restrict__ bo) {
    extern __shared__ char smem[];
    __half* Wh  = (__half*)smem;                   // [64][72] (d,k) at d*72+k
    __half* xs  = (__half*)(smem + 9216);          // [128][72] raw acc halves
    float*  stg = (float*)(smem + 9216 + 18432);   // 8 x [16][72]
    int tid = threadIdx.x, wid = tid >> 5, lane = tid & 31;

    for (int i = tid; i < 64 * 16; i += 256) {
        int d = i >> 4, q4 = i & 15;
        *(uint2*)(Wh + d * 72 + q4 * 4) = *(const uint2*)(g_Woh + d * 64 + q4 * 4);
    }
    size_t base = (size_t)blockIdx.x * 128;
    for (int i = tid; i < 128 * 8; i += 256) {
        int row = i >> 3, q8 = i & 7;
        size_t r = base + row;
        if (r < NM)
            *(uint4*)(xs + row * 72 + q8 * 8) = *(const uint4*)(g_acch + r * 64 + q8 * 8);
    }
    __syncthreads();

    if (base + (size_t)wid * 16 < NM) {
        HA a[4];
        #pragma unroll
        for (int k = 0; k < 4; k++)
            wmma::load_matrix_sync(a[k], xs + wid * 16 * 72 + k * 16, 72);
        float* band = stg + wid * 16 * 72;
        #pragma unroll
        for (int tc = 0; tc < 4; tc++) {
            HC acc;
            wmma::fill_fragment(acc, 0.f);
            #pragma unroll
            for (int k = 0; k < 4; k++) {
                HBC b;
                wmma::load_matrix_sync(b, Wh + tc * 16 * 72 + k * 16, 72);
                wmma::mma_sync(acc, a[k], b, acc);
            }
            wmma::store_matrix_sync(band + tc * 16, acc, 72, wmma::mem_row_major);
        }
        __syncwarp();
        for (int i = lane; i < 16 * 16; i += 32) {
            int row = i >> 4, q4 = i & 15;
            size_t r = base + wid * 16 + row;
            float rc = g_cnt[r];
            float4 y = *(const float4*)(band + row * 72 + q4 * 4);
            float4 x = ((const float4*)(g_x + r * 64))[q4];
            float4 b = ((const float4*)bo)[q4];
            x.x += y.x * rc + b.x; x.y += y.y * rc + b.y;
            x.z += y.z * rc + b.z; x.w += y.w * rc + b.w;
            ((float4*)(g_x + r * 64))[q4] = x;
        }
    }
}

// ---------------- cluster features + Q2/K2/V2 projection ---------------------
__global__ void k_cf(const int* __restrict__ cvar,
                     const float* __restrict__ WQ2, const float* __restrict__ WK2,
                     const float* __restrict__ WV2) {
    __shared__ float cf[64];
    __shared__ int ids[64];
    int c = blockIdx.x, d = threadIdx.x;
    ids[d] = cvar[c * VC + d];
    __syncthreads();
    float s = 0.f;
    #pragma unroll 8
    for (int v = 0; v < VC; v++) s += g_x[(size_t)ids[v] * DD + d];
    cf[d] = s * (1.f / 64.f);
    __syncthreads();
    float q = 0.f, k = 0.f, v = 0.f;
    #pragma unroll 8
    for (int j = 0; j < 64; j++) {
        float x = cf[j];
        q = fmaf(x, WQ2[d * 64 + j], q);
        k = fmaf(x, WK2[d * 64 + j], k);
        v = fmaf(x, WV2[d * 64 + j], v);
    }
    g_Q2[c * 64 + d] = q; g_K2[c * 64 + d] = k; g_V2[c * 64 + d] = v;
}

// ---------------- inter-cluster edge scatter (GAT2, vectorized atomics) ------
__global__ void k_edge(const int* __restrict__ ei, const int* __restrict__ shv,
                       const float* __restrict__ hw) {
    int tid = threadIdx.x;
    int warp = tid >> 5, lane = tid & 31;
    int e = blockIdx.x * 8 + warp;
    if (e >= NE) return;
    int c1 = ei[e], c2 = ei[NE + e];
    float p = g_Q2[c1 * 64 + lane] * g_K2[c2 * 64 + lane]
            + g_Q2[c1 * 64 + lane + 32] * g_K2[c2 * 64 + lane + 32];
    #pragma unroll
    for (int o = 16; o > 0; o >>= 1) p += __shfl_xor_sync(0xffffffffu, p, o);
    float s = p * INVSCALE;
    float lr = (s >= 0.f) ? s : NEG * s;
    float hwm = 0.25f * (hw[0] + hw[1] + hw[2] + hw[3]);
    float a = hwm / (1.f + __expf(-lr));
    float4 v4 = make_float4(0.f, 0.f, 0.f, 0.f);
    if (lane < 16) {
        v4 = ((const float4*)(g_V2 + (size_t)c2 * 64))[lane];
        v4.x *= a; v4.y *= a; v4.z *= a; v4.w *= a;
    }
    #pragma unroll
    for (int k = 0; k < NSH; k++) {
        int sv = shv[e * NSH + k];
        if (lane < 16) red_add_v4(g_x + (size_t)sv * 64 + lane * 4, v4);
    }
}

// ---------------- pooling + MLP readout --------------------------------------
__global__ void k_pool() {
    int tid = threadIdx.x;
    int col = tid & 63;
    int rg = tid >> 6;
    float sv = 0.f, sc = 0.f;
    for (int r = blockIdx.x * 4 + rg; r < NM; r += gridDim.x * 4) {
        float x = g_x[(size_t)r * DD + col];
        if (r < N_VAR) sv += x; else sc += x;
    }
    atomicAdd(&g_pool[col], sv);
    atomicAdd(&g_pool[64 + col], sc);
}

__global__ void k_mlp(const float* __restrict__ W1, const float* __restrict__ b1,
                      const float* __restrict__ W2, const float* __restrict__ b2,
                      float* __restrict__ out) {
    __shared__ float p[128];
    __shared__ float h[64];
    int tid = threadIdx.x;
    if (tid < 128)
        p[tid] = tanhf(g_pool[tid] * (tid < 64 ? 1.f / N_VAR : 1.f / N_CLA));
    __syncthreads();
    if (tid < 64) {
        float a = b1[tid];
        #pragma unroll 8
        for (int j = 0; j < 128; j++) a = fmaf(p[j], W1[tid * 128 + j], a);
        h[tid] = (a > 0.f) ? a : 0.f;
    }
    __syncthreads();
    if (tid == 0) {
        float s = b2[0];
        for (int i = 0; i < 64; i++) s = fmaf(h[i], W2[i], s);
        out[0] = s;
    }
}

// ---------------- launch ------------------------------------------------------
extern "C" void kernel_launch(void* const* d_in, const int* in_sizes, int n_in,
                              void* d_out, int out_size) {
    (void)in_sizes; (void)n_in; (void)out_size;
    const float* xv   = (const float*)d_in[0];
    const float* xc   = (const float*)d_in[1];
    const float* sat  = (const float*)d_in[2];
    const int*   cvar = (const int*)d_in[3];
    const int*   ccla = (const int*)d_in[4];
    const int*   ei   = (const int*)d_in[5];
    const int*   shv  = (const int*)d_in[6];
    const float* WQ1  = (const float*)d_in[7];
    const float* WK1  = (const float*)d_in[8];
    const float* WV1  = (const float*)d_in[9];
    const float* hw1  = (const float*)d_in[10];
    const float* Wo   = (const float*)d_in[11];
    const float* bo   = (const float*)d_in[12];
    const float* WQ2  = (const float*)d_in[13];
    const float* WK2  = (const float*)d_in[14];
    const float* WV2  = (const float*)d_in[15];
    const float* hw2  = (const float*)d_in[16];
    const float* W1   = (const float*)d_in[17];
    const float* b1   = (const float*)d_in[18];
    const float* W2   = (const float*)d_in[19];
    const float* b2   = (const float*)d_in[20];

    cudaFuncSetAttribute(k_proj,    cudaFuncAttributeMaxDynamicSharedMemorySize, PROJ_SMEM);
    cudaFuncSetAttribute(k_attn_wm, cudaFuncAttributeMaxDynamicSharedMemorySize, ATTN_SMEM);
    cudaFuncSetAttribute(k_fin,     cudaFuncAttributeMaxDynamicSharedMemorySize, FIN_SMEM);

    k_init<<<512, 256>>>(xv, xc);
    k_prep<<<(NC * (VC + KCL) + 255) / 256, 256>>>(WQ1, WK1, WV1, Wo, cvar, ccla);
    k_rcnt<<<(NM + 255) / 256, 256>>>();
    const int projBlocks = (NM + 255) / 256;
    const int finBlocks  = (NM + 127) / 128;
    for (int it = 0; it < NITER; it++) {
        k_proj<<<projBlocks, 256, PROJ_SMEM>>>();               // also zeroes g_acch
        k_attn_wm<<<NC, 384, ATTN_SMEM>>>(cvar, ccla, sat, hw1);
        k_fin<<<finBlocks, 256, FIN_SMEM>>>(bo);
        k_cf<<<NC, 64>>>(cvar, WQ2, WK2, WV2);
        k_edge<<<(NE + 7) / 8, 256>>>(ei, shv, hw2);
    }
    k_pool<<<512, 256>>>();
    k_mlp<<<1, 128>>>(W1, b1, W2, b2, (float*)d_out);
}

// round 13
// speedup vs baseline: 2.7290x; 1.1553x over previous
#include <cuda_runtime.h>
#include <cuda_fp16.h>
#include <math.h>
#include <cstdint>
#include <mma.h>

using namespace nvcuda;

#define N_VAR 50000
#define N_CLA 100000
#define NM    150000
#define DD    64
#define NC    1000
#define VC    64
#define KCL   128
#define NN    192
#define NE    8000
#define NSH   8
#define NITER 3
#define NEG   0.2f
#define INVSCALE 0.125f

// fp16 fragments (all GEMMs)
typedef wmma::fragment<wmma::matrix_a, 16, 16, 16, __half, wmma::row_major> HA;
typedef wmma::fragment<wmma::matrix_b, 16, 16, 16, __half, wmma::col_major> HBC;
typedef wmma::fragment<wmma::matrix_b, 16, 16, 16, __half, wmma::row_major> HBR;
typedef wmma::fragment<wmma::accumulator, 16, 16, 16, float> HC;
typedef wmma::fragment<wmma::accumulator, 16, 16, 16, __half> HCH;

__device__ __forceinline__ void red_add_v4(float* p, float4 v) {
    asm volatile("red.global.add.v4.f32 [%0], {%1,%2,%3,%4};"
                 :: "l"(p), "f"(v.x), "f"(v.y), "f"(v.z), "f"(v.w) : "memory");
}
__device__ __forceinline__ void red_add_v4h2(__half* p, uint32_t a, uint32_t b,
                                             uint32_t c, uint32_t d) {
    asm volatile("red.global.add.noftz.v4.f16x2 [%0], {%1,%2,%3,%4};"
                 :: "l"(p), "r"(a), "r"(b), "r"(c), "r"(d) : "memory");
}

// ---------------- scratch ----------------------------------------------------
__device__ float  g_x   [NM * DD];
__device__ __half g_Qh  [NM * DD];
__device__ __half g_Kh  [NM * DD];
__device__ __half g_Vh  [NM * DD];
__device__ __half g_acch[NM * DD];
__device__ float  g_cnt [NM];        // reciprocal counts after k_rcnt
__device__ float  g_Q2  [NC * DD];
__device__ float  g_K2  [NC * DD];
__device__ float  g_V2  [NC * DD];
__device__ float  g_pool[2 * DD];
__device__ __half g_Wh  [3 * DD * DD];   // WQ1/WK1/WV1 as half
__device__ __half g_Woh [DD * DD];       // Wo as half

__global__ void k_init(const float* __restrict__ xv, const float* __restrict__ xc) {
    int stride = gridDim.x * blockDim.x;
    int t = blockIdx.x * blockDim.x + threadIdx.x;
    for (int i = t; i < NM * DD; i += stride)
        g_x[i] = (i < N_VAR * DD) ? xv[i] : xc[i - N_VAR * DD];
    for (int i = t; i < NM; i += stride) g_cnt[i] = 0.f;
    if (t < 2 * DD) g_pool[t] = 0.f;
}

// weights->half AND node occurrence counts (both iteration-invariant)
__global__ void k_prep(const float* __restrict__ WQ, const float* __restrict__ WK,
                       const float* __restrict__ WV, const float* __restrict__ Wo,
                       const int* __restrict__ cvar, const int* __restrict__ ccla) {
    int i = blockIdx.x * blockDim.x + threadIdx.x;
    if (i < 4096)       g_Wh[i]        = __float2half_rn(WQ[i]);
    else if (i < 8192)  g_Wh[i]        = __float2half_rn(WK[i - 4096]);
    else if (i < 12288) g_Wh[i]        = __float2half_rn(WV[i - 8192]);
    else if (i < 16384) g_Woh[i-12288] = __float2half_rn(Wo[i - 12288]);
    if (i < NC * VC) atomicAdd(&g_cnt[cvar[i]], 1.f);
    else if (i < NC * (VC + KCL)) atomicAdd(&g_cnt[N_VAR + ccla[i - NC * VC]], 1.f);
}
__global__ void k_rcnt() {
    int i = blockIdx.x * blockDim.x + threadIdx.x;
    if (i < NM) g_cnt[i] = 1.f / fmaxf(g_cnt[i], 1.f);
}

// ---------------- Q/K/V projection via WMMA fp16, staged coalesced stores ----
// 128 rows/CTA, 8 warps; each warp stages its half C-tiles in its own dead
// A-band of xs, then copies out as coalesced 128B rows. 46KB -> 4 CTAs/SM.
#define PROJ_SMEM (27648 + 18432)
__global__ void __launch_bounds__(256, 4) k_proj() {
    extern __shared__ char smem[];
    __half* Wh = (__half*)smem;                       // [3][64][72]
    __half* xs = (__half*)(smem + 27648);             // [128][72]
    int tid = threadIdx.x, wid = tid >> 5, lane = tid & 31;

    for (int i = tid; i < 3 * 64 * 16; i += 256) {
        int m = i >> 10, rem = i & 1023, d = rem >> 4, q4 = rem & 15;
        *(uint2*)(Wh + m * 4608 + d * 72 + q4 * 4) =
            *(const uint2*)(g_Wh + m * 4096 + d * 64 + q4 * 4);
    }
    size_t base = (size_t)blockIdx.x * 128;
    for (int i = tid; i < 128 * 16; i += 256) {
        int row = i >> 4, q4 = i & 15;
        size_t r = base + row;
        if (r < NM) {
            float4 v = ((const float4*)(g_x + r * 64))[q4];
            __half2 h0 = __floats2half2_rn(v.x, v.y);
            __half2 h1 = __floats2half2_rn(v.z, v.w);
            uint2 u; u.x = *(uint32_t*)&h0; u.y = *(uint32_t*)&h1;
            *(uint2*)(xs + row * 72 + q4 * 4) = u;
        }
    }
    __syncthreads();

    int rowbase = wid * 16;
    if (base + rowbase < NM) {
        HA a[4];
        #pragma unroll
        for (int k = 0; k < 4; k++)
            wmma::load_matrix_sync(a[k], xs + rowbase * 72 + k * 16, 72);
        __half* band = xs + rowbase * 72;     // dead after A-frag loads
        __half* outs[3] = {g_Qh, g_Kh, g_Vh};
        #pragma unroll
        for (int m = 0; m < 3; m++) {
            #pragma unroll
            for (int tc = 0; tc < 4; tc++) {
                HC acc;
                wmma::fill_fragment(acc, 0.f);
                #pragma unroll
                for (int k = 0; k < 4; k++) {
                    HBC b;
                    wmma::load_matrix_sync(b, Wh + m * 4608 + tc * 16 * 72 + k * 16, 72);
                    wmma::mma_sync(acc, a[k], b, acc);
                }
                HCH h;
                if (m == 0) {
                    #pragma unroll
                    for (int t = 0; t < acc.num_elements; t++)
                        h.x[t] = __float2half_rn(acc.x[t] * INVSCALE);
                } else {
                    #pragma unroll
                    for (int t = 0; t < acc.num_elements; t++)
                        h.x[t] = __float2half_rn(acc.x[t]);
                }
                wmma::store_matrix_sync(band + tc * 16, h, 72, wmma::mem_row_major);
            }
            __syncwarp();
            // coalesced copy out: 16 rows x 8 uint4 (128B per row)
            __half* dst = outs[m] + (base + rowbase) * 64;
            #pragma unroll
            for (int i = 0; i < 4; i++) {
                int idx = lane + 32 * i;
                int row = idx >> 3, q8 = idx & 7;
                *(uint4*)(dst + row * 64 + q8 * 8) =
                    *(const uint4*)(band + row * 72 + q8 * 8);
            }
            __syncwarp();
        }
    }
    // zero g_acch
    uint4 z4 = make_uint4(0u, 0u, 0u, 0u);
    for (int i = tid; i < 128 * 8; i += 256) {
        int row = i >> 3, q8 = i & 7;
        size_t r = base + row;
        if (r < NM) *(uint4*)(g_acch + r * 64 + q8 * 8) = z4;
    }
}

// ---------------- intra-cluster attention via WMMA fp16 ----------------------
// 6 bands x 32 queries; Q prefetch overlapped with softmax; fused tile scatter.
#define OFFB_K  0
#define OFFB_V  27648
#define OFFB_Q  55296
#define OFFB_S  59904
#define OFFB_RS 72704
#define OFFB_B  72832
#define OFFB_N  73600
#define ATTN_SMEM 74368

__global__ void __launch_bounds__(384, 3) k_attn_wm(const int* __restrict__ cvar,
                                                    const int* __restrict__ ccla,
                                                    const float* __restrict__ sat,
                                                    const float* __restrict__ hw) {
    extern __shared__ char smem[];
    __half* Kh = (__half*)(smem + OFFB_K);     // [192][72]
    __half* Vh = (__half*)(smem + OFFB_V);     // [192][72]
    __half* Qh = (__half*)(smem + OFFB_Q);     // [32][72]
    __half* Sh = (__half*)(smem + OFFB_S);     // [32][200] scores -> exp (in place)
    float*  Of = (float*)(smem + OFFB_S);      // [32][72] O staging (aliases Sh)
    float*  rowsum = (float*)(smem + OFFB_RS); // [32]
    float*  bsh = (float*)(smem + OFFB_B);     // [192]
    int*    nsh = (int*)(smem + OFFB_N);       // [192]

    int c = blockIdx.x, tid = threadIdx.x, wid = tid >> 5, lane = tid & 31;
    if (tid < NN) {
        int g; float b;
        if (tid < VC) { g = cvar[c * VC + tid]; b = 0.f; }
        else { int cl = ccla[c * KCL + (tid - VC)]; g = N_VAR + cl; b = sat[cl]; }
        nsh[tid] = g; bsh[tid] = b;
    }
    float hwm = 0.25f * (hw[0] + hw[1] + hw[2] + hw[3]);
    __syncthreads();

    for (int idx = tid; idx < 192 * 8; idx += 384) {
        int row = idx >> 3, q8 = idx & 7;
        size_t o = (size_t)nsh[row] * 64;
        *(uint4*)(Kh + row * 72 + q8 * 8) = ((const uint4*)(g_Kh + o))[q8];
        *(uint4*)(Vh + row * 72 + q8 * 8) = ((const uint4*)(g_Vh + o))[q8];
    }
    // gather band-0 Q
    for (int idx = tid; idx < 32 * 8; idx += 384) {
        int row = idx >> 3, q8 = idx & 7;
        *(uint4*)(Qh + row * 72 + q8 * 8) =
            ((const uint4*)(g_Qh + (size_t)nsh[row] * 64))[q8];
    }
    __syncthreads();

    for (int band = 0; band < 6; band++) {
        // GEMM1: S[32,192] = Qh @ Kh^T, stored as half
        {
            int tr = wid & 1, tc = wid >> 1;
            HA a[4];
            #pragma unroll
            for (int k = 0; k < 4; k++)
                wmma::load_matrix_sync(a[k], Qh + tr * 16 * 72 + k * 16, 72);
            #pragma unroll
            for (int half2x = 0; half2x < 2; half2x++) {
                int tcc = tc + half2x * 6;
                HC acc;
                wmma::fill_fragment(acc, 0.f);
                #pragma unroll
                for (int k = 0; k < 4; k++) {
                    HBC b;
                    wmma::load_matrix_sync(b, Kh + tcc * 16 * 72 + k * 16, 72);
                    wmma::mma_sync(acc, a[k], b, acc);
                }
                HCH h;
                #pragma unroll
                for (int t = 0; t < acc.num_elements; t++)
                    h.x[t] = __float2half_rn(acc.x[t]);
                wmma::store_matrix_sync(Sh + tr * 16 * 200 + tcc * 16, h, 200,
                                        wmma::mem_row_major);
            }
        }
        __syncthreads();

        // softmax (warps 0-7) || prefetch next band's Q (warps 8-11)
        if (tid < 256) {
            int srow = tid >> 3, c0 = tid & 7;
            __half* srw = Sh + srow * 200;
            float mx = -1e30f;
            #pragma unroll 8
            for (int i = 0; i < 24; i++) {
                int col = c0 + 8 * i;
                float s = __half2float(srw[col]) + bsh[col];
                s = (s >= 0.f) ? s : NEG * s;
                srw[col] = __float2half_rn(s);
                mx = fmaxf(mx, s);
            }
            mx = fmaxf(mx, __shfl_xor_sync(0xffffffffu, mx, 1));
            mx = fmaxf(mx, __shfl_xor_sync(0xffffffffu, mx, 2));
            mx = fmaxf(mx, __shfl_xor_sync(0xffffffffu, mx, 4));
            float sum = 0.f;
            #pragma unroll 8
            for (int i = 0; i < 24; i++) {
                int col = c0 + 8 * i;
                float e = __expf(__half2float(srw[col]) - mx);
                sum += e;
                srw[col] = __float2half_rn(e);
            }
            sum += __shfl_xor_sync(0xffffffffu, sum, 1);
            sum += __shfl_xor_sync(0xffffffffu, sum, 2);
            sum += __shfl_xor_sync(0xffffffffu, sum, 4);
            if (c0 == 0) rowsum[srow] = sum;
        } else if (band < 5) {
            for (int idx = tid - 256; idx < 32 * 8; idx += 128) {
                int row = idx >> 3, q8 = idx & 7;
                *(uint4*)(Qh + row * 72 + q8 * 8) =
                    ((const uint4*)(g_Qh + (size_t)nsh[(band + 1) * 32 + row] * 64))[q8];
            }
        }
        __syncthreads();

        // GEMM2: O[32,64] = P @ V; C-frag in regs across sync
        HC o0;
        wmma::fill_fragment(o0, 0.f);
        int tr2 = wid >> 2, tc2 = wid & 3;
        if (wid < 8) {
            #pragma unroll 4
            for (int k = 0; k < 12; k++) {
                HA a;
                wmma::load_matrix_sync(a, Sh + tr2 * 16 * 200 + k * 16, 200);
                HBR b0;
                wmma::load_matrix_sync(b0, Vh + k * 16 * 72 + tc2 * 16, 72);
                wmma::mma_sync(o0, a, b0, o0);
            }
        }
        __syncthreads();   // all reads of Sh done
        if (wid < 8) {
            wmma::store_matrix_sync(Of + tr2 * 16 * 72 + tc2 * 16, o0, 72,
                                    wmma::mem_row_major);
            __syncwarp();
            // fused scatter of this warp's own 16x16 tile
            int row = lane >> 1, c8 = (lane & 1) * 8;
            int grow = tr2 * 16 + row;
            int g = nsh[band * 32 + grow];
            float scl = hwm / rowsum[grow];
            const float* src = Of + grow * 72 + tc2 * 16 + c8;
            __half* dst = g_acch + (size_t)g * 64 + tc2 * 16 + c8;
            float4 f0 = *(const float4*)(src);
            float4 f1 = *(const float4*)(src + 4);
            __half2 h0 = __floats2half2_rn(f0.x * scl, f0.y * scl);
            __half2 h1 = __floats2half2_rn(f0.z * scl, f0.w * scl);
            __half2 h2 = __floats2half2_rn(f1.x * scl, f1.y * scl);
            __half2 h3 = __floats2half2_rn(f1.z * scl, f1.w * scl);
            red_add_v4h2(dst, *(uint32_t*)&h0, *(uint32_t*)&h1,
                              *(uint32_t*)&h2, *(uint32_t*)&h3);
        }
        __syncthreads();   // Of reads done before next band's GEMM1 writes Sh
    }
}

// ---------------- finalize via WMMA fp16 (staged in dead A-band) -------------
#define FIN_SMEM (9216 + 18432)
__global__ void __launch_bounds__(256, 4) k_fin(const float* __restrict__ bo) {
    extern __shared__ char smem[];
    __half* Wh = (__half*)smem;                   // [64][72] (d,k) at d*72+k
    __half* xs = (__half*)(smem + 9216);          // [128][72] acc halves / staging
    int tid = threadIdx.x, wid = tid >> 5, lane = tid & 31;

    for (int i = tid; i < 64 * 16; i += 256) {
        int d = i >> 4, q4 = i & 15;
        *(uint2*)(Wh + d * 72 + q4 * 4) = *(const uint2*)(g_Woh + d * 64 + q4 * 4);
    }
    size_t base = (size_t)blockIdx.x * 128;
    for (int i = tid; i < 128 * 8; i += 256) {
        int row = i >> 3, q8 = i & 7;
        size_t r = base + row;
        if (r < NM)
            *(uint4*)(xs + row * 72 + q8 * 8) = *(const uint4*)(g_acch + r * 64 + q8 * 8);
    }
    __syncthreads();

    int rowbase = wid * 16;
    if (base + rowbase < NM) {
        HA a[4];
        #pragma unroll
        for (int k = 0; k < 4; k++)
            wmma::load_matrix_sync(a[k], xs + rowbase * 72 + k * 16, 72);
        __half* band = xs + rowbase * 72;     // dead after A-frag loads
        #pragma unroll
        for (int tc = 0; tc < 4; tc++) {
            HC acc;
            wmma::fill_fragment(acc, 0.f);
            #pragma unroll
            for (int k = 0; k < 4; k++) {
                HBC b;
                wmma::load_matrix_sync(b, Wh + tc * 16 * 72 + k * 16, 72);
                wmma::mma_sync(acc, a[k], b, acc);
            }
            HCH h;
            #pragma unroll
            for (int t = 0; t < acc.num_elements; t++)
                h.x[t] = __float2half_rn(acc.x[t]);
            wmma::store_matrix_sync(band + tc * 16, h, 72, wmma::mem_row_major);
        }
        __syncwarp();
        // epilogue: read staged halves coalesced, fp32 scale + bias + residual
        #pragma unroll
        for (int i = 0; i < 4; i++) {
            int idx = lane + 32 * i;
            int row = idx >> 3, q8 = idx & 7;
            size_t r = base + rowbase + row;
            float rc = g_cnt[r];
            uint4 u = *(const uint4*)(band + row * 72 + q8 * 8);
            __half2 h0 = *(__half2*)&u.x, h1 = *(__half2*)&u.y;
            __half2 h2 = *(__half2*)&u.z, h3 = *(__half2*)&u.w;
            float2 f0 = __half22float2(h0), f1 = __half22float2(h1);
            float2 f2 = __half22float2(h2), f3 = __half22float2(h3);
            float* gx = g_x + r * 64 + q8 * 8;
            const float* bb = bo + q8 * 8;
            float4 x0 = *(float4*)gx, x1 = *(float4*)(gx + 4);
            float4 b0 = *(const float4*)bb, b1 = *(const float4*)(bb + 4);
            x0.x += f0.x * rc + b0.x; x0.y += f0.y * rc + b0.y;
            x0.z += f1.x * rc + b0.z; x0.w += f1.y * rc + b0.w;
            x1.x += f2.x * rc + b1.x; x1.y += f2.y * rc + b1.y;
            x1.z += f3.x * rc + b1.z; x1.w += f3.y * rc + b1.w;
            *(float4*)gx = x0; *(float4*)(gx + 4) = x1;
        }
    }
}

// ---------------- cluster features + Q2/K2/V2 projection ---------------------
__global__ void k_cf(const int* __restrict__ cvar,
                     const float* __restrict__ WQ2, const float* __restrict__ WK2,
                     const float* __restrict__ WV2) {
    __shared__ float cf[64];
    __shared__ int ids[64];
    int c = blockIdx.x, d = threadIdx.x;
    ids[d] = cvar[c * VC + d];
    __syncthreads();
    float s = 0.f;
    #pragma unroll 8
    for (int v = 0; v < VC; v++) s += g_x[(size_t)ids[v] * DD + d];
    cf[d] = s * (1.f / 64.f);
    __syncthreads();
    float q = 0.f, k = 0.f, v = 0.f;
    #pragma unroll 8
    for (int j = 0; j < 64; j++) {
        float x = cf[j];
        q = fmaf(x, WQ2[d * 64 + j], q);
        k = fmaf(x, WK2[d * 64 + j], k);
        v = fmaf(x, WV2[d * 64 + j], v);
    }
    g_Q2[c * 64 + d] = q; g_K2[c * 64 + d] = k; g_V2[c * 64 + d] = v;
}

// ---------------- inter-cluster edge scatter (GAT2, vectorized atomics) ------
__global__ void k_edge(const int* __restrict__ ei, const int* __restrict__ shv,
                       const float* __restrict__ hw) {
    int tid = threadIdx.x;
    int warp = tid >> 5, lane = tid & 31;
    int e = blockIdx.x * 8 + warp;
    if (e >= NE) return;
    int c1 = ei[e], c2 = ei[NE + e];
    float p = g_Q2[c1 * 64 + lane] * g_K2[c2 * 64 + lane]
            + g_Q2[c1 * 64 + lane + 32] * g_K2[c2 * 64 + lane + 32];
    #pragma unroll
    for (int o = 16; o > 0; o >>= 1) p += __shfl_xor_sync(0xffffffffu, p, o);
    float s = p * INVSCALE;
    float lr = (s >= 0.f) ? s : NEG * s;
    float hwm = 0.25f * (hw[0] + hw[1] + hw[2] + hw[3]);
    float a = hwm / (1.f + __expf(-lr));
    float4 v4 = make_float4(0.f, 0.f, 0.f, 0.f);
    if (lane < 16) {
        v4 = ((const float4*)(g_V2 + (size_t)c2 * 64))[lane];
        v4.x *= a; v4.y *= a; v4.z *= a; v4.w *= a;
    }
    #pragma unroll
    for (int k = 0; k < NSH; k++) {
        int sv = shv[e * NSH + k];
        if (lane < 16) red_add_v4(g_x + (size_t)sv * 64 + lane * 4, v4);
    }
}

// ---------------- pooling + MLP readout --------------------------------------
__global__ void k_pool() {
    int tid = threadIdx.x;
    int col = tid & 63;
    int rg = tid >> 6;
    float sv = 0.f, sc = 0.f;
    for (int r = blockIdx.x * 4 + rg; r < NM; r += gridDim.x * 4) {
        float x = g_x[(size_t)r * DD + col];
        if (r < N_VAR) sv += x; else sc += x;
    }
    atomicAdd(&g_pool[col], sv);
    atomicAdd(&g_pool[64 + col], sc);
}

__global__ void k_mlp(const float* __restrict__ W1, const float* __restrict__ b1,
                      const float* __restrict__ W2, const float* __restrict__ b2,
                      float* __restrict__ out) {
    __shared__ float p[128];
    __shared__ float h[64];
    int tid = threadIdx.x;
    if (tid < 128)
        p[tid] = tanhf(g_pool[tid] * (tid < 64 ? 1.f / N_VAR : 1.f / N_CLA));
    __syncthreads();
    if (tid < 64) {
        float a = b1[tid];
        #pragma unroll 8
        for (int j = 0; j < 128; j++) a = fmaf(p[j], W1[tid * 128 + j], a);
        h[tid] = (a > 0.f) ? a : 0.f;
    }
    __syncthreads();
    if (tid == 0) {
        float s = b2[0];
        for (int i = 0; i < 64; i++) s = fmaf(h[i], W2[i], s);
        out[0] = s;
    }
}

// ---------------- launch ------------------------------------------------------
extern "C" void kernel_launch(void* const* d_in, const int* in_sizes, int n_in,
                              void* d_out, int out_size) {
    (void)in_sizes; (void)n_in; (void)out_size;
    const float* xv   = (const float*)d_in[0];
    const float* xc   = (const float*)d_in[1];
    const float* sat  = (const float*)d_in[2];
    const int*   cvar = (const int*)d_in[3];
    const int*   ccla = (const int*)d_in[4];
    const int*   ei   = (const int*)d_in[5];
    const int*   shv  = (const int*)d_in[6];
    const float* WQ1  = (const float*)d_in[7];
    const float* WK1  = (const float*)d_in[8];
    const float* WV1  = (const float*)d_in[9];
    const float* hw1  = (const float*)d_in[10];
    const float* Wo   = (const float*)d_in[11];
    const float* bo   = (const float*)d_in[12];
    const float* WQ2  = (const float*)d_in[13];
    const float* WK2  = (const float*)d_in[14];
    const float* WV2  = (const float*)d_in[15];
    const float* hw2  = (const float*)d_in[16];
    const float* W1   = (const float*)d_in[17];
    const float* b1   = (const float*)d_in[18];
    const float* W2   = (const float*)d_in[19];
    const float* b2   = (const float*)d_in[20];

    cudaFuncSetAttribute(k_proj,    cudaFuncAttributeMaxDynamicSharedMemorySize, PROJ_SMEM);
    cudaFuncSetAttribute(k_attn_wm, cudaFuncAttributeMaxDynamicSharedMemorySize, ATTN_SMEM);
    cudaFuncSetAttribute(k_fin,     cudaFuncAttributeMaxDynamicSharedMemorySize, FIN_SMEM);

    k_init<<<512, 256>>>(xv, xc);
    k_prep<<<(NC * (VC + KCL) + 255) / 256, 256>>>(WQ1, WK1, WV1, Wo, cvar, ccla);
    k_rcnt<<<(NM + 255) / 256, 256>>>();
    const int blocks128 = (NM + 127) / 128;
    for (int it = 0; it < NITER; it++) {
        k_proj<<<blocks128, 256, PROJ_SMEM>>>();                // also zeroes g_acch
        k_attn_wm<<<NC, 384, ATTN_SMEM>>>(cvar, ccla, sat, hw1);
        k_fin<<<blocks128, 256, FIN_SMEM>>>(bo);
        k_cf<<<NC, 64>>>(cvar, WQ2, WK2, WV2);
        k_edge<<<(NE + 7) / 8, 256>>>(ei, shv, hw2);
    }
    k_pool<<<512, 256>>>();
    k_mlp<<<1, 128>>>(W1, b1, W2, b2, (float*)d_out);
}

// round 14
// speedup vs baseline: 2.8457x; 1.0428x over previous
#include <cuda_runtime.h>
#include <cuda_fp16.h>
#include <math.h>
#include <cstdint>
#include <mma.h>

using namespace nvcuda;

#define N_VAR 50000
#define N_CLA 100000
#define NM    150000
#define DD    64
#define NC    1000
#define VC    64
#define KCL   128
#define NN    192
#define NE    8000
#define NSH   8
#define NITER 3
#define NEG   0.2f
#define INVSCALE 0.125f

// fp16 fragments (all GEMMs)
typedef wmma::fragment<wmma::matrix_a, 16, 16, 16, __half, wmma::row_major> HA;
typedef wmma::fragment<wmma::matrix_b, 16, 16, 16, __half, wmma::col_major> HBC;
typedef wmma::fragment<wmma::matrix_b, 16, 16, 16, __half, wmma::row_major> HBR;
typedef wmma::fragment<wmma::accumulator, 16, 16, 16, float> HC;
typedef wmma::fragment<wmma::accumulator, 16, 16, 16, __half> HCH;

__device__ __forceinline__ void red_add_v4(float* p, float4 v) {
    asm volatile("red.global.add.v4.f32 [%0], {%1,%2,%3,%4};"
                 :: "l"(p), "f"(v.x), "f"(v.y), "f"(v.z), "f"(v.w) : "memory");
}
__device__ __forceinline__ void red_add_v4h2(__half* p, uint32_t a, uint32_t b,
                                             uint32_t c, uint32_t d) {
    asm volatile("red.global.add.noftz.v4.f16x2 [%0], {%1,%2,%3,%4};"
                 :: "l"(p), "r"(a), "r"(b), "r"(c), "r"(d) : "memory");
}

// ---------------- scratch ----------------------------------------------------
__device__ float  g_x   [NM * DD];
__device__ __half g_Qh  [NM * DD];
__device__ __half g_Kh  [NM * DD];
__device__ __half g_Vh  [NM * DD];
__device__ __half g_acch[NM * DD];
__device__ float  g_cnt [NM];        // reciprocal counts after k_rcnt
__device__ float  g_Q2  [NC * DD];
__device__ float  g_K2  [NC * DD];
__device__ float  g_V2  [NC * DD];
__device__ float  g_pool[2 * DD];
__device__ __half g_Wh  [3 * DD * DD];   // WQ1/WK1/WV1 as half
__device__ __half g_Woh [DD * DD];       // Wo as half

__global__ void k_zero0() {
    int t = blockIdx.x * blockDim.x + threadIdx.x;
    if (t < NM) g_cnt[t] = 0.f;
    if (t < 2 * DD) g_pool[t] = 0.f;
}

// weights->half AND node occurrence counts (both iteration-invariant)
__global__ void k_prep(const float* __restrict__ WQ, const float* __restrict__ WK,
                       const float* __restrict__ WV, const float* __restrict__ Wo,
                       const int* __restrict__ cvar, const int* __restrict__ ccla) {
    int i = blockIdx.x * blockDim.x + threadIdx.x;
    if (i < 4096)       g_Wh[i]        = __float2half_rn(WQ[i]);
    else if (i < 8192)  g_Wh[i]        = __float2half_rn(WK[i - 4096]);
    else if (i < 12288) g_Wh[i]        = __float2half_rn(WV[i - 8192]);
    else if (i < 16384) g_Woh[i-12288] = __float2half_rn(Wo[i - 12288]);
    if (i < NC * VC) atomicAdd(&g_cnt[cvar[i]], 1.f);
    else if (i < NC * (VC + KCL)) atomicAdd(&g_cnt[N_VAR + ccla[i - NC * VC]], 1.f);
}
__global__ void k_rcnt() {
    int i = blockIdx.x * blockDim.x + threadIdx.x;
    if (i < NM) g_cnt[i] = 1.f / fmaxf(g_cnt[i], 1.f);
}

// row pointer helper: iteration 0 reads directly from the harness inputs
__device__ __forceinline__ const float* xrow(const float* xv, const float* xc,
                                             int first, size_t r) {
    if (first)
        return (r < N_VAR) ? (xv + r * 64) : (xc + (r - (size_t)N_VAR) * 64);
    return g_x + r * 64;
}

// ---------------- Q/K/V projection via WMMA fp16, staged coalesced stores ----
#define PROJ_SMEM (27648 + 18432)
__global__ void __launch_bounds__(256, 4) k_proj(const float* __restrict__ xv,
                                                 const float* __restrict__ xc,
                                                 int first) {
    extern __shared__ char smem[];
    __half* Wh = (__half*)smem;                       // [3][64][72]
    __half* xs = (__half*)(smem + 27648);             // [128][72]
    int tid = threadIdx.x, wid = tid >> 5, lane = tid & 31;

    for (int i = tid; i < 3 * 64 * 16; i += 256) {
        int m = i >> 10, rem = i & 1023, d = rem >> 4, q4 = rem & 15;
        *(uint2*)(Wh + m * 4608 + d * 72 + q4 * 4) =
            *(const uint2*)(g_Wh + m * 4096 + d * 64 + q4 * 4);
    }
    size_t base = (size_t)blockIdx.x * 128;
    for (int i = tid; i < 128 * 16; i += 256) {
        int row = i >> 4, q4 = i & 15;
        size_t r = base + row;
        if (r < NM) {
            float4 v = ((const float4*)xrow(xv, xc, first, r))[q4];
            __half2 h0 = __floats2half2_rn(v.x, v.y);
            __half2 h1 = __floats2half2_rn(v.z, v.w);
            uint2 u; u.x = *(uint32_t*)&h0; u.y = *(uint32_t*)&h1;
            *(uint2*)(xs + row * 72 + q4 * 4) = u;
        }
    }
    __syncthreads();

    int rowbase = wid * 16;
    if (base + rowbase < NM) {
        HA a[4];
        #pragma unroll
        for (int k = 0; k < 4; k++)
            wmma::load_matrix_sync(a[k], xs + rowbase * 72 + k * 16, 72);
        __half* band = xs + rowbase * 72;     // dead after A-frag loads
        __half* outs[3] = {g_Qh, g_Kh, g_Vh};
        #pragma unroll
        for (int m = 0; m < 3; m++) {
            #pragma unroll
            for (int tc = 0; tc < 4; tc++) {
                HC acc;
                wmma::fill_fragment(acc, 0.f);
                #pragma unroll
                for (int k = 0; k < 4; k++) {
                    HBC b;
                    wmma::load_matrix_sync(b, Wh + m * 4608 + tc * 16 * 72 + k * 16, 72);
                    wmma::mma_sync(acc, a[k], b, acc);
                }
                HCH h;
                if (m == 0) {
                    #pragma unroll
                    for (int t = 0; t < acc.num_elements; t++)
                        h.x[t] = __float2half_rn(acc.x[t] * INVSCALE);
                } else {
                    #pragma unroll
                    for (int t = 0; t < acc.num_elements; t++)
                        h.x[t] = __float2half_rn(acc.x[t]);
                }
                wmma::store_matrix_sync(band + tc * 16, h, 72, wmma::mem_row_major);
            }
            __syncwarp();
            __half* dst = outs[m] + (base + rowbase) * 64;
            #pragma unroll
            for (int i = 0; i < 4; i++) {
                int idx = lane + 32 * i;
                int row = idx >> 3, q8 = idx & 7;
                *(uint4*)(dst + row * 64 + q8 * 8) =
                    *(const uint4*)(band + row * 72 + q8 * 8);
            }
            __syncwarp();
        }
    }
    // zero g_acch
    uint4 z4 = make_uint4(0u, 0u, 0u, 0u);
    for (int i = tid; i < 128 * 8; i += 256) {
        int row = i >> 3, q8 = i & 7;
        size_t r = base + row;
        if (r < NM) *(uint4*)(g_acch + r * 64 + q8 * 8) = z4;
    }
}

// ---------------- intra-cluster attention via WMMA fp16 ----------------------
#define OFFB_K  0
#define OFFB_V  27648
#define OFFB_Q  55296
#define OFFB_S  59904
#define OFFB_RS 72704
#define OFFB_B  72832
#define OFFB_N  73600
#define ATTN_SMEM 74368

__global__ void __launch_bounds__(384, 3) k_attn_wm(const int* __restrict__ cvar,
                                                    const int* __restrict__ ccla,
                                                    const float* __restrict__ sat,
                                                    const float* __restrict__ hw) {
    extern __shared__ char smem[];
    __half* Kh = (__half*)(smem + OFFB_K);     // [192][72]
    __half* Vh = (__half*)(smem + OFFB_V);     // [192][72]
    __half* Qh = (__half*)(smem + OFFB_Q);     // [32][72]
    __half* Sh = (__half*)(smem + OFFB_S);     // [32][200] scores -> exp (in place)
    float*  Of = (float*)(smem + OFFB_S);      // [32][72] O staging (aliases Sh)
    float*  rowsum = (float*)(smem + OFFB_RS); // [32]
    float*  bsh = (float*)(smem + OFFB_B);     // [192]
    int*    nsh = (int*)(smem + OFFB_N);       // [192]

    int c = blockIdx.x, tid = threadIdx.x, wid = tid >> 5, lane = tid & 31;
    if (tid < NN) {
        int g; float b;
        if (tid < VC) { g = cvar[c * VC + tid]; b = 0.f; }
        else { int cl = ccla[c * KCL + (tid - VC)]; g = N_VAR + cl; b = sat[cl]; }
        nsh[tid] = g; bsh[tid] = b;
    }
    float hwm = 0.25f * (hw[0] + hw[1] + hw[2] + hw[3]);
    __syncthreads();

    for (int idx = tid; idx < 192 * 8; idx += 384) {
        int row = idx >> 3, q8 = idx & 7;
        size_t o = (size_t)nsh[row] * 64;
        *(uint4*)(Kh + row * 72 + q8 * 8) = ((const uint4*)(g_Kh + o))[q8];
        *(uint4*)(Vh + row * 72 + q8 * 8) = ((const uint4*)(g_Vh + o))[q8];
    }
    // gather band-0 Q
    for (int idx = tid; idx < 32 * 8; idx += 384) {
        int row = idx >> 3, q8 = idx & 7;
        *(uint4*)(Qh + row * 72 + q8 * 8) =
            ((const uint4*)(g_Qh + (size_t)nsh[row] * 64))[q8];
    }
    __syncthreads();

    for (int band = 0; band < 6; band++) {
        // GEMM1: S[32,192] = Qh @ Kh^T, stored as half
        {
            int tr = wid & 1, tc = wid >> 1;
            HA a[4];
            #pragma unroll
            for (int k = 0; k < 4; k++)
                wmma::load_matrix_sync(a[k], Qh + tr * 16 * 72 + k * 16, 72);
            #pragma unroll
            for (int half2x = 0; half2x < 2; half2x++) {
                int tcc = tc + half2x * 6;
                HC acc;
                wmma::fill_fragment(acc, 0.f);
                #pragma unroll
                for (int k = 0; k < 4; k++) {
                    HBC b;
                    wmma::load_matrix_sync(b, Kh + tcc * 16 * 72 + k * 16, 72);
                    wmma::mma_sync(acc, a[k], b, acc);
                }
                HCH h;
                #pragma unroll
                for (int t = 0; t < acc.num_elements; t++)
                    h.x[t] = __float2half_rn(acc.x[t]);
                wmma::store_matrix_sync(Sh + tr * 16 * 200 + tcc * 16, h, 200,
                                        wmma::mem_row_major);
            }
        }
        __syncthreads();

        // softmax (warps 0-7) || prefetch next band's Q (warps 8-11)
        if (tid < 256) {
            int srow = tid >> 3, c0 = tid & 7;
            __half* srw = Sh + srow * 200;
            float mx = -1e30f;
            #pragma unroll 8
            for (int i = 0; i < 24; i++) {
                int col = c0 + 8 * i;
                float s = __half2float(srw[col]) + bsh[col];
                s = (s >= 0.f) ? s : NEG * s;
                srw[col] = __float2half_rn(s);
                mx = fmaxf(mx, s);
            }
            mx = fmaxf(mx, __shfl_xor_sync(0xffffffffu, mx, 1));
            mx = fmaxf(mx, __shfl_xor_sync(0xffffffffu, mx, 2));
            mx = fmaxf(mx, __shfl_xor_sync(0xffffffffu, mx, 4));
            float sum = 0.f;
            #pragma unroll 8
            for (int i = 0; i < 24; i++) {
                int col = c0 + 8 * i;
                float e = __expf(__half2float(srw[col]) - mx);
                sum += e;
                srw[col] = __float2half_rn(e);
            }
            sum += __shfl_xor_sync(0xffffffffu, sum, 1);
            sum += __shfl_xor_sync(0xffffffffu, sum, 2);
            sum += __shfl_xor_sync(0xffffffffu, sum, 4);
            if (c0 == 0) rowsum[srow] = sum;
        } else if (band < 5) {
            for (int idx = tid - 256; idx < 32 * 8; idx += 128) {
                int row = idx >> 3, q8 = idx & 7;
                *(uint4*)(Qh + row * 72 + q8 * 8) =
                    ((const uint4*)(g_Qh + (size_t)nsh[(band + 1) * 32 + row] * 64))[q8];
            }
        }
        __syncthreads();

        // GEMM2: O[32,64] = P @ V; C-frag in regs across sync
        HC o0;
        wmma::fill_fragment(o0, 0.f);
        int tr2 = wid >> 2, tc2 = wid & 3;
        if (wid < 8) {
            #pragma unroll 4
            for (int k = 0; k < 12; k++) {
                HA a;
                wmma::load_matrix_sync(a, Sh + tr2 * 16 * 200 + k * 16, 200);
                HBR b0;
                wmma::load_matrix_sync(b0, Vh + k * 16 * 72 + tc2 * 16, 72);
                wmma::mma_sync(o0, a, b0, o0);
            }
        }
        __syncthreads();   // all reads of Sh done
        if (wid < 8) {
            wmma::store_matrix_sync(Of + tr2 * 16 * 72 + tc2 * 16, o0, 72,
                                    wmma::mem_row_major);
            __syncwarp();
            int row = lane >> 1, c8 = (lane & 1) * 8;
            int grow = tr2 * 16 + row;
            int g = nsh[band * 32 + grow];
            float scl = hwm / rowsum[grow];
            const float* src = Of + grow * 72 + tc2 * 16 + c8;
            __half* dst = g_acch + (size_t)g * 64 + tc2 * 16 + c8;
            float4 f0 = *(const float4*)(src);
            float4 f1 = *(const float4*)(src + 4);
            __half2 h0 = __floats2half2_rn(f0.x * scl, f0.y * scl);
            __half2 h1 = __floats2half2_rn(f0.z * scl, f0.w * scl);
            __half2 h2 = __floats2half2_rn(f1.x * scl, f1.y * scl);
            __half2 h3 = __floats2half2_rn(f1.z * scl, f1.w * scl);
            red_add_v4h2(dst, *(uint32_t*)&h0, *(uint32_t*)&h1,
                              *(uint32_t*)&h2, *(uint32_t*)&h3);
        }
        __syncthreads();   // Of reads done before next band's GEMM1 writes Sh
    }
}

// ---------------- finalize via WMMA fp16 (staged in dead A-band) -------------
#define FIN_SMEM (9216 + 18432)
__global__ void __launch_bounds__(256, 4) k_fin(const float* __restrict__ bo,
                                                const float* __restrict__ xv,
                                                const float* __restrict__ xc,
                                                int first) {
    extern __shared__ char smem[];
    __half* Wh = (__half*)smem;                   // [64][72] (d,k) at d*72+k
    __half* xs = (__half*)(smem + 9216);          // [128][72] acc halves / staging
    int tid = threadIdx.x, wid = tid >> 5, lane = tid & 31;

    for (int i = tid; i < 64 * 16; i += 256) {
        int d = i >> 4, q4 = i & 15;
        *(uint2*)(Wh + d * 72 + q4 * 4) = *(const uint2*)(g_Woh + d * 64 + q4 * 4);
    }
    size_t base = (size_t)blockIdx.x * 128;
    for (int i = tid; i < 128 * 8; i += 256) {
        int row = i >> 3, q8 = i & 7;
        size_t r = base + row;
        if (r < NM)
            *(uint4*)(xs + row * 72 + q8 * 8) = *(const uint4*)(g_acch + r * 64 + q8 * 8);
    }
    __syncthreads();

    int rowbase = wid * 16;
    if (base + rowbase < NM) {
        HA a[4];
        #pragma unroll
        for (int k = 0; k < 4; k++)
            wmma::load_matrix_sync(a[k], xs + rowbase * 72 + k * 16, 72);
        __half* band = xs + rowbase * 72;
        #pragma unroll
        for (int tc = 0; tc < 4; tc++) {
            HC acc;
            wmma::fill_fragment(acc, 0.f);
            #pragma unroll
            for (int k = 0; k < 4; k++) {
                HBC b;
                wmma::load_matrix_sync(b, Wh + tc * 16 * 72 + k * 16, 72);
                wmma::mma_sync(acc, a[k], b, acc);
            }
            HCH h;
            #pragma unroll
            for (int t = 0; t < acc.num_elements; t++)
                h.x[t] = __float2half_rn(acc.x[t]);
            wmma::store_matrix_sync(band + tc * 16, h, 72, wmma::mem_row_major);
        }
        __syncwarp();
        #pragma unroll
        for (int i = 0; i < 4; i++) {
            int idx = lane + 32 * i;
            int row = idx >> 3, q8 = idx & 7;
            size_t r = base + rowbase + row;
            float rc = g_cnt[r];
            uint4 u = *(const uint4*)(band + row * 72 + q8 * 8);
            __half2 h0 = *(__half2*)&u.x, h1 = *(__half2*)&u.y;
            __half2 h2 = *(__half2*)&u.z, h3 = *(__half2*)&u.w;
            float2 f0 = __half22float2(h0), f1 = __half22float2(h1);
            float2 f2 = __half22float2(h2), f3 = __half22float2(h3);
            const float* xr = xrow(xv, xc, first, r) + q8 * 8;
            float* gx = g_x + r * 64 + q8 * 8;
            const float* bb = bo + q8 * 8;
            float4 x0 = *(const float4*)xr, x1 = *(const float4*)(xr + 4);
            float4 b0 = *(const float4*)bb, b1 = *(const float4*)(bb + 4);
            x0.x += f0.x * rc + b0.x; x0.y += f0.y * rc + b0.y;
            x0.z += f1.x * rc + b0.z; x0.w += f1.y * rc + b0.w;
            x1.x += f2.x * rc + b1.x; x1.y += f2.y * rc + b1.y;
            x1.z += f3.x * rc + b1.z; x1.w += f3.y * rc + b1.w;
            *(float4*)gx = x0; *(float4*)(gx + 4) = x1;
        }
    }
}

// ---------------- cluster features + Q2/K2/V2 projection ---------------------
__global__ void k_cf(const int* __restrict__ cvar,
                     const float* __restrict__ WQ2, const float* __restrict__ WK2,
                     const float* __restrict__ WV2) {
    __shared__ float cf[64];
    __shared__ int ids[64];
    int c = blockIdx.x, d = threadIdx.x;
    ids[d] = cvar[c * VC + d];
    __syncthreads();
    float s = 0.f;
    #pragma unroll 8
    for (int v = 0; v < VC; v++) s += g_x[(size_t)ids[v] * DD + d];
    cf[d] = s * (1.f / 64.f);
    __syncthreads();
    float q = 0.f, k = 0.f, v = 0.f;
    #pragma unroll 8
    for (int j = 0; j < 64; j++) {
        float x = cf[j];
        q = fmaf(x, WQ2[d * 64 + j], q);
        k = fmaf(x, WK2[d * 64 + j], k);
        v = fmaf(x, WV2[d * 64 + j], v);
    }
    g_Q2[c * 64 + d] = q; g_K2[c * 64 + d] = k; g_V2[c * 64 + d] = v;
}

// ---------------- inter-cluster edge scatter (GAT2, vectorized atomics) ------
__global__ void k_edge(const int* __restrict__ ei, const int* __restrict__ shv,
                       const float* __restrict__ hw) {
    int tid = threadIdx.x;
    int warp = tid >> 5, lane = tid & 31;
    int e = blockIdx.x * 8 + warp;
    if (e >= NE) return;
    int c1 = ei[e], c2 = ei[NE + e];
    float p = g_Q2[c1 * 64 + lane] * g_K2[c2 * 64 + lane]
            + g_Q2[c1 * 64 + lane + 32] * g_K2[c2 * 64 + lane + 32];
    #pragma unroll
    for (int o = 16; o > 0; o >>= 1) p += __shfl_xor_sync(0xffffffffu, p, o);
    float s = p * INVSCALE;
    float lr = (s >= 0.f) ? s : NEG * s;
    float hwm = 0.25f * (hw[0] + hw[1] + hw[2] + hw[3]);
    float a = hwm / (1.f + __expf(-lr));
    float4 v4 = make_float4(0.f, 0.f, 0.f, 0.f);
    if (lane < 16) {
        v4 = ((const float4*)(g_V2 + (size_t)c2 * 64))[lane];
        v4.x *= a; v4.y *= a; v4.z *= a; v4.w *= a;
    }
    #pragma unroll
    for (int k = 0; k < NSH; k++) {
        int sv = shv[e * NSH + k];
        if (lane < 16) red_add_v4(g_x + (size_t)sv * 64 + lane * 4, v4);
    }
}

// ---------------- pooling + MLP readout --------------------------------------
__global__ void k_pool() {
    int tid = threadIdx.x;
    int col = tid & 63;
    int rg = tid >> 6;
    float sv = 0.f, sc = 0.f;
    for (int r = blockIdx.x * 4 + rg; r < NM; r += gridDim.x * 4) {
        float x = g_x[(size_t)r * DD + col];
        if (r < N_VAR) sv += x; else sc += x;
    }
    atomicAdd(&g_pool[col], sv);
    atomicAdd(&g_pool[64 + col], sc);
}

__global__ void k_mlp(const float* __restrict__ W1, const float* __restrict__ b1,
                      const float* __restrict__ W2, const float* __restrict__ b2,
                      float* __restrict__ out) {
    __shared__ float p[128];
    __shared__ float h[64];
    int tid = threadIdx.x;
    if (tid < 128)
        p[tid] = tanhf(g_pool[tid] * (tid < 64 ? 1.f / N_VAR : 1.f / N_CLA));
    __syncthreads();
    if (tid < 64) {
        float a = b1[tid];
        #pragma unroll 8
        for (int j = 0; j < 128; j++) a = fmaf(p[j], W1[tid * 128 + j], a);
        h[tid] = (a > 0.f) ? a : 0.f;
    }
    __syncthreads();
    if (tid == 0) {
        float s = b2[0];
        for (int i = 0; i < 64; i++) s = fmaf(h[i], W2[i], s);
        out[0] = s;
    }
}

// ---------------- launch ------------------------------------------------------
extern "C" void kernel_launch(void* const* d_in, const int* in_sizes, int n_in,
                              void* d_out, int out_size) {
    (void)in_sizes; (void)n_in; (void)out_size;
    const float* xv   = (const float*)d_in[0];
    const float* xc   = (const float*)d_in[1];
    const float* sat  = (const float*)d_in[2];
    const int*   cvar = (const int*)d_in[3];
    const int*   ccla = (const int*)d_in[4];
    const int*   ei   = (const int*)d_in[5];
    const int*   shv  = (const int*)d_in[6];
    const float* WQ1  = (const float*)d_in[7];
    const float* WK1  = (const float*)d_in[8];
    const float* WV1  = (const float*)d_in[9];
    const float* hw1  = (const float*)d_in[10];
    const float* Wo   = (const float*)d_in[11];
    const float* bo   = (const float*)d_in[12];
    const float* WQ2  = (const float*)d_in[13];
    const float* WK2  = (const float*)d_in[14];
    const float* WV2  = (const float*)d_in[15];
    const float* hw2  = (const float*)d_in[16];
    const float* W1   = (const float*)d_in[17];
    const float* b1   = (const float*)d_in[18];
    const float* W2   = (const float*)d_in[19];
    const float* b2   = (const float*)d_in[20];

    cudaFuncSetAttribute(k_proj,    cudaFuncAttributeMaxDynamicSharedMemorySize, PROJ_SMEM);
    cudaFuncSetAttribute(k_attn_wm, cudaFuncAttributeMaxDynamicSharedMemorySize, ATTN_SMEM);
    cudaFuncSetAttribute(k_fin,     cudaFuncAttributeMaxDynamicSharedMemorySize, FIN_SMEM);

    k_zero0<<<(NM + 255) / 256, 256>>>();
    k_prep<<<(NC * (VC + KCL) + 255) / 256, 256>>>(WQ1, WK1, WV1, Wo, cvar, ccla);
    k_rcnt<<<(NM + 255) / 256, 256>>>();
    const int blocks128 = (NM + 127) / 128;
    for (int it = 0; it < NITER; it++) {
        k_proj<<<blocks128, 256, PROJ_SMEM>>>(xv, xc, it == 0);
        k_attn_wm<<<NC, 384, ATTN_SMEM>>>(cvar, ccla, sat, hw1);
        k_fin<<<blocks128, 256, FIN_SMEM>>>(bo, xv, xc, it == 0);
        k_cf<<<NC, 64>>>(cvar, WQ2, WK2, WV2);
        k_edge<<<(NE + 7) / 8, 256>>>(ei, shv, hw2);
    }
    k_pool<<<512, 256>>>();
    k_mlp<<<1, 128>>>(W1, b1, W2, b2, (float*)d_out);
}

// round 15
// speedup vs baseline: 2.8761x; 1.0107x over previous
#include <cuda_runtime.h>
#include <cuda_fp16.h>
#include <math.h>
#include <cstdint>
#include <mma.h>

using namespace nvcuda;

#define N_VAR 50000
#define N_CLA 100000
#define NM    150000
#define DD    64
#define NC    1000
#define VC    64
#define KCL   128
#define NN    192
#define NE    8000
#define NSH   8
#define NITER 3
#define NEG   0.2f
#define INVSCALE 0.125f

// fp16 fragments (all GEMMs)
typedef wmma::fragment<wmma::matrix_a, 16, 16, 16, __half, wmma::row_major> HA;
typedef wmma::fragment<wmma::matrix_b, 16, 16, 16, __half, wmma::col_major> HBC;
typedef wmma::fragment<wmma::matrix_b, 16, 16, 16, __half, wmma::row_major> HBR;
typedef wmma::fragment<wmma::accumulator, 16, 16, 16, float> HC;
typedef wmma::fragment<wmma::accumulator, 16, 16, 16, __half> HCH;

__device__ __forceinline__ void red_add_v4(float* p, float4 v) {
    asm volatile("red.global.add.v4.f32 [%0], {%1,%2,%3,%4};"
                 :: "l"(p), "f"(v.x), "f"(v.y), "f"(v.z), "f"(v.w) : "memory");
}
__device__ __forceinline__ void red_add_v4h2(__half* p, uint32_t a, uint32_t b,
                                             uint32_t c, uint32_t d) {
    asm volatile("red.global.add.noftz.v4.f16x2 [%0], {%1,%2,%3,%4};"
                 :: "l"(p), "r"(a), "r"(b), "r"(c), "r"(d) : "memory");
}

// ---------------- scratch ----------------------------------------------------
__device__ float  g_x   [NM * DD];
__device__ __half g_Qh  [NM * DD];
__device__ __half g_Kh  [NM * DD];
__device__ __half g_Vh  [NM * DD];
__device__ __half g_acch[NM * DD];
__device__ float  g_cnt [NM];        // reciprocal counts after k_rcnt
__device__ float  g_Q2  [NC * DD];
__device__ float  g_K2  [NC * DD];
__device__ float  g_V2  [NC * DD];
__device__ float  g_pool[2 * DD];
__device__ __half g_Wh  [3 * DD * DD];   // WQ1/WK1/WV1 as half
__device__ __half g_Woh [DD * DD];       // Wo as half

__global__ void k_zero0() {
    int t = blockIdx.x * blockDim.x + threadIdx.x;
    if (t < NM) g_cnt[t] = 0.f;
    if (t < 2 * DD) g_pool[t] = 0.f;
}

// weights->half AND node occurrence counts (both iteration-invariant)
__global__ void k_prep(const float* __restrict__ WQ, const float* __restrict__ WK,
                       const float* __restrict__ WV, const float* __restrict__ Wo,
                       const int* __restrict__ cvar, const int* __restrict__ ccla) {
    int i = blockIdx.x * blockDim.x + threadIdx.x;
    if (i < 4096)       g_Wh[i]        = __float2half_rn(WQ[i]);
    else if (i < 8192)  g_Wh[i]        = __float2half_rn(WK[i - 4096]);
    else if (i < 12288) g_Wh[i]        = __float2half_rn(WV[i - 8192]);
    else if (i < 16384) g_Woh[i-12288] = __float2half_rn(Wo[i - 12288]);
    if (i < NC * VC) atomicAdd(&g_cnt[cvar[i]], 1.f);
    else if (i < NC * (VC + KCL)) atomicAdd(&g_cnt[N_VAR + ccla[i - NC * VC]], 1.f);
}
__global__ void k_rcnt() {
    int i = blockIdx.x * blockDim.x + threadIdx.x;
    if (i < NM) g_cnt[i] = 1.f / fmaxf(g_cnt[i], 1.f);
}

// row pointer helper: iteration 0 reads directly from the harness inputs
__device__ __forceinline__ const float* xrow(const float* xv, const float* xc,
                                             int first, size_t r) {
    if (first)
        return (r < N_VAR) ? (xv + r * 64) : (xc + (r - (size_t)N_VAR) * 64);
    return g_x + r * 64;
}

// ---------------- Q/K/V projection via WMMA fp16, staged coalesced stores ----
#define PROJ_SMEM (27648 + 18432)
__global__ void __launch_bounds__(256, 4) k_proj(const float* __restrict__ xv,
                                                 const float* __restrict__ xc,
                                                 int first) {
    extern __shared__ char smem[];
    __half* Wh = (__half*)smem;                       // [3][64][72]
    __half* xs = (__half*)(smem + 27648);             // [128][72]
    int tid = threadIdx.x, wid = tid >> 5, lane = tid & 31;

    for (int i = tid; i < 3 * 64 * 16; i += 256) {
        int m = i >> 10, rem = i & 1023, d = rem >> 4, q4 = rem & 15;
        *(uint2*)(Wh + m * 4608 + d * 72 + q4 * 4) =
            *(const uint2*)(g_Wh + m * 4096 + d * 64 + q4 * 4);
    }
    size_t base = (size_t)blockIdx.x * 128;
    for (int i = tid; i < 128 * 16; i += 256) {
        int row = i >> 4, q4 = i & 15;
        size_t r = base + row;
        if (r < NM) {
            float4 v = ((const float4*)xrow(xv, xc, first, r))[q4];
            __half2 h0 = __floats2half2_rn(v.x, v.y);
            __half2 h1 = __floats2half2_rn(v.z, v.w);
            uint2 u; u.x = *(uint32_t*)&h0; u.y = *(uint32_t*)&h1;
            *(uint2*)(xs + row * 72 + q4 * 4) = u;
        }
    }
    __syncthreads();

    int rowbase = wid * 16;
    if (base + rowbase < NM) {
        HA a[4];
        #pragma unroll
        for (int k = 0; k < 4; k++)
            wmma::load_matrix_sync(a[k], xs + rowbase * 72 + k * 16, 72);
        __half* band = xs + rowbase * 72;     // dead after A-frag loads
        __half* outs[3] = {g_Qh, g_Kh, g_Vh};
        #pragma unroll
        for (int m = 0; m < 3; m++) {
            #pragma unroll
            for (int tc = 0; tc < 4; tc++) {
                HC acc;
                wmma::fill_fragment(acc, 0.f);
                #pragma unroll
                for (int k = 0; k < 4; k++) {
                    HBC b;
                    wmma::load_matrix_sync(b, Wh + m * 4608 + tc * 16 * 72 + k * 16, 72);
                    wmma::mma_sync(acc, a[k], b, acc);
                }
                HCH h;
                if (m == 0) {
                    #pragma unroll
                    for (int t = 0; t < acc.num_elements; t++)
                        h.x[t] = __float2half_rn(acc.x[t] * INVSCALE);
                } else {
                    #pragma unroll
                    for (int t = 0; t < acc.num_elements; t++)
                        h.x[t] = __float2half_rn(acc.x[t]);
                }
                wmma::store_matrix_sync(band + tc * 16, h, 72, wmma::mem_row_major);
            }
            __syncwarp();
            __half* dst = outs[m] + (base + rowbase) * 64;
            #pragma unroll
            for (int i = 0; i < 4; i++) {
                int idx = lane + 32 * i;
                int row = idx >> 3, q8 = idx & 7;
                *(uint4*)(dst + row * 64 + q8 * 8) =
                    *(const uint4*)(band + row * 72 + q8 * 8);
            }
            __syncwarp();
        }
    }
    // zero g_acch
    uint4 z4 = make_uint4(0u, 0u, 0u, 0u);
    for (int i = tid; i < 128 * 8; i += 256) {
        int row = i >> 3, q8 = i & 7;
        size_t r = base + row;
        if (r < NM) *(uint4*)(g_acch + r * 64 + q8 * 8) = z4;
    }
}

// ---------------- intra-cluster attention via WMMA fp16 ----------------------
// 2 CTAs/cluster, 3 bands x 32 queries each; Q prefetch overlapped w/ softmax.
#define OFFB_K  0
#define OFFB_V  27648
#define OFFB_Q  55296
#define OFFB_S  59904
#define OFFB_RS 72704
#define OFFB_B  72832
#define OFFB_N  73600
#define ATTN_SMEM 74368

__global__ void __launch_bounds__(384, 3) k_attn_wm(const int* __restrict__ cvar,
                                                    const int* __restrict__ ccla,
                                                    const float* __restrict__ sat,
                                                    const float* __restrict__ hw) {
    extern __shared__ char smem[];
    __half* Kh = (__half*)(smem + OFFB_K);     // [192][72]
    __half* Vh = (__half*)(smem + OFFB_V);     // [192][72]
    __half* Qh = (__half*)(smem + OFFB_Q);     // [32][72]
    __half* Sh = (__half*)(smem + OFFB_S);     // [32][200] scores -> exp (in place)
    float*  Of = (float*)(smem + OFFB_S);      // [32][72] O staging (aliases Sh)
    float*  rowsum = (float*)(smem + OFFB_RS); // [32]
    float*  bsh = (float*)(smem + OFFB_B);     // [192]
    int*    nsh = (int*)(smem + OFFB_N);       // [192]

    int c = blockIdx.x >> 1, qhalf = blockIdx.x & 1;
    int tid = threadIdx.x, wid = tid >> 5, lane = tid & 31;
    int qbase = qhalf * 96;
    if (tid < NN) {
        int g; float b;
        if (tid < VC) { g = cvar[c * VC + tid]; b = 0.f; }
        else { int cl = ccla[c * KCL + (tid - VC)]; g = N_VAR + cl; b = sat[cl]; }
        nsh[tid] = g; bsh[tid] = b;
    }
    float hwm = 0.25f * (hw[0] + hw[1] + hw[2] + hw[3]);
    __syncthreads();

    for (int idx = tid; idx < 192 * 8; idx += 384) {
        int row = idx >> 3, q8 = idx & 7;
        size_t o = (size_t)nsh[row] * 64;
        *(uint4*)(Kh + row * 72 + q8 * 8) = ((const uint4*)(g_Kh + o))[q8];
        *(uint4*)(Vh + row * 72 + q8 * 8) = ((const uint4*)(g_Vh + o))[q8];
    }
    // gather first band's Q
    for (int idx = tid; idx < 32 * 8; idx += 384) {
        int row = idx >> 3, q8 = idx & 7;
        *(uint4*)(Qh + row * 72 + q8 * 8) =
            ((const uint4*)(g_Qh + (size_t)nsh[qbase + row] * 64))[q8];
    }
    __syncthreads();

    for (int b = 0; b < 3; b++) {
        int band = qbase + b * 32;
        // GEMM1: S[32,192] = Qh @ Kh^T, stored as half
        {
            int tr = wid & 1, tc = wid >> 1;
            HA a[4];
            #pragma unroll
            for (int k = 0; k < 4; k++)
                wmma::load_matrix_sync(a[k], Qh + tr * 16 * 72 + k * 16, 72);
            #pragma unroll
            for (int half2x = 0; half2x < 2; half2x++) {
                int tcc = tc + half2x * 6;
                HC acc;
                wmma::fill_fragment(acc, 0.f);
                #pragma unroll
                for (int k = 0; k < 4; k++) {
                    HBC bb;
                    wmma::load_matrix_sync(bb, Kh + tcc * 16 * 72 + k * 16, 72);
                    wmma::mma_sync(acc, a[k], bb, acc);
                }
                HCH h;
                #pragma unroll
                for (int t = 0; t < acc.num_elements; t++)
                    h.x[t] = __float2half_rn(acc.x[t]);
                wmma::store_matrix_sync(Sh + tr * 16 * 200 + tcc * 16, h, 200,
                                        wmma::mem_row_major);
            }
        }
        __syncthreads();

        // softmax (warps 0-7) || prefetch next band's Q (warps 8-11)
        if (tid < 256) {
            int srow = tid >> 3, c0 = tid & 7;
            __half* srw = Sh + srow * 200;
            float mx = -1e30f;
            #pragma unroll 8
            for (int i = 0; i < 24; i++) {
                int col = c0 + 8 * i;
                float s = __half2float(srw[col]) + bsh[col];
                s = (s >= 0.f) ? s : NEG * s;
                srw[col] = __float2half_rn(s);
                mx = fmaxf(mx, s);
            }
            mx = fmaxf(mx, __shfl_xor_sync(0xffffffffu, mx, 1));
            mx = fmaxf(mx, __shfl_xor_sync(0xffffffffu, mx, 2));
            mx = fmaxf(mx, __shfl_xor_sync(0xffffffffu, mx, 4));
            float sum = 0.f;
            #pragma unroll 8
            for (int i = 0; i < 24; i++) {
                int col = c0 + 8 * i;
                float e = __expf(__half2float(srw[col]) - mx);
                sum += e;
                srw[col] = __float2half_rn(e);
            }
            sum += __shfl_xor_sync(0xffffffffu, sum, 1);
            sum += __shfl_xor_sync(0xffffffffu, sum, 2);
            sum += __shfl_xor_sync(0xffffffffu, sum, 4);
            if (c0 == 0) rowsum[srow] = sum;
        } else if (b < 2) {
            for (int idx = tid - 256; idx < 32 * 8; idx += 128) {
                int row = idx >> 3, q8 = idx & 7;
                *(uint4*)(Qh + row * 72 + q8 * 8) =
                    ((const uint4*)(g_Qh + (size_t)nsh[band + 32 + row] * 64))[q8];
            }
        }
        __syncthreads();

        // GEMM2: O[32,64] = P @ V; C-frag in regs across sync
        HC o0;
        wmma::fill_fragment(o0, 0.f);
        int tr2 = wid >> 2, tc2 = wid & 3;
        if (wid < 8) {
            #pragma unroll 4
            for (int k = 0; k < 12; k++) {
                HA a;
                wmma::load_matrix_sync(a, Sh + tr2 * 16 * 200 + k * 16, 200);
                HBR bb;
                wmma::load_matrix_sync(bb, Vh + k * 16 * 72 + tc2 * 16, 72);
                wmma::mma_sync(o0, a, bb, o0);
            }
        }
        __syncthreads();   // all reads of Sh done
        if (wid < 8) {
            wmma::store_matrix_sync(Of + tr2 * 16 * 72 + tc2 * 16, o0, 72,
                                    wmma::mem_row_major);
            __syncwarp();
            int row = lane >> 1, c8 = (lane & 1) * 8;
            int grow = tr2 * 16 + row;
            int g = nsh[band + grow];
            float scl = hwm / rowsum[grow];
            const float* src = Of + grow * 72 + tc2 * 16 + c8;
            __half* dst = g_acch + (size_t)g * 64 + tc2 * 16 + c8;
            float4 f0 = *(const float4*)(src);
            float4 f1 = *(const float4*)(src + 4);
            __half2 h0 = __floats2half2_rn(f0.x * scl, f0.y * scl);
            __half2 h1 = __floats2half2_rn(f0.z * scl, f0.w * scl);
            __half2 h2 = __floats2half2_rn(f1.x * scl, f1.y * scl);
            __half2 h3 = __floats2half2_rn(f1.z * scl, f1.w * scl);
            red_add_v4h2(dst, *(uint32_t*)&h0, *(uint32_t*)&h1,
                              *(uint32_t*)&h2, *(uint32_t*)&h3);
        }
        __syncthreads();   // Of reads done before next band's GEMM1 writes Sh
    }
}

// ---------------- finalize via WMMA fp16 (staged in dead A-band) -------------
#define FIN_SMEM (9216 + 18432)
__global__ void __launch_bounds__(256, 4) k_fin(const float* __restrict__ bo,
                                                const float* __restrict__ xv,
                                                const float* __restrict__ xc,
                                                int first) {
    extern __shared__ char smem[];
    __half* Wh = (__half*)smem;                   // [64][72] (d,k) at d*72+k
    __half* xs = (__half*)(smem + 9216);          // [128][72] acc halves / staging
    int tid = threadIdx.x, wid = tid >> 5, lane = tid & 31;

    for (int i = tid; i < 64 * 16; i += 256) {
        int d = i >> 4, q4 = i & 15;
        *(uint2*)(Wh + d * 72 + q4 * 4) = *(const uint2*)(g_Woh + d * 64 + q4 * 4);
    }
    size_t base = (size_t)blockIdx.x * 128;
    for (int i = tid; i < 128 * 8; i += 256) {
        int row = i >> 3, q8 = i & 7;
        size_t r = base + row;
        if (r < NM)
            *(uint4*)(xs + row * 72 + q8 * 8) = *(const uint4*)(g_acch + r * 64 + q8 * 8);
    }
    __syncthreads();

    int rowbase = wid * 16;
    if (base + rowbase < NM) {
        HA a[4];
        #pragma unroll
        for (int k = 0; k < 4; k++)
            wmma::load_matrix_sync(a[k], xs + rowbase * 72 + k * 16, 72);
        __half* band = xs + rowbase * 72;
        #pragma unroll
        for (int tc = 0; tc < 4; tc++) {
            HC acc;
            wmma::fill_fragment(acc, 0.f);
            #pragma unroll
            for (int k = 0; k < 4; k++) {
                HBC b;
                wmma::load_matrix_sync(b, Wh + tc * 16 * 72 + k * 16, 72);
                wmma::mma_sync(acc, a[k], b, acc);
            }
            HCH h;
            #pragma unroll
            for (int t = 0; t < acc.num_elements; t++)
                h.x[t] = __float2half_rn(acc.x[t]);
            wmma::store_matrix_sync(band + tc * 16, h, 72, wmma::mem_row_major);
        }
        __syncwarp();
        #pragma unroll
        for (int i = 0; i < 4; i++) {
            int idx = lane + 32 * i;
            int row = idx >> 3, q8 = idx & 7;
            size_t r = base + rowbase + row;
            float rc = g_cnt[r];
            uint4 u = *(const uint4*)(band + row * 72 + q8 * 8);
            __half2 h0 = *(__half2*)&u.x, h1 = *(__half2*)&u.y;
            __half2 h2 = *(__half2*)&u.z, h3 = *(__half2*)&u.w;
            float2 f0 = __half22float2(h0), f1 = __half22float2(h1);
            float2 f2 = __half22float2(h2), f3 = __half22float2(h3);
            const float* xr = xrow(xv, xc, first, r) + q8 * 8;
            float* gx = g_x + r * 64 + q8 * 8;
            const float* bb = bo + q8 * 8;
            float4 x0 = *(const float4*)xr, x1 = *(const float4*)(xr + 4);
            float4 b0 = *(const float4*)bb, b1 = *(const float4*)(bb + 4);
            x0.x += f0.x * rc + b0.x; x0.y += f0.y * rc + b0.y;
            x0.z += f1.x * rc + b0.z; x0.w += f1.y * rc + b0.w;
            x1.x += f2.x * rc + b1.x; x1.y += f2.y * rc + b1.y;
            x1.z += f3.x * rc + b1.z; x1.w += f3.y * rc + b1.w;
            *(float4*)gx = x0; *(float4*)(gx + 4) = x1;
        }
    }
}

// ---------------- cluster features + Q2/K2/V2 projection ---------------------
__global__ void k_cf(const int* __restrict__ cvar,
                     const float* __restrict__ WQ2, const float* __restrict__ WK2,
                     const float* __restrict__ WV2) {
    __shared__ float cf[64];
    __shared__ int ids[64];
    int c = blockIdx.x, d = threadIdx.x;
    ids[d] = cvar[c * VC + d];
    __syncthreads();
    float s = 0.f;
    #pragma unroll 8
    for (int v = 0; v < VC; v++) s += g_x[(size_t)ids[v] * DD + d];
    cf[d] = s * (1.f / 64.f);
    __syncthreads();
    float q = 0.f, k = 0.f, v = 0.f;
    #pragma unroll 8
    for (int j = 0; j < 64; j++) {
        float x = cf[j];
        q = fmaf(x, WQ2[d * 64 + j], q);
        k = fmaf(x, WK2[d * 64 + j], k);
        v = fmaf(x, WV2[d * 64 + j], v);
    }
    g_Q2[c * 64 + d] = q; g_K2[c * 64 + d] = k; g_V2[c * 64 + d] = v;
}

// ---------------- inter-cluster edge scatter (GAT2, vectorized atomics) ------
__global__ void k_edge(const int* __restrict__ ei, const int* __restrict__ shv,
                       const float* __restrict__ hw) {
    int tid = threadIdx.x;
    int warp = tid >> 5, lane = tid & 31;
    int e = blockIdx.x * 8 + warp;
    if (e >= NE) return;
    int c1 = ei[e], c2 = ei[NE + e];
    float p = g_Q2[c1 * 64 + lane] * g_K2[c2 * 64 + lane]
            + g_Q2[c1 * 64 + lane + 32] * g_K2[c2 * 64 + lane + 32];
    #pragma unroll
    for (int o = 16; o > 0; o >>= 1) p += __shfl_xor_sync(0xffffffffu, p, o);
    float s = p * INVSCALE;
    float lr = (s >= 0.f) ? s : NEG * s;
    float hwm = 0.25f * (hw[0] + hw[1] + hw[2] + hw[3]);
    float a = hwm / (1.f + __expf(-lr));
    float4 v4 = make_float4(0.f, 0.f, 0.f, 0.f);
    if (lane < 16) {
        v4 = ((const float4*)(g_V2 + (size_t)c2 * 64))[lane];
        v4.x *= a; v4.y *= a; v4.z *= a; v4.w *= a;
    }
    #pragma unroll
    for (int k = 0; k < NSH; k++) {
        int sv = shv[e * NSH + k];
        if (lane < 16) red_add_v4(g_x + (size_t)sv * 64 + lane * 4, v4);
    }
}

// ---------------- pooling (float4 + block reduction) + MLP readout -----------
__global__ void __launch_bounds__(256) k_pool() {
    __shared__ float red[2 * 64];
    int tid = threadIdx.x;
    int quad = tid & 15, rowg = tid >> 4;   // 16 quads x 16 row-groups
    if (tid < 128) red[tid] = 0.f;
    __syncthreads();
    float4 sv = make_float4(0.f, 0.f, 0.f, 0.f);
    float4 sc = make_float4(0.f, 0.f, 0.f, 0.f);
    for (int r = blockIdx.x * 16 + rowg; r < NM; r += gridDim.x * 16) {
        float4 x = ((const float4*)(g_x + (size_t)r * 64))[quad];
        if (r < N_VAR) { sv.x += x.x; sv.y += x.y; sv.z += x.z; sv.w += x.w; }
        else           { sc.x += x.x; sc.y += x.y; sc.z += x.z; sc.w += x.w; }
    }
    atomicAdd(&red[quad * 4 + 0], sv.x); atomicAdd(&red[quad * 4 + 1], sv.y);
    atomicAdd(&red[quad * 4 + 2], sv.z); atomicAdd(&red[quad * 4 + 3], sv.w);
    atomicAdd(&red[64 + quad * 4 + 0], sc.x); atomicAdd(&red[64 + quad * 4 + 1], sc.y);
    atomicAdd(&red[64 + quad * 4 + 2], sc.z); atomicAdd(&red[64 + quad * 4 + 3], sc.w);
    __syncthreads();
    if (tid < 128) atomicAdd(&g_pool[tid], red[tid]);
}

__global__ void k_mlp(const float* __restrict__ W1, const float* __restrict__ b1,
                      const float* __restrict__ W2, const float* __restrict__ b2,
                      float* __restrict__ out) {
    __shared__ float p[128];
    __shared__ float h[64];
    int tid = threadIdx.x;
    if (tid < 128)
        p[tid] = tanhf(g_pool[tid] * (tid < 64 ? 1.f / N_VAR : 1.f / N_CLA));
    __syncthreads();
    if (tid < 64) {
        float a = b1[tid];
        #pragma unroll 8
        for (int j = 0; j < 128; j++) a = fmaf(p[j], W1[tid * 128 + j], a);
        h[tid] = (a > 0.f) ? a : 0.f;
    }
    __syncthreads();
    if (tid == 0) {
        float s = b2[0];
        for (int i = 0; i < 64; i++) s = fmaf(h[i], W2[i], s);
        out[0] = s;
    }
}

// ---------------- launch ------------------------------------------------------
extern "C" void kernel_launch(void* const* d_in, const int* in_sizes, int n_in,
                              void* d_out, int out_size) {
    (void)in_sizes; (void)n_in; (void)out_size;
    const float* xv   = (const float*)d_in[0];
    const float* xc   = (const float*)d_in[1];
    const float* sat  = (const float*)d_in[2];
    const int*   cvar = (const int*)d_in[3];
    const int*   ccla = (const int*)d_in[4];
    const int*   ei   = (const int*)d_in[5];
    const int*   shv  = (const int*)d_in[6];
    const float* WQ1  = (const float*)d_in[7];
    const float* WK1  = (const float*)d_in[8];
    const float* WV1  = (const float*)d_in[9];
    const float* hw1  = (const float*)d_in[10];
    const float* Wo   = (const float*)d_in[11];
    const float* bo   = (const float*)d_in[12];
    const float* WQ2  = (const float*)d_in[13];
    const float* WK2  = (const float*)d_in[14];
    const float* WV2  = (const float*)d_in[15];
    const float* hw2  = (const float*)d_in[16];
    const float* W1   = (const float*)d_in[17];
    const float* b1   = (const float*)d_in[18];
    const float* W2   = (const float*)d_in[19];
    const float* b2   = (const float*)d_in[20];

    cudaFuncSetAttribute(k_proj,    cudaFuncAttributeMaxDynamicSharedMemorySize, PROJ_SMEM);
    cudaFuncSetAttribute(k_attn_wm, cudaFuncAttributeMaxDynamicSharedMemorySize, ATTN_SMEM);
    cudaFuncSetAttribute(k_fin,     cudaFuncAttributeMaxDynamicSharedMemorySize, FIN_SMEM);

    k_zero0<<<(NM + 255) / 256, 256>>>();
    k_prep<<<(NC * (VC + KCL) + 255) / 256, 256>>>(WQ1, WK1, WV1, Wo, cvar, ccla);
    k_rcnt<<<(NM + 255) / 256, 256>>>();
    const int blocks128 = (NM + 127) / 128;
    for (int it = 0; it < NITER; it++) {
        k_proj<<<blocks128, 256, PROJ_SMEM>>>(xv, xc, it == 0);
        k_attn_wm<<<2 * NC, 384, ATTN_SMEM>>>(cvar, ccla, sat, hw1);
        k_fin<<<blocks128, 256, FIN_SMEM>>>(bo, xv, xc, it == 0);
        k_cf<<<NC, 64>>>(cvar, WQ2, WK2, WV2);
        k_edge<<<(NE + 7) / 8, 256>>>(ei, shv, hw2);
    }
    k_pool<<<296, 256>>>();
    k_mlp<<<1, 128>>>(W1, b1, W2, b2, (float*)d_out);
}